// round 11
// baseline (speedup 1.0000x reference)
#include <cuda_runtime.h>
#include <cuda_bf16.h>
#include <math.h>
#include <stdint.h>

#define B_   4
#define LQ_  2048
#define LK_  2048
#define DM_  1024
#define NH_  16
#define M_   8192

// ---------------- device scratch (allocation-free rule) --------------------
__device__ uint32_t g_Ih[3][4194304];     // split-hi of q,k,v inputs (bf16x2)
__device__ uint32_t g_Il[3][4194304];     // split-lo (mat 2 unused)
__device__ uint32_t g_Wth[4][524288];     // transposed weights hi [n][k-pair]; idx3 = fc_w
__device__ uint32_t g_Wtl[3][524288];     // transposed weights lo
__device__ uint32_t g_Qhi[4194304], g_Qlo[4194304];   // [b,h,l,d-pair], pre-scaled 1/8
__device__ uint32_t g_Khi[4194304], g_Klo[4194304];
__device__ uint32_t g_Vh [4194304];       // V TRANSPOSED bf16 [bh*64+d][l]
__device__ uint32_t g_Hbf[4194304];       // attn output bf16 [m][k-pair] for FC
__device__ uint32_t g_mbits[524288];      // mask bitwords [b][lq][lk/32]
__device__ float    g_mchunk[(size_t)B_*NH_*LQ_*16];
__device__ float2   g_rowstat[(size_t)B_*NH_*LQ_];

// ---------------- helpers --------------------------------------------------
__device__ __forceinline__ uint32_t pack_bf16(float x, float y){
    __nv_bfloat162 t = __floats2bfloat162_rn(x, y);
    return *reinterpret_cast<uint32_t*>(&t);
}
__device__ __forceinline__ void split_u32(float x0, float x1, uint32_t& h, uint32_t& l){
    float h0 = __bfloat162float(__float2bfloat16(x0));
    float h1 = __bfloat162float(__float2bfloat16(x1));
    h = pack_bf16(h0, h1);
    l = pack_bf16(x0 - h0, x1 - h1);
}
__device__ __forceinline__ void mma16816(float* c,
    uint32_t a0, uint32_t a1, uint32_t a2, uint32_t a3, uint32_t b0, uint32_t b1){
    asm volatile("mma.sync.aligned.m16n8k16.row.col.f32.bf16.bf16.f32 "
        "{%0,%1,%2,%3}, {%4,%5,%6,%7}, {%8,%9}, {%0,%1,%2,%3};"
        : "+f"(c[0]), "+f"(c[1]), "+f"(c[2]), "+f"(c[3])
        : "r"(a0), "r"(a1), "r"(a2), "r"(a3), "r"(b0), "r"(b1));
}
__device__ __forceinline__ void ldsm_x4(uint32_t* r, uint32_t addr){
    asm volatile("ldmatrix.sync.aligned.m8n8.x4.shared.b16 {%0,%1,%2,%3}, [%4];"
        : "=r"(r[0]), "=r"(r[1]), "=r"(r[2]), "=r"(r[3]) : "r"(addr));
}
__device__ __forceinline__ void cp_async16(uint32_t saddr, const void* gaddr){
    asm volatile("cp.async.cg.shared.global [%0], [%1], 16;" :: "r"(saddr), "l"(gaddr));
}
__device__ __forceinline__ void cp_commit(){ asm volatile("cp.async.commit_group;"); }
template<int N> __device__ __forceinline__ void cp_wait(){
    asm volatile("cp.async.wait_group %0;" :: "n"(N));
}
__device__ __forceinline__ uint32_t smem_u32addr(const void* p){
    uint32_t a;
    asm("{.reg .u64 t; cvta.to.shared.u64 t, %1; cvt.u32.u64 %0, t;}" : "=r"(a) : "l"(p));
    return a;
}

// ---------------- convert kernels ------------------------------------------
__global__ void k_split_inputs(const float* __restrict__ q,
                               const float* __restrict__ k,
                               const float* __restrict__ v){
    size_t F = (size_t)blockIdx.x*256 + threadIdx.x;   // float4 index
    int mat = (int)(F >> 21);
    size_t rem = F & 2097151u;
    const float* src = mat==0 ? q : mat==1 ? k : v;
    float4 a = reinterpret_cast<const float4*>(src)[rem];
    uint32_t h0,l0,h1,l1;
    split_u32(a.x, a.y, h0, l0);
    split_u32(a.z, a.w, h1, l1);
    g_Ih[mat][rem*2]   = h0; g_Ih[mat][rem*2+1] = h1;
    if (mat < 2){                                      // V lo-plane never read
        g_Il[mat][rem*2] = l0; g_Il[mat][rem*2+1] = l1;
    }
}

__global__ void k_conv_w(const float* __restrict__ wq, const float* __restrict__ wk,
                         const float* __restrict__ wv, const float* __restrict__ fcw){
    const int mat = blockIdx.z;
    const float* W = mat==0 ? wq : mat==1 ? wk : mat==2 ? wv : fcw;
    __shared__ float T[32][33];
    const int k0 = blockIdx.y*32, n0 = blockIdx.x*32;
    const int tx = threadIdx.x & 31, ty = threadIdx.x >> 5;
    #pragma unroll
    for (int i=0;i<4;i++)
        T[ty+8*i][tx] = W[(size_t)(k0+ty+8*i)*DM_ + n0 + tx];
    __syncthreads();
    const int n = threadIdx.x >> 3;
    const int kp0 = (threadIdx.x & 7)*2;
    #pragma unroll
    for (int s2=0;s2<2;s2++){
        int kp = kp0 + s2;
        float x0 = T[kp*2][n], x1 = T[kp*2+1][n];
        uint32_t h, l; split_u32(x0, x1, h, l);
        size_t o = (size_t)(n0+n)*512 + (k0>>1) + kp;
        g_Wth[mat][o] = h;
        if (mat < 3) g_Wtl[mat][o] = l;
    }
}

__global__ void k_mask_bits(const int* __restrict__ mask){
    int wrp = blockIdx.x*8 + (threadIdx.x>>5);
    int lane = threadIdx.x & 31;
    size_t base = (size_t)wrp*32;
    for (int j=0;j<32;j++){
        size_t w = base + j;
        int mv = mask[w*32 + lane];
        uint32_t bits = __ballot_sync(0xffffffffu, mv != 0);
        if (lane==0) g_mbits[w] = bits;
    }
}

// ---------------- projection GEMM ------------------------------------------
// 128x128 tile, k16 stages x4, cp.async + ldmatrix + 3-mma split
// p-pair batched, term-major MMA order (breaks accumulator RAW chains)
// which==2 (V): single-bf16
#define PSTG 6144            // u32 per stage (4 buffers x 1536)
#define BUFB 6144            // bytes per buffer

__global__ void __launch_bounds__(256,2) proj_kernel(
    const float* __restrict__ bq, const float* __restrict__ bk,
    const float* __restrict__ bv)
{
    extern __shared__ uint32_t smp[];
    const uint32_t sbase = smem_u32addr(smp);

    const int which = blockIdx.z;
    const bool vonly = (which == 2);
    const uint32_t* gAh = g_Ih[which];
    const uint32_t* gAl = g_Il[which];
    const uint32_t* gBh = g_Wth[which];
    const uint32_t* gBl = g_Wtl[which];
    const float* bias = which==0 ? bq : which==1 ? bk : bv;

    const int m0 = blockIdx.y*128, n0 = blockIdx.x*128;
    const int tid = threadIdx.x, lane = tid & 31, wid = tid >> 5;
    const int wm = (wid & 3)*32, wn = (wid >> 2)*64;

    const int crow = tid >> 1, chalf = tid & 1;
    const uint32_t* gsrc0 = gAh + (size_t)(m0+crow)*512 + chalf*4;
    const uint32_t* gsrc1 = gAl + (size_t)(m0+crow)*512 + chalf*4;
    const uint32_t* gsrc2 = gBh + (size_t)(n0+crow)*512 + chalf*4;
    const uint32_t* gsrc3 = gBl + (size_t)(n0+crow)*512 + chalf*4;
    const uint32_t sdst = sbase + crow*48 + chalf*16;

    auto issue = [&](int itk){
        int stage = itk & 3;
        uint32_t so = sdst + stage*(PSTG*4);
        size_t ko = (size_t)itk*8;
        cp_async16(so + 0*BUFB, gsrc0 + ko);
        cp_async16(so + 2*BUFB, gsrc2 + ko);
        if (!vonly){
            cp_async16(so + 1*BUFB, gsrc1 + ko);
            cp_async16(so + 3*BUFB, gsrc3 + ko);
        }
        cp_commit();
    };

    float acc[2][8][4];
    #pragma unroll
    for (int a=0;a<2;a++)
        #pragma unroll
        for (int b2=0;b2<8;b2++){ acc[a][b2][0]=0.f;acc[a][b2][1]=0.f;acc[a][b2][2]=0.f;acc[a][b2][3]=0.f; }

    issue(0); issue(1); issue(2);

    const uint32_t arow = wm + (lane & 15);
    const uint32_t aoff0 = arow*48 + ((lane>>4)&1)*16;
    const uint32_t brow = wn + (lane & 7) + ((lane & 16) ? 8 : 0);
    const uint32_t boff0 = 2*BUFB + brow*48 + ((lane & 8) ? 16 : 0);

    #pragma unroll 1
    for (int it=0; it<64; it++){
        if (it <= 61) cp_wait<2>(); else if (it == 62) cp_wait<1>(); else cp_wait<0>();
        __syncthreads();
        if (it + 3 < 64) issue(it+3);

        uint32_t sb = sbase + (it & 3)*(PSTG*4);
        uint32_t a_h[2][4], a_l[2][4];
        ldsm_x4(a_h[0], sb + aoff0);
        ldsm_x4(a_h[1], sb + aoff0 + 16*48);
        if (!vonly){
            ldsm_x4(a_l[0], sb + aoff0 + BUFB);
            ldsm_x4(a_l[1], sb + aoff0 + BUFB + 16*48);
        }
        #pragma unroll
        for (int pp=0;pp<2;pp++){
            const int p0 = 2*pp, p1 = 2*pp + 1;
            uint32_t b0h[4], b1h[4], b0l[4], b1l[4];
            ldsm_x4(b0h, sb + boff0 + p0*16*48);
            ldsm_x4(b1h, sb + boff0 + p1*16*48);
            if (!vonly){
                ldsm_x4(b0l, sb + boff0 + BUFB + p0*16*48);
                ldsm_x4(b1l, sb + boff0 + BUFB + p1*16*48);
            }
            // term hh — 8 independent accumulators
            #pragma unroll
            for (int mt=0;mt<2;mt++){
                mma16816(acc[mt][2*p0],   a_h[mt][0],a_h[mt][1],a_h[mt][2],a_h[mt][3], b0h[0],b0h[1]);
                mma16816(acc[mt][2*p0+1], a_h[mt][0],a_h[mt][1],a_h[mt][2],a_h[mt][3], b0h[2],b0h[3]);
                mma16816(acc[mt][2*p1],   a_h[mt][0],a_h[mt][1],a_h[mt][2],a_h[mt][3], b1h[0],b1h[1]);
                mma16816(acc[mt][2*p1+1], a_h[mt][0],a_h[mt][1],a_h[mt][2],a_h[mt][3], b1h[2],b1h[3]);
            }
            if (!vonly){
                // term hl
                #pragma unroll
                for (int mt=0;mt<2;mt++){
                    mma16816(acc[mt][2*p0],   a_h[mt][0],a_h[mt][1],a_h[mt][2],a_h[mt][3], b0l[0],b0l[1]);
                    mma16816(acc[mt][2*p0+1], a_h[mt][0],a_h[mt][1],a_h[mt][2],a_h[mt][3], b0l[2],b0l[3]);
                    mma16816(acc[mt][2*p1],   a_h[mt][0],a_h[mt][1],a_h[mt][2],a_h[mt][3], b1l[0],b1l[1]);
                    mma16816(acc[mt][2*p1+1], a_h[mt][0],a_h[mt][1],a_h[mt][2],a_h[mt][3], b1l[2],b1l[3]);
                }
                // term lh
                #pragma unroll
                for (int mt=0;mt<2;mt++){
                    mma16816(acc[mt][2*p0],   a_l[mt][0],a_l[mt][1],a_l[mt][2],a_l[mt][3], b0h[0],b0h[1]);
                    mma16816(acc[mt][2*p0+1], a_l[mt][0],a_l[mt][1],a_l[mt][2],a_l[mt][3], b0h[2],b0h[3]);
                    mma16816(acc[mt][2*p1],   a_l[mt][0],a_l[mt][1],a_l[mt][2],a_l[mt][3], b1h[0],b1h[1]);
                    mma16816(acc[mt][2*p1+1], a_l[mt][0],a_l[mt][1],a_l[mt][2],a_l[mt][3], b1h[2],b1h[3]);
                }
            }
        }
    }

    const float sc = (which==0) ? 0.125f : 1.0f;
    __nv_bfloat16* vt = reinterpret_cast<__nv_bfloat16*>(g_Vh);
    #pragma unroll
    for (int mt=0;mt<2;mt++){
        int r0 = m0 + wm + mt*16 + (lane>>2);
        #pragma unroll
        for (int nt=0;nt<8;nt++){
            int col = n0 + wn + nt*8 + 2*(lane&3);
            float2 bv2 = *reinterpret_cast<const float2*>(bias + col);
            int hh = col>>6, dd = col&63;
            #pragma unroll
            for (int rr=0;rr<2;rr++){
                int r = r0 + rr*8;
                int bb2 = r>>11, ll = r&2047;
                float x0 = (acc[mt][nt][rr*2]   + bv2.x)*sc;
                float x1 = (acc[mt][nt][rr*2+1] + bv2.y)*sc;
                if (which==2){
                    size_t vb = ((size_t)(bb2*NH_+hh)*64 + dd)*2048 + ll;
                    vt[vb]        = __float2bfloat16(x0);
                    vt[vb + 2048] = __float2bfloat16(x1);
                } else {
                    size_t o = (((size_t)(bb2*NH_+hh))*LQ_ + ll)*32 + (dd>>1);
                    uint32_t h, l; split_u32(x0, x1, h, l);
                    if (which==0){ g_Qhi[o]=h; g_Qlo[o]=l; }
                    else         { g_Khi[o]=h; g_Klo[o]=l; }
                }
            }
        }
    }
}

// ---------------- FC GEMM + bias + residual --------------------------------
#define FSTG 3072

__global__ void __launch_bounds__(256,2) fc_kernel(
    const float* __restrict__ fc_b, const float* __restrict__ q_in,
    float* __restrict__ out)
{
    extern __shared__ uint32_t smf[];
    const uint32_t sbase = smem_u32addr(smf);

    const int m0 = blockIdx.y*128, n0 = blockIdx.x*128;
    const int tid = threadIdx.x, lane = tid & 31, wid = tid >> 5;
    const int wm = (wid & 3)*32, wn = (wid >> 2)*64;

    const int crow = tid >> 1, chalf = tid & 1;
    const uint32_t* gsrc0 = g_Hbf    + (size_t)(m0+crow)*512 + chalf*4;
    const uint32_t* gsrc1 = g_Wth[3] + (size_t)(n0+crow)*512 + chalf*4;
    const uint32_t sdst = sbase + crow*48 + chalf*16;

    auto issue = [&](int itk){
        int stage = itk & 3;
        uint32_t so = sdst + stage*(FSTG*4);
        size_t ko = (size_t)itk*8;
        cp_async16(so,        gsrc0 + ko);
        cp_async16(so + BUFB, gsrc1 + ko);
        cp_commit();
    };

    float acc[2][8][4];
    #pragma unroll
    for (int a=0;a<2;a++)
        #pragma unroll
        for (int b2=0;b2<8;b2++){ acc[a][b2][0]=0.f;acc[a][b2][1]=0.f;acc[a][b2][2]=0.f;acc[a][b2][3]=0.f; }

    issue(0); issue(1); issue(2);

    const uint32_t arow = wm + (lane & 15);
    const uint32_t aoff0 = arow*48 + ((lane>>4)&1)*16;
    const uint32_t brow = wn + (lane & 7) + ((lane & 16) ? 8 : 0);
    const uint32_t boff0 = BUFB + brow*48 + ((lane & 8) ? 16 : 0);

    #pragma unroll 1
    for (int it=0; it<64; it++){
        if (it <= 61) cp_wait<2>(); else if (it == 62) cp_wait<1>(); else cp_wait<0>();
        __syncthreads();
        if (it + 3 < 64) issue(it+3);

        uint32_t sb = sbase + (it & 3)*(FSTG*4);
        uint32_t a_h[2][4];
        ldsm_x4(a_h[0], sb + aoff0);
        ldsm_x4(a_h[1], sb + aoff0 + 16*48);
        #pragma unroll
        for (int p=0;p<4;p++){
            uint32_t bh4[4];
            ldsm_x4(bh4, sb + boff0 + p*16*48);
            #pragma unroll
            for (int mt=0;mt<2;mt++){
                mma16816(acc[mt][2*p],   a_h[mt][0],a_h[mt][1],a_h[mt][2],a_h[mt][3], bh4[0],bh4[1]);
                mma16816(acc[mt][2*p+1], a_h[mt][0],a_h[mt][1],a_h[mt][2],a_h[mt][3], bh4[2],bh4[3]);
            }
        }
    }

    #pragma unroll
    for (int mt=0;mt<2;mt++){
        int r0 = m0 + wm + mt*16 + (lane>>2);
        #pragma unroll
        for (int nt=0;nt<8;nt++){
            int col = n0 + wn + nt*8 + 2*(lane&3);
            float2 bv2 = *reinterpret_cast<const float2*>(fc_b + col);
            #pragma unroll
            for (int rr=0;rr<2;rr++){
                size_t idx = (size_t)(r0+rr*8)*DM_ + col;
                float2 res = *reinterpret_cast<const float2*>(q_in + idx);
                *reinterpret_cast<float2*>(out + idx) =
                    make_float2(acc[mt][nt][rr*2]+bv2.x+res.x, acc[mt][nt][rr*2+1]+bv2.y+res.y);
            }
        }
    }
}

// ---------------- attention: double-buffered cp.async, p-pair batched S ----
#define QSTR 36
#define OF_QH 0
#define OF_QL 4608
#define OF_K0 9216                   // per buf: Kh 4608 + Kl 4608
#define OF_V0 27648                  // per buf: 64*68 = 4352
#define ATTN_SMEM_U32 36352          // 145408 bytes

__global__ void __launch_bounds__(256,1) attn_kernel(float* __restrict__ attn_out)
{
    extern __shared__ uint32_t smq[];
    const uint32_t sbase = smem_u32addr(smq);
    uint32_t* Qh = smq;
    uint32_t* Ql = smq + OF_QL;

    const int b  = blockIdx.z, h = blockIdx.y;
    const int q0 = blockIdx.x * 128;
    const int bh = b*NH_ + h;
    const int tid = threadIdx.x, lane = tid & 31, wid = tid >> 5;
    const int wrow = wid * 16;
    const size_t ho32 = (size_t)bh * LK_ * 32;

    // K/V chunk loader (cp.async, 48KB per chunk)
    auto load_kv = [&](int kc, int buf){
        uint32_t kb = sbase + (OF_K0 + buf*9216)*4;
        uint32_t vb = sbase + (OF_V0 + buf*4352)*4;
        #pragma unroll
        for (int p=0;p<4;p++){
            int id = tid + p*256;
            int row = id>>3, c = id&7;
            const uint32_t* ks = g_Khi + ho32 + (size_t)(kc+row)*32 + c*4;
            const uint32_t* ls = g_Klo + ho32 + (size_t)(kc+row)*32 + c*4;
            cp_async16(kb + row*144 + c*16, ks);
            cp_async16(kb + 4608*4 + row*144 + c*16, ls);
            int d = id>>4, c2 = id&15;
            const uint32_t* vs = g_Vh + ((size_t)bh*64 + d)*1024 + (kc>>1) + c2*4;
            cp_async16(vb + d*272 + c2*16, vs);
        }
        cp_commit();
    };

    load_kv(0, 0);

    // Q tile (pre-scaled, pre-split) — plain loads, overlap with cp.async
    #pragma unroll
    for (int p=0;p<4;p++){
        int item = tid + p*256;
        int row = item>>3, o = item&7;
        *reinterpret_cast<uint4*>(Qh + row*QSTR + o*4) =
            *reinterpret_cast<const uint4*>(g_Qhi + ho32 + (size_t)(q0+row)*32 + o*4);
        *reinterpret_cast<uint4*>(Ql + row*QSTR + o*4) =
            *reinterpret_cast<const uint4*>(g_Qlo + ho32 + (size_t)(q0+row)*32 + o*4);
    }

    float mrow0 = -INFINITY, mrow1 = -INFINITY;
    float lrow0 = 0.f, lrow1 = 0.f;
    float o_[8][4];
    #pragma unroll
    for (int t=0;t<8;t++){ o_[t][0]=0.f;o_[t][1]=0.f;o_[t][2]=0.f;o_[t][3]=0.f; }

    const int rbase = q0 + wrow + (lane>>2);
    const uint32_t* mbits_row0 = g_mbits + ((size_t)b*LQ_ + rbase)*64;

    const uint32_t aaddr = sbase + (wrow + (lane&15))*144 + ((lane&16)?16:0);
    const uint32_t boff  = ((lane&7) + ((lane&16)?8:0))*144 + ((lane&8)?16:0);
    const uint32_t voff  = ((lane&7) + ((lane&16)?8:0))*272 + ((lane&8)?16:0);

    int cur = 0;
    #pragma unroll 1
    for (int kc=0; kc<LK_; kc+=128){
        cp_wait<0>();
        __syncthreads();
        if (kc + 128 < LK_) load_kv(kc+128, cur^1);

        const uint32_t kb = sbase + (OF_K0 + cur*9216)*4;
        const uint32_t vb = sbase + (OF_V0 + cur*4352)*4;
        const uint32_t baddr = kb + boff;
        const uint32_t vaddr = vb + voff;

        // hoist mask word loads (latency overlapped with S mma loop)
        uint32_t mw0[4], mw1[4];
        #pragma unroll
        for (int c2=0;c2<4;c2++){
            mw0[c2] = mbits_row0[(kc>>5) + c2];
            mw1[c2] = mbits_row0[8*64 + (kc>>5) + c2];
        }

        float s[16][4];
        #pragma unroll
        for (int t=0;t<16;t++){ s[t][0]=0.f;s[t][1]=0.f;s[t][2]=0.f;s[t][3]=0.f; }
        #pragma unroll
        for (int ks=0; ks<4; ks++){
            uint32_t ah[4], al[4];
            ldsm_x4(ah, aaddr + ks*32);
            ldsm_x4(al, aaddr + (OF_QL-OF_QH)*4 + ks*32);
            #pragma unroll
            for (int pp=0;pp<4;pp++){
                const int p0 = 2*pp, p1 = 2*pp + 1;
                uint32_t b0h[4], b1h[4], b0l[4], b1l[4];
                ldsm_x4(b0h, baddr + p0*16*144 + ks*32);
                ldsm_x4(b1h, baddr + p1*16*144 + ks*32);
                ldsm_x4(b0l, baddr + 4608*4 + p0*16*144 + ks*32);
                ldsm_x4(b1l, baddr + 4608*4 + p1*16*144 + ks*32);
                // term hh — 4 independent accumulators
                mma16816(s[2*p0],   ah[0],ah[1],ah[2],ah[3], b0h[0],b0h[1]);
                mma16816(s[2*p0+1], ah[0],ah[1],ah[2],ah[3], b0h[2],b0h[3]);
                mma16816(s[2*p1],   ah[0],ah[1],ah[2],ah[3], b1h[0],b1h[1]);
                mma16816(s[2*p1+1], ah[0],ah[1],ah[2],ah[3], b1h[2],b1h[3]);
                // term hl
                mma16816(s[2*p0],   ah[0],ah[1],ah[2],ah[3], b0l[0],b0l[1]);
                mma16816(s[2*p0+1], ah[0],ah[1],ah[2],ah[3], b0l[2],b0l[3]);
                mma16816(s[2*p1],   ah[0],ah[1],ah[2],ah[3], b1l[0],b1l[1]);
                mma16816(s[2*p1+1], ah[0],ah[1],ah[2],ah[3], b1l[2],b1l[3]);
                // term lh
                mma16816(s[2*p0],   al[0],al[1],al[2],al[3], b0h[0],b0h[1]);
                mma16816(s[2*p0+1], al[0],al[1],al[2],al[3], b0h[2],b0h[3]);
                mma16816(s[2*p1],   al[0],al[1],al[2],al[3], b1h[0],b1h[1]);
                mma16816(s[2*p1+1], al[0],al[1],al[2],al[3], b1h[2],b1h[3]);
            }
        }

        float cm0 = -INFINITY, cm1 = -INFINITY;
        #pragma unroll
        for (int nt=0;nt<16;nt++){
            uint32_t w0 = mw0[nt>>2], w1 = mw1[nt>>2];
            int bsh = ((nt&3)<<3) + ((lane&3)<<1);
            if ((w0>>bsh)&1)     s[nt][0] = -INFINITY;
            if ((w0>>(bsh+1))&1) s[nt][1] = -INFINITY;
            if ((w1>>bsh)&1)     s[nt][2] = -INFINITY;
            if ((w1>>(bsh+1))&1) s[nt][3] = -INFINITY;
            cm0 = fmaxf(cm0, fmaxf(s[nt][0], s[nt][1]));
            cm1 = fmaxf(cm1, fmaxf(s[nt][2], s[nt][3]));
        }
        cm0 = fmaxf(cm0, __shfl_xor_sync(0xffffffffu, cm0, 1));
        cm0 = fmaxf(cm0, __shfl_xor_sync(0xffffffffu, cm0, 2));
        cm1 = fmaxf(cm1, __shfl_xor_sync(0xffffffffu, cm1, 1));
        cm1 = fmaxf(cm1, __shfl_xor_sync(0xffffffffu, cm1, 2));

        float mn0 = fmaxf(mrow0, cm0), mn1 = fmaxf(mrow1, cm1);
        float corr0 = (mrow0 == -INFINITY) ? 0.f : __expf(mrow0 - mn0);
        float corr1 = (mrow1 == -INFINITY) ? 0.f : __expf(mrow1 - mn1);

        float sum0 = 0.f, sum1 = 0.f;
        #pragma unroll
        for (int nt=0;nt<16;nt++){
            s[nt][0] = __expf(s[nt][0] - mn0);
            s[nt][1] = __expf(s[nt][1] - mn0);
            s[nt][2] = __expf(s[nt][2] - mn1);
            s[nt][3] = __expf(s[nt][3] - mn1);
            sum0 += s[nt][0] + s[nt][1];
            sum1 += s[nt][2] + s[nt][3];
        }
        sum0 += __shfl_xor_sync(0xffffffffu, sum0, 1);
        sum0 += __shfl_xor_sync(0xffffffffu, sum0, 2);
        sum1 += __shfl_xor_sync(0xffffffffu, sum1, 1);
        sum1 += __shfl_xor_sync(0xffffffffu, sum1, 2);

        lrow0 = lrow0*corr0 + sum0;
        lrow1 = lrow1*corr1 + sum1;
        mrow0 = mn0; mrow1 = mn1;

        #pragma unroll
        for (int t=0;t<8;t++){
            o_[t][0]*=corr0; o_[t][1]*=corr0; o_[t][2]*=corr1; o_[t][3]*=corr1;
        }

        float* ar0 = attn_out + ((size_t)bh*LQ_ + rbase)*LK_;
        float* ar1 = ar0 + 8*(size_t)LK_;
        #pragma unroll
        for (int nt=0;nt<16;nt++){
            int col = kc + nt*8 + 2*(lane&3);
            __stcs(reinterpret_cast<float2*>(ar0 + col), make_float2(s[nt][0], s[nt][1]));
            __stcs(reinterpret_cast<float2*>(ar1 + col), make_float2(s[nt][2], s[nt][3]));
        }
        if ((lane & 3) == 0){
            g_mchunk[((size_t)bh*LQ_ + rbase)*16 + (kc>>7)]     = mn0;
            g_mchunk[((size_t)bh*LQ_ + rbase + 8)*16 + (kc>>7)] = mn1;
        }

        #pragma unroll
        for (int kk=0;kk<8;kk++){
            uint32_t a0 = pack_bf16(s[2*kk][0],   s[2*kk][1]);
            uint32_t a1 = pack_bf16(s[2*kk][2],   s[2*kk][3]);
            uint32_t a2 = pack_bf16(s[2*kk+1][0], s[2*kk+1][1]);
            uint32_t a3 = pack_bf16(s[2*kk+1][2], s[2*kk+1][3]);
            #pragma unroll
            for (int g=0; g<4; g++){
                uint32_t bv4[4];
                ldsm_x4(bv4, vaddr + g*16*272 + kk*32);
                mma16816(o_[2*g],   a0,a1,a2,a3, bv4[0],bv4[1]);
                mma16816(o_[2*g+1], a0,a1,a2,a3, bv4[2],bv4[3]);
            }
        }
        cur ^= 1;
    }

    float inv0 = 1.f / lrow0, inv1 = 1.f / lrow1;
    #pragma unroll
    for (int nt2=0;nt2<8;nt2++){
        int dcol = nt2*8 + 2*(lane&3);
        size_t ro = ((size_t)b*LQ_ + rbase)*512 + h*32 + (dcol>>1);
        g_Hbf[ro]         = pack_bf16(o_[nt2][0]*inv0, o_[nt2][1]*inv0);
        g_Hbf[ro + 8*512] = pack_bf16(o_[nt2][2]*inv1, o_[nt2][3]*inv1);
    }
    if ((lane & 3) == 0){
        g_rowstat[(size_t)bh*LQ_ + rbase]     = make_float2(mrow0, lrow0);
        g_rowstat[(size_t)bh*LQ_ + rbase + 8] = make_float2(mrow1, lrow1);
    }
}

// ---------------- rescale ---------------------------------------------------
__global__ void rescale_kernel(float* __restrict__ attn)
{
    const int bh = blockIdx.y;
    const int qq = blockIdx.x;
    const size_t rowidx = (size_t)bh*LQ_ + qq;
    float2 st = g_rowstat[rowidx];
    int t = threadIdx.x;
    int chunk = t >> 4;
    float f = __expf(g_mchunk[rowidx*16 + chunk] - st.x) / st.y;
    float4* p = reinterpret_cast<float4*>(attn + rowidx*LK_ + t*8);
    float4 v0 = p[0], v1 = p[1];
    v0.x*=f; v0.y*=f; v0.z*=f; v0.w*=f;
    v1.x*=f; v1.y*=f; v1.z*=f; v1.w*=f;
    p[0] = v0; p[1] = v1;
}

// ---------------- launch ----------------------------------------------------
extern "C" void kernel_launch(void* const* d_in, const int* in_sizes, int n_in,
                              void* d_out, int out_size)
{
    const float* q    = (const float*)d_in[0];
    const float* k    = (const float*)d_in[1];
    const float* v    = (const float*)d_in[2];
    const int*   mask = (const int*)d_in[3];
    const float* w_qs = (const float*)d_in[4];
    const float* b_qs = (const float*)d_in[5];
    const float* w_ks = (const float*)d_in[6];
    const float* b_ks = (const float*)d_in[7];
    const float* w_vs = (const float*)d_in[8];
    const float* b_vs = (const float*)d_in[9];
    const float* fc_w = (const float*)d_in[10];
    const float* fc_b = (const float*)d_in[11];

    float* out = (float*)d_out;
    float* attn_out = out + (size_t)M_ * DM_;

    cudaFuncSetAttribute(proj_kernel, cudaFuncAttributeMaxDynamicSharedMemorySize, 4*PSTG*4);
    cudaFuncSetAttribute(fc_kernel,   cudaFuncAttributeMaxDynamicSharedMemorySize, 4*FSTG*4);
    cudaFuncSetAttribute(attn_kernel, cudaFuncAttributeMaxDynamicSharedMemorySize, ATTN_SMEM_U32*4);

    k_split_inputs<<<24576, 256>>>(q, k, v);
    k_conv_w<<<dim3(32,32,4), 256>>>(w_qs, w_ks, w_vs, fc_w);
    k_mask_bits<<<2048, 256>>>(mask);

    proj_kernel<<<dim3(8,64,3), 256, 4*PSTG*4>>>(b_qs, b_ks, b_vs);
    attn_kernel<<<dim3(16,NH_,B_), 256, ATTN_SMEM_U32*4>>>(attn_out);
    rescale_kernel<<<dim3(LQ_, B_*NH_), 256>>>(attn_out);
    fc_kernel<<<dim3(8,64), 256, 4*FSTG*4>>>(fc_b, q, out);
}

// round 12
// speedup vs baseline: 1.0020x; 1.0020x over previous
#include <cuda_runtime.h>
#include <cuda_bf16.h>
#include <math.h>
#include <stdint.h>

#define B_   4
#define LQ_  2048
#define LK_  2048
#define DM_  1024
#define NH_  16
#define M_   8192

// ---------------- device scratch (allocation-free rule) --------------------
__device__ uint32_t g_Ih[3][4194304];     // split-hi of q,k,v inputs (bf16x2)
__device__ uint32_t g_Il[3][4194304];     // split-lo (mat 2 unused)
__device__ uint32_t g_Wth[4][524288];     // transposed weights hi [n][k-pair]; idx3 = fc_w
__device__ uint32_t g_Wtl[3][524288];     // transposed weights lo
__device__ uint32_t g_Qhi[4194304], g_Qlo[4194304];   // [b,h,l,d-pair], pre-scaled 1/8
__device__ uint32_t g_Khi[4194304], g_Klo[4194304];
__device__ uint32_t g_Vh [4194304];       // V TRANSPOSED bf16 [bh*64+d][l]
__device__ uint32_t g_Hbf[4194304];       // attn output bf16 [m][k-pair] for FC
__device__ uint32_t g_mbits[524288];      // mask bitwords [b][lq][lk/32]
__device__ float    g_mchunk[(size_t)B_*NH_*LQ_*16];
__device__ float2   g_rowstat[(size_t)B_*NH_*LQ_];

// ---------------- helpers --------------------------------------------------
__device__ __forceinline__ uint32_t pack_bf16(float x, float y){
    __nv_bfloat162 t = __floats2bfloat162_rn(x, y);
    return *reinterpret_cast<uint32_t*>(&t);
}
__device__ __forceinline__ void split_u32(float x0, float x1, uint32_t& h, uint32_t& l){
    float h0 = __bfloat162float(__float2bfloat16(x0));
    float h1 = __bfloat162float(__float2bfloat16(x1));
    h = pack_bf16(h0, h1);
    l = pack_bf16(x0 - h0, x1 - h1);
}
__device__ __forceinline__ void mma16816(float* c,
    uint32_t a0, uint32_t a1, uint32_t a2, uint32_t a3, uint32_t b0, uint32_t b1){
    asm volatile("mma.sync.aligned.m16n8k16.row.col.f32.bf16.bf16.f32 "
        "{%0,%1,%2,%3}, {%4,%5,%6,%7}, {%8,%9}, {%0,%1,%2,%3};"
        : "+f"(c[0]), "+f"(c[1]), "+f"(c[2]), "+f"(c[3])
        : "r"(a0), "r"(a1), "r"(a2), "r"(a3), "r"(b0), "r"(b1));
}
__device__ __forceinline__ void ldsm_x4(uint32_t* r, uint32_t addr){
    asm volatile("ldmatrix.sync.aligned.m8n8.x4.shared.b16 {%0,%1,%2,%3}, [%4];"
        : "=r"(r[0]), "=r"(r[1]), "=r"(r[2]), "=r"(r[3]) : "r"(addr));
}
__device__ __forceinline__ void cp_async16(uint32_t saddr, const void* gaddr){
    asm volatile("cp.async.cg.shared.global [%0], [%1], 16;" :: "r"(saddr), "l"(gaddr));
}
__device__ __forceinline__ void cp_commit(){ asm volatile("cp.async.commit_group;"); }
template<int N> __device__ __forceinline__ void cp_wait(){
    asm volatile("cp.async.wait_group %0;" :: "n"(N));
}
__device__ __forceinline__ uint32_t smem_u32addr(const void* p){
    uint32_t a;
    asm("{.reg .u64 t; cvta.to.shared.u64 t, %1; cvt.u32.u64 %0, t;}" : "=r"(a) : "l"(p));
    return a;
}

// ---------------- convert kernels ------------------------------------------
__global__ void k_split_inputs(const float* __restrict__ q,
                               const float* __restrict__ k,
                               const float* __restrict__ v){
    size_t F = (size_t)blockIdx.x*256 + threadIdx.x;   // float4 index
    int mat = (int)(F >> 21);
    size_t rem = F & 2097151u;
    const float* src = mat==0 ? q : mat==1 ? k : v;
    float4 a = reinterpret_cast<const float4*>(src)[rem];
    uint32_t h0,l0,h1,l1;
    split_u32(a.x, a.y, h0, l0);
    split_u32(a.z, a.w, h1, l1);
    g_Ih[mat][rem*2]   = h0; g_Ih[mat][rem*2+1] = h1;
    if (mat < 2){                                      // V lo-plane never read
        g_Il[mat][rem*2] = l0; g_Il[mat][rem*2+1] = l1;
    }
}

__global__ void k_conv_w(const float* __restrict__ wq, const float* __restrict__ wk,
                         const float* __restrict__ wv, const float* __restrict__ fcw){
    const int mat = blockIdx.z;
    const float* W = mat==0 ? wq : mat==1 ? wk : mat==2 ? wv : fcw;
    __shared__ float T[32][33];
    const int k0 = blockIdx.y*32, n0 = blockIdx.x*32;
    const int tx = threadIdx.x & 31, ty = threadIdx.x >> 5;
    #pragma unroll
    for (int i=0;i<4;i++)
        T[ty+8*i][tx] = W[(size_t)(k0+ty+8*i)*DM_ + n0 + tx];
    __syncthreads();
    const int n = threadIdx.x >> 3;
    const int kp0 = (threadIdx.x & 7)*2;
    #pragma unroll
    for (int s2=0;s2<2;s2++){
        int kp = kp0 + s2;
        float x0 = T[kp*2][n], x1 = T[kp*2+1][n];
        uint32_t h, l; split_u32(x0, x1, h, l);
        size_t o = (size_t)(n0+n)*512 + (k0>>1) + kp;
        g_Wth[mat][o] = h;
        if (mat < 3) g_Wtl[mat][o] = l;
    }
}

__global__ void k_mask_bits(const int* __restrict__ mask){
    int wrp = blockIdx.x*8 + (threadIdx.x>>5);
    int lane = threadIdx.x & 31;
    size_t base = (size_t)wrp*32;
    for (int j=0;j<32;j++){
        size_t w = base + j;
        int mv = mask[w*32 + lane];
        uint32_t bits = __ballot_sync(0xffffffffu, mv != 0);
        if (lane==0) g_mbits[w] = bits;
    }
}

// ---------------- projection GEMM ------------------------------------------
// 128x128 tile, k16 stages x4, cp.async + ldmatrix + 3-mma split
// p-pair batched, term-major MMA order (breaks accumulator RAW chains)
// which==2 (V): single-bf16
#define PSTG 6144            // u32 per stage (4 buffers x 1536)
#define BUFB 6144            // bytes per buffer

__global__ void __launch_bounds__(256,2) proj_kernel(
    const float* __restrict__ bq, const float* __restrict__ bk,
    const float* __restrict__ bv)
{
    extern __shared__ uint32_t smp[];
    const uint32_t sbase = smem_u32addr(smp);

    const int which = blockIdx.z;
    const bool vonly = (which == 2);
    const uint32_t* gAh = g_Ih[which];
    const uint32_t* gAl = g_Il[which];
    const uint32_t* gBh = g_Wth[which];
    const uint32_t* gBl = g_Wtl[which];
    const float* bias = which==0 ? bq : which==1 ? bk : bv;

    const int m0 = blockIdx.y*128, n0 = blockIdx.x*128;
    const int tid = threadIdx.x, lane = tid & 31, wid = tid >> 5;
    const int wm = (wid & 3)*32, wn = (wid >> 2)*64;

    const int crow = tid >> 1, chalf = tid & 1;
    const uint32_t* gsrc0 = gAh + (size_t)(m0+crow)*512 + chalf*4;
    const uint32_t* gsrc1 = gAl + (size_t)(m0+crow)*512 + chalf*4;
    const uint32_t* gsrc2 = gBh + (size_t)(n0+crow)*512 + chalf*4;
    const uint32_t* gsrc3 = gBl + (size_t)(n0+crow)*512 + chalf*4;
    const uint32_t sdst = sbase + crow*48 + chalf*16;

    auto issue = [&](int itk){
        int stage = itk & 3;
        uint32_t so = sdst + stage*(PSTG*4);
        size_t ko = (size_t)itk*8;
        cp_async16(so + 0*BUFB, gsrc0 + ko);
        cp_async16(so + 2*BUFB, gsrc2 + ko);
        if (!vonly){
            cp_async16(so + 1*BUFB, gsrc1 + ko);
            cp_async16(so + 3*BUFB, gsrc3 + ko);
        }
        cp_commit();
    };

    float acc[2][8][4];
    #pragma unroll
    for (int a=0;a<2;a++)
        #pragma unroll
        for (int b2=0;b2<8;b2++){ acc[a][b2][0]=0.f;acc[a][b2][1]=0.f;acc[a][b2][2]=0.f;acc[a][b2][3]=0.f; }

    issue(0); issue(1); issue(2);

    const uint32_t arow = wm + (lane & 15);
    const uint32_t aoff0 = arow*48 + ((lane>>4)&1)*16;
    const uint32_t brow = wn + (lane & 7) + ((lane & 16) ? 8 : 0);
    const uint32_t boff0 = 2*BUFB + brow*48 + ((lane & 8) ? 16 : 0);

    #pragma unroll 1
    for (int it=0; it<64; it++){
        if (it <= 61) cp_wait<2>(); else if (it == 62) cp_wait<1>(); else cp_wait<0>();
        __syncthreads();
        if (it + 3 < 64) issue(it+3);

        uint32_t sb = sbase + (it & 3)*(PSTG*4);
        uint32_t a_h[2][4], a_l[2][4];
        ldsm_x4(a_h[0], sb + aoff0);
        ldsm_x4(a_h[1], sb + aoff0 + 16*48);
        if (!vonly){
            ldsm_x4(a_l[0], sb + aoff0 + BUFB);
            ldsm_x4(a_l[1], sb + aoff0 + BUFB + 16*48);
        }
        #pragma unroll
        for (int pp=0;pp<2;pp++){
            const int p0 = 2*pp, p1 = 2*pp + 1;
            uint32_t b0h[4], b1h[4], b0l[4], b1l[4];
            ldsm_x4(b0h, sb + boff0 + p0*16*48);
            ldsm_x4(b1h, sb + boff0 + p1*16*48);
            if (!vonly){
                ldsm_x4(b0l, sb + boff0 + BUFB + p0*16*48);
                ldsm_x4(b1l, sb + boff0 + BUFB + p1*16*48);
            }
            // term hh — 8 independent accumulators
            #pragma unroll
            for (int mt=0;mt<2;mt++){
                mma16816(acc[mt][2*p0],   a_h[mt][0],a_h[mt][1],a_h[mt][2],a_h[mt][3], b0h[0],b0h[1]);
                mma16816(acc[mt][2*p0+1], a_h[mt][0],a_h[mt][1],a_h[mt][2],a_h[mt][3], b0h[2],b0h[3]);
                mma16816(acc[mt][2*p1],   a_h[mt][0],a_h[mt][1],a_h[mt][2],a_h[mt][3], b1h[0],b1h[1]);
                mma16816(acc[mt][2*p1+1], a_h[mt][0],a_h[mt][1],a_h[mt][2],a_h[mt][3], b1h[2],b1h[3]);
            }
            if (!vonly){
                // term hl
                #pragma unroll
                for (int mt=0;mt<2;mt++){
                    mma16816(acc[mt][2*p0],   a_h[mt][0],a_h[mt][1],a_h[mt][2],a_h[mt][3], b0l[0],b0l[1]);
                    mma16816(acc[mt][2*p0+1], a_h[mt][0],a_h[mt][1],a_h[mt][2],a_h[mt][3], b0l[2],b0l[3]);
                    mma16816(acc[mt][2*p1],   a_h[mt][0],a_h[mt][1],a_h[mt][2],a_h[mt][3], b1l[0],b1l[1]);
                    mma16816(acc[mt][2*p1+1], a_h[mt][0],a_h[mt][1],a_h[mt][2],a_h[mt][3], b1l[2],b1l[3]);
                }
                // term lh
                #pragma unroll
                for (int mt=0;mt<2;mt++){
                    mma16816(acc[mt][2*p0],   a_l[mt][0],a_l[mt][1],a_l[mt][2],a_l[mt][3], b0h[0],b0h[1]);
                    mma16816(acc[mt][2*p0+1], a_l[mt][0],a_l[mt][1],a_l[mt][2],a_l[mt][3], b0h[2],b0h[3]);
                    mma16816(acc[mt][2*p1],   a_l[mt][0],a_l[mt][1],a_l[mt][2],a_l[mt][3], b1h[0],b1h[1]);
                    mma16816(acc[mt][2*p1+1], a_l[mt][0],a_l[mt][1],a_l[mt][2],a_l[mt][3], b1h[2],b1h[3]);
                }
            }
        }
    }

    const float sc = (which==0) ? 0.125f : 1.0f;
    __nv_bfloat16* vt = reinterpret_cast<__nv_bfloat16*>(g_Vh);
    #pragma unroll
    for (int mt=0;mt<2;mt++){
        int r0 = m0 + wm + mt*16 + (lane>>2);
        #pragma unroll
        for (int nt=0;nt<8;nt++){
            int col = n0 + wn + nt*8 + 2*(lane&3);
            float2 bv2 = *reinterpret_cast<const float2*>(bias + col);
            int hh = col>>6, dd = col&63;
            #pragma unroll
            for (int rr=0;rr<2;rr++){
                int r = r0 + rr*8;
                int bb2 = r>>11, ll = r&2047;
                float x0 = (acc[mt][nt][rr*2]   + bv2.x)*sc;
                float x1 = (acc[mt][nt][rr*2+1] + bv2.y)*sc;
                if (which==2){
                    size_t vb = ((size_t)(bb2*NH_+hh)*64 + dd)*2048 + ll;
                    vt[vb]        = __float2bfloat16(x0);
                    vt[vb + 2048] = __float2bfloat16(x1);
                } else {
                    size_t o = (((size_t)(bb2*NH_+hh))*LQ_ + ll)*32 + (dd>>1);
                    uint32_t h, l; split_u32(x0, x1, h, l);
                    if (which==0){ g_Qhi[o]=h; g_Qlo[o]=l; }
                    else         { g_Khi[o]=h; g_Klo[o]=l; }
                }
            }
        }
    }
}

// ---------------- FC GEMM + bias + residual --------------------------------
#define FSTG 3072

__global__ void __launch_bounds__(256,2) fc_kernel(
    const float* __restrict__ fc_b, const float* __restrict__ q_in,
    float* __restrict__ out)
{
    extern __shared__ uint32_t smf[];
    const uint32_t sbase = smem_u32addr(smf);

    const int m0 = blockIdx.y*128, n0 = blockIdx.x*128;
    const int tid = threadIdx.x, lane = tid & 31, wid = tid >> 5;
    const int wm = (wid & 3)*32, wn = (wid >> 2)*64;

    const int crow = tid >> 1, chalf = tid & 1;
    const uint32_t* gsrc0 = g_Hbf    + (size_t)(m0+crow)*512 + chalf*4;
    const uint32_t* gsrc1 = g_Wth[3] + (size_t)(n0+crow)*512 + chalf*4;
    const uint32_t sdst = sbase + crow*48 + chalf*16;

    auto issue = [&](int itk){
        int stage = itk & 3;
        uint32_t so = sdst + stage*(FSTG*4);
        size_t ko = (size_t)itk*8;
        cp_async16(so,        gsrc0 + ko);
        cp_async16(so + BUFB, gsrc1 + ko);
        cp_commit();
    };

    float acc[2][8][4];
    #pragma unroll
    for (int a=0;a<2;a++)
        #pragma unroll
        for (int b2=0;b2<8;b2++){ acc[a][b2][0]=0.f;acc[a][b2][1]=0.f;acc[a][b2][2]=0.f;acc[a][b2][3]=0.f; }

    issue(0); issue(1); issue(2);

    const uint32_t arow = wm + (lane & 15);
    const uint32_t aoff0 = arow*48 + ((lane>>4)&1)*16;
    const uint32_t brow = wn + (lane & 7) + ((lane & 16) ? 8 : 0);
    const uint32_t boff0 = BUFB + brow*48 + ((lane & 8) ? 16 : 0);

    #pragma unroll 1
    for (int it=0; it<64; it++){
        if (it <= 61) cp_wait<2>(); else if (it == 62) cp_wait<1>(); else cp_wait<0>();
        __syncthreads();
        if (it + 3 < 64) issue(it+3);

        uint32_t sb = sbase + (it & 3)*(FSTG*4);
        uint32_t a_h[2][4];
        ldsm_x4(a_h[0], sb + aoff0);
        ldsm_x4(a_h[1], sb + aoff0 + 16*48);
        #pragma unroll
        for (int p=0;p<4;p++){
            uint32_t bh4[4];
            ldsm_x4(bh4, sb + boff0 + p*16*48);
            #pragma unroll
            for (int mt=0;mt<2;mt++){
                mma16816(acc[mt][2*p],   a_h[mt][0],a_h[mt][1],a_h[mt][2],a_h[mt][3], bh4[0],bh4[1]);
                mma16816(acc[mt][2*p+1], a_h[mt][0],a_h[mt][1],a_h[mt][2],a_h[mt][3], bh4[2],bh4[3]);
            }
        }
    }

    #pragma unroll
    for (int mt=0;mt<2;mt++){
        int r0 = m0 + wm + mt*16 + (lane>>2);
        #pragma unroll
        for (int nt=0;nt<8;nt++){
            int col = n0 + wn + nt*8 + 2*(lane&3);
            float2 bv2 = *reinterpret_cast<const float2*>(fc_b + col);
            #pragma unroll
            for (int rr=0;rr<2;rr++){
                size_t idx = (size_t)(r0+rr*8)*DM_ + col;
                float2 res = *reinterpret_cast<const float2*>(q_in + idx);
                *reinterpret_cast<float2*>(out + idx) =
                    make_float2(acc[mt][nt][rr*2]+bv2.x+res.x, acc[mt][nt][rr*2+1]+bv2.y+res.y);
            }
        }
    }
}

// ---------------- attention: double-buffered cp.async ----------------------
#define QSTR 36
#define OF_QH 0
#define OF_QL 4608
#define OF_K0 9216                   // per buf: Kh 4608 + Kl 4608
#define OF_V0 27648                  // per buf: 64*68 = 4352
#define ATTN_SMEM_U32 36352          // 145408 bytes

__global__ void __launch_bounds__(256,1) attn_kernel(float* __restrict__ attn_out)
{
    extern __shared__ uint32_t smq[];
    const uint32_t sbase = smem_u32addr(smq);
    uint32_t* Qh = smq;
    uint32_t* Ql = smq + OF_QL;

    const int b  = blockIdx.z, h = blockIdx.y;
    const int q0 = blockIdx.x * 128;
    const int bh = b*NH_ + h;
    const int tid = threadIdx.x, lane = tid & 31, wid = tid >> 5;
    const int wrow = wid * 16;
    const size_t ho32 = (size_t)bh * LK_ * 32;

    // K/V chunk loader (cp.async, 48KB per chunk)
    auto load_kv = [&](int kc, int buf){
        uint32_t kb = sbase + (OF_K0 + buf*9216)*4;
        uint32_t vb = sbase + (OF_V0 + buf*4352)*4;
        #pragma unroll
        for (int p=0;p<4;p++){
            int id = tid + p*256;
            int row = id>>3, c = id&7;
            const uint32_t* ks = g_Khi + ho32 + (size_t)(kc+row)*32 + c*4;
            const uint32_t* ls = g_Klo + ho32 + (size_t)(kc+row)*32 + c*4;
            cp_async16(kb + row*144 + c*16, ks);
            cp_async16(kb + 4608*4 + row*144 + c*16, ls);
            int d = id>>4, c2 = id&15;
            const uint32_t* vs = g_Vh + ((size_t)bh*64 + d)*1024 + (kc>>1) + c2*4;
            cp_async16(vb + d*272 + c2*16, vs);
        }
        cp_commit();
    };

    load_kv(0, 0);

    // Q tile (pre-scaled, pre-split) — plain loads, overlap with cp.async
    #pragma unroll
    for (int p=0;p<4;p++){
        int item = tid + p*256;
        int row = item>>3, o = item&7;
        *reinterpret_cast<uint4*>(Qh + row*QSTR + o*4) =
            *reinterpret_cast<const uint4*>(g_Qhi + ho32 + (size_t)(q0+row)*32 + o*4);
        *reinterpret_cast<uint4*>(Ql + row*QSTR + o*4) =
            *reinterpret_cast<const uint4*>(g_Qlo + ho32 + (size_t)(q0+row)*32 + o*4);
    }

    float mrow0 = -INFINITY, mrow1 = -INFINITY;
    float lrow0 = 0.f, lrow1 = 0.f;
    float o_[8][4];
    #pragma unroll
    for (int t=0;t<8;t++){ o_[t][0]=0.f;o_[t][1]=0.f;o_[t][2]=0.f;o_[t][3]=0.f; }

    const int rbase = q0 + wrow + (lane>>2);
    const uint32_t* mbits_row0 = g_mbits + ((size_t)b*LQ_ + rbase)*64;

    const uint32_t aaddr = sbase + (wrow + (lane&15))*144 + ((lane&16)?16:0);
    const uint32_t boff  = ((lane&7) + ((lane&16)?8:0))*144 + ((lane&8)?16:0);
    const uint32_t voff  = ((lane&7) + ((lane&16)?8:0))*272 + ((lane&8)?16:0);

    int cur = 0;
    #pragma unroll 1
    for (int kc=0; kc<LK_; kc+=128){
        cp_wait<0>();
        __syncthreads();
        if (kc + 128 < LK_) load_kv(kc+128, cur^1);

        const uint32_t kb = sbase + (OF_K0 + cur*9216)*4;
        const uint32_t vb = sbase + (OF_V0 + cur*4352)*4;
        const uint32_t baddr = kb + boff;
        const uint32_t vaddr = vb + voff;

        // hoist mask word loads (latency overlapped with S mma loop)
        uint32_t mw0[4], mw1[4];
        #pragma unroll
        for (int c2=0;c2<4;c2++){
            mw0[c2] = mbits_row0[(kc>>5) + c2];
            mw1[c2] = mbits_row0[8*64 + (kc>>5) + c2];
        }

        float s[16][4];
        #pragma unroll
        for (int t=0;t<16;t++){ s[t][0]=0.f;s[t][1]=0.f;s[t][2]=0.f;s[t][3]=0.f; }
        #pragma unroll
        for (int ks=0; ks<4; ks++){
            uint32_t ah[4], al[4];
            ldsm_x4(ah, aaddr + ks*32);
            ldsm_x4(al, aaddr + (OF_QL-OF_QH)*4 + ks*32);
            #pragma unroll
            for (int p=0;p<8;p++){
                uint32_t bh4[4], bl4[4];
                ldsm_x4(bh4, baddr + p*16*144 + ks*32);
                ldsm_x4(bl4, baddr + 4608*4 + p*16*144 + ks*32);
                mma16816(s[2*p],   ah[0],ah[1],ah[2],ah[3], bh4[0],bh4[1]);
                mma16816(s[2*p+1], ah[0],ah[1],ah[2],ah[3], bh4[2],bh4[3]);
                mma16816(s[2*p],   ah[0],ah[1],ah[2],ah[3], bl4[0],bl4[1]);
                mma16816(s[2*p+1], ah[0],ah[1],ah[2],ah[3], bl4[2],bl4[3]);
                mma16816(s[2*p],   al[0],al[1],al[2],al[3], bh4[0],bh4[1]);
                mma16816(s[2*p+1], al[0],al[1],al[2],al[3], bh4[2],bh4[3]);
            }
        }

        float cm0 = -INFINITY, cm1 = -INFINITY;
        #pragma unroll
        for (int nt=0;nt<16;nt++){
            uint32_t w0 = mw0[nt>>2], w1 = mw1[nt>>2];
            int bsh = ((nt&3)<<3) + ((lane&3)<<1);
            if ((w0>>bsh)&1)     s[nt][0] = -INFINITY;
            if ((w0>>(bsh+1))&1) s[nt][1] = -INFINITY;
            if ((w1>>bsh)&1)     s[nt][2] = -INFINITY;
            if ((w1>>(bsh+1))&1) s[nt][3] = -INFINITY;
            cm0 = fmaxf(cm0, fmaxf(s[nt][0], s[nt][1]));
            cm1 = fmaxf(cm1, fmaxf(s[nt][2], s[nt][3]));
        }
        cm0 = fmaxf(cm0, __shfl_xor_sync(0xffffffffu, cm0, 1));
        cm0 = fmaxf(cm0, __shfl_xor_sync(0xffffffffu, cm0, 2));
        cm1 = fmaxf(cm1, __shfl_xor_sync(0xffffffffu, cm1, 1));
        cm1 = fmaxf(cm1, __shfl_xor_sync(0xffffffffu, cm1, 2));

        float mn0 = fmaxf(mrow0, cm0), mn1 = fmaxf(mrow1, cm1);
        float corr0 = (mrow0 == -INFINITY) ? 0.f : __expf(mrow0 - mn0);
        float corr1 = (mrow1 == -INFINITY) ? 0.f : __expf(mrow1 - mn1);

        float sum0 = 0.f, sum1 = 0.f;
        #pragma unroll
        for (int nt=0;nt<16;nt++){
            s[nt][0] = __expf(s[nt][0] - mn0);
            s[nt][1] = __expf(s[nt][1] - mn0);
            s[nt][2] = __expf(s[nt][2] - mn1);
            s[nt][3] = __expf(s[nt][3] - mn1);
            sum0 += s[nt][0] + s[nt][1];
            sum1 += s[nt][2] + s[nt][3];
        }
        sum0 += __shfl_xor_sync(0xffffffffu, sum0, 1);
        sum0 += __shfl_xor_sync(0xffffffffu, sum0, 2);
        sum1 += __shfl_xor_sync(0xffffffffu, sum1, 1);
        sum1 += __shfl_xor_sync(0xffffffffu, sum1, 2);

        lrow0 = lrow0*corr0 + sum0;
        lrow1 = lrow1*corr1 + sum1;
        mrow0 = mn0; mrow1 = mn1;

        #pragma unroll
        for (int t=0;t<8;t++){
            o_[t][0]*=corr0; o_[t][1]*=corr0; o_[t][2]*=corr1; o_[t][3]*=corr1;
        }

        float* ar0 = attn_out + ((size_t)bh*LQ_ + rbase)*LK_;
        float* ar1 = ar0 + 8*(size_t)LK_;
        #pragma unroll
        for (int nt=0;nt<16;nt++){
            int col = kc + nt*8 + 2*(lane&3);
            __stcs(reinterpret_cast<float2*>(ar0 + col), make_float2(s[nt][0], s[nt][1]));
            __stcs(reinterpret_cast<float2*>(ar1 + col), make_float2(s[nt][2], s[nt][3]));
        }
        if ((lane & 3) == 0){
            g_mchunk[((size_t)bh*LQ_ + rbase)*16 + (kc>>7)]     = mn0;
            g_mchunk[((size_t)bh*LQ_ + rbase + 8)*16 + (kc>>7)] = mn1;
        }

        #pragma unroll
        for (int kk=0;kk<8;kk++){
            uint32_t a0 = pack_bf16(s[2*kk][0],   s[2*kk][1]);
            uint32_t a1 = pack_bf16(s[2*kk][2],   s[2*kk][3]);
            uint32_t a2 = pack_bf16(s[2*kk+1][0], s[2*kk+1][1]);
            uint32_t a3 = pack_bf16(s[2*kk+1][2], s[2*kk+1][3]);
            #pragma unroll
            for (int g=0; g<4; g++){
                uint32_t bv4[4];
                ldsm_x4(bv4, vaddr + g*16*272 + kk*32);
                mma16816(o_[2*g],   a0,a1,a2,a3, bv4[0],bv4[1]);
                mma16816(o_[2*g+1], a0,a1,a2,a3, bv4[2],bv4[3]);
            }
        }
        cur ^= 1;
    }

    float inv0 = 1.f / lrow0, inv1 = 1.f / lrow1;
    #pragma unroll
    for (int nt2=0;nt2<8;nt2++){
        int dcol = nt2*8 + 2*(lane&3);
        size_t ro = ((size_t)b*LQ_ + rbase)*512 + h*32 + (dcol>>1);
        g_Hbf[ro]         = pack_bf16(o_[nt2][0]*inv0, o_[nt2][1]*inv0);
        g_Hbf[ro + 8*512] = pack_bf16(o_[nt2][2]*inv1, o_[nt2][3]*inv1);
    }
    if ((lane & 3) == 0){
        g_rowstat[(size_t)bh*LQ_ + rbase]     = make_float2(mrow0, lrow0);
        g_rowstat[(size_t)bh*LQ_ + rbase + 8] = make_float2(mrow1, lrow1);
    }
}

// ---------------- rescale ---------------------------------------------------
__global__ void rescale_kernel(float* __restrict__ attn)
{
    const int bh = blockIdx.y;
    const int qq = blockIdx.x;
    const size_t rowidx = (size_t)bh*LQ_ + qq;
    float2 st = g_rowstat[rowidx];
    int t = threadIdx.x;
    int chunk = t >> 4;
    float f = __expf(g_mchunk[rowidx*16 + chunk] - st.x) / st.y;
    float4* p = reinterpret_cast<float4*>(attn + rowidx*LK_ + t*8);
    float4 v0 = p[0], v1 = p[1];
    v0.x*=f; v0.y*=f; v0.z*=f; v0.w*=f;
    v1.x*=f; v1.y*=f; v1.z*=f; v1.w*=f;
    p[0] = v0; p[1] = v1;
}

// ---------------- launch ----------------------------------------------------
extern "C" void kernel_launch(void* const* d_in, const int* in_sizes, int n_in,
                              void* d_out, int out_size)
{
    const float* q    = (const float*)d_in[0];
    const float* k    = (const float*)d_in[1];
    const float* v    = (const float*)d_in[2];
    const int*   mask = (const int*)d_in[3];
    const float* w_qs = (const float*)d_in[4];
    const float* b_qs = (const float*)d_in[5];
    const float* w_ks = (const float*)d_in[6];
    const float* b_ks = (const float*)d_in[7];
    const float* w_vs = (const float*)d_in[8];
    const float* b_vs = (const float*)d_in[9];
    const float* fc_w = (const float*)d_in[10];
    const float* fc_b = (const float*)d_in[11];

    float* out = (float*)d_out;
    float* attn_out = out + (size_t)M_ * DM_;

    // one-time setup on the eager (non-captured) correctness call
    static cudaStream_t s1 = nullptr;
    static cudaEvent_t evFork = nullptr, evMask = nullptr, evAttn = nullptr, evResc = nullptr;
    if (s1 == nullptr){
        cudaStreamCreateWithFlags(&s1, cudaStreamNonBlocking);
        cudaEventCreateWithFlags(&evFork, cudaEventDisableTiming);
        cudaEventCreateWithFlags(&evMask, cudaEventDisableTiming);
        cudaEventCreateWithFlags(&evAttn, cudaEventDisableTiming);
        cudaEventCreateWithFlags(&evResc, cudaEventDisableTiming);
        cudaFuncSetAttribute(proj_kernel, cudaFuncAttributeMaxDynamicSharedMemorySize, 4*PSTG*4);
        cudaFuncSetAttribute(fc_kernel,   cudaFuncAttributeMaxDynamicSharedMemorySize, 4*FSTG*4);
        cudaFuncSetAttribute(attn_kernel, cudaFuncAttributeMaxDynamicSharedMemorySize, ATTN_SMEM_U32*4);
    }

    // stream 0: converts -> proj -> attn -> fc
    // stream 1 (forked):        mask-pack  (|| proj)   and   rescale (|| fc)
    k_split_inputs<<<24576, 256>>>(q, k, v);
    k_conv_w<<<dim3(32,32,4), 256>>>(w_qs, w_ks, w_vs, fc_w);

    cudaEventRecord(evFork, 0);
    cudaStreamWaitEvent(s1, evFork, 0);
    k_mask_bits<<<2048, 256, 0, s1>>>(mask);
    cudaEventRecord(evMask, s1);

    proj_kernel<<<dim3(8,64,3), 256, 4*PSTG*4>>>(b_qs, b_ks, b_vs);

    cudaStreamWaitEvent(0, evMask, 0);
    attn_kernel<<<dim3(16,NH_,B_), 256, ATTN_SMEM_U32*4>>>(attn_out);

    cudaEventRecord(evAttn, 0);
    cudaStreamWaitEvent(s1, evAttn, 0);
    rescale_kernel<<<dim3(LQ_, B_*NH_), 256, 0, s1>>>(attn_out);
    cudaEventRecord(evResc, s1);

    fc_kernel<<<dim3(8,64), 256, 4*FSTG*4>>>(fc_b, q, out);

    cudaStreamWaitEvent(0, evResc, 0);
}

// round 13
// speedup vs baseline: 1.0406x; 1.0385x over previous
#include <cuda_runtime.h>
#include <cuda_bf16.h>
#include <cuda_fp16.h>
#include <math.h>
#include <stdint.h>

#define B_   4
#define LQ_  2048
#define LK_  2048
#define DM_  1024
#define NH_  16
#define M_   8192

// ---------------- device scratch (allocation-free rule) --------------------
__device__ uint32_t g_Ih[3][4194304];     // split-hi of q,k,v inputs (bf16x2)
__device__ uint32_t g_Il[3][4194304];     // split-lo (mat 2 unused)
__device__ uint32_t g_Wth[4][524288];     // transposed weights hi [n][k-pair]; idx3 = fc_w
__device__ uint32_t g_Wtl[3][524288];     // transposed weights lo
__device__ uint32_t g_Qhi[4194304], g_Qlo[4194304];   // [b,h,l,d-pair], pre-scaled 1/8
__device__ uint32_t g_Khi[4194304], g_Klo[4194304];
__device__ uint32_t g_Vh [4194304];       // V TRANSPOSED bf16 [bh*64+d][l]
__device__ uint32_t g_Hbf[4194304];       // attn output bf16 [m][k-pair] for FC
__device__ uint32_t g_mbits[524288];      // mask bitwords [b][lq][lk/32]
__device__ uint32_t g_Pt[134217728];      // p_tilde staging, fp16x2 [bh*lq][lk/2]
__device__ float    g_mchunk[(size_t)B_*NH_*LQ_*16];
__device__ float2   g_rowstat[(size_t)B_*NH_*LQ_];

// ---------------- helpers --------------------------------------------------
__device__ __forceinline__ uint32_t pack_bf16(float x, float y){
    __nv_bfloat162 t = __floats2bfloat162_rn(x, y);
    return *reinterpret_cast<uint32_t*>(&t);
}
__device__ __forceinline__ uint32_t pack_h2(float x, float y){
    __half2 t = __floats2half2_rn(x, y);
    return *reinterpret_cast<uint32_t*>(&t);
}
__device__ __forceinline__ void split_u32(float x0, float x1, uint32_t& h, uint32_t& l){
    float h0 = __bfloat162float(__float2bfloat16(x0));
    float h1 = __bfloat162float(__float2bfloat16(x1));
    h = pack_bf16(h0, h1);
    l = pack_bf16(x0 - h0, x1 - h1);
}
__device__ __forceinline__ void mma16816(float* c,
    uint32_t a0, uint32_t a1, uint32_t a2, uint32_t a3, uint32_t b0, uint32_t b1){
    asm volatile("mma.sync.aligned.m16n8k16.row.col.f32.bf16.bf16.f32 "
        "{%0,%1,%2,%3}, {%4,%5,%6,%7}, {%8,%9}, {%0,%1,%2,%3};"
        : "+f"(c[0]), "+f"(c[1]), "+f"(c[2]), "+f"(c[3])
        : "r"(a0), "r"(a1), "r"(a2), "r"(a3), "r"(b0), "r"(b1));
}
__device__ __forceinline__ void ldsm_x4(uint32_t* r, uint32_t addr){
    asm volatile("ldmatrix.sync.aligned.m8n8.x4.shared.b16 {%0,%1,%2,%3}, [%4];"
        : "=r"(r[0]), "=r"(r[1]), "=r"(r[2]), "=r"(r[3]) : "r"(addr));
}
__device__ __forceinline__ void cp_async16(uint32_t saddr, const void* gaddr){
    asm volatile("cp.async.cg.shared.global [%0], [%1], 16;" :: "r"(saddr), "l"(gaddr));
}
__device__ __forceinline__ void cp_commit(){ asm volatile("cp.async.commit_group;"); }
template<int N> __device__ __forceinline__ void cp_wait(){
    asm volatile("cp.async.wait_group %0;" :: "n"(N));
}
__device__ __forceinline__ uint32_t smem_u32addr(const void* p){
    uint32_t a;
    asm("{.reg .u64 t; cvta.to.shared.u64 t, %1; cvt.u32.u64 %0, t;}" : "=r"(a) : "l"(p));
    return a;
}

// ---------------- convert kernels ------------------------------------------
__global__ void k_split_inputs(const float* __restrict__ q,
                               const float* __restrict__ k,
                               const float* __restrict__ v){
    size_t F = (size_t)blockIdx.x*256 + threadIdx.x;   // float4 index
    int mat = (int)(F >> 21);
    size_t rem = F & 2097151u;
    const float* src = mat==0 ? q : mat==1 ? k : v;
    float4 a = reinterpret_cast<const float4*>(src)[rem];
    uint32_t h0,l0,h1,l1;
    split_u32(a.x, a.y, h0, l0);
    split_u32(a.z, a.w, h1, l1);
    g_Ih[mat][rem*2]   = h0; g_Ih[mat][rem*2+1] = h1;
    if (mat < 2){                                      // V lo-plane never read
        g_Il[mat][rem*2] = l0; g_Il[mat][rem*2+1] = l1;
    }
}

__global__ void k_conv_w(const float* __restrict__ wq, const float* __restrict__ wk,
                         const float* __restrict__ wv, const float* __restrict__ fcw){
    const int mat = blockIdx.z;
    const float* W = mat==0 ? wq : mat==1 ? wk : mat==2 ? wv : fcw;
    __shared__ float T[32][33];
    const int k0 = blockIdx.y*32, n0 = blockIdx.x*32;
    const int tx = threadIdx.x & 31, ty = threadIdx.x >> 5;
    #pragma unroll
    for (int i=0;i<4;i++)
        T[ty+8*i][tx] = W[(size_t)(k0+ty+8*i)*DM_ + n0 + tx];
    __syncthreads();
    const int n = threadIdx.x >> 3;
    const int kp0 = (threadIdx.x & 7)*2;
    #pragma unroll
    for (int s2=0;s2<2;s2++){
        int kp = kp0 + s2;
        float x0 = T[kp*2][n], x1 = T[kp*2+1][n];
        uint32_t h, l; split_u32(x0, x1, h, l);
        size_t o = (size_t)(n0+n)*512 + (k0>>1) + kp;
        g_Wth[mat][o] = h;
        if (mat < 3) g_Wtl[mat][o] = l;
    }
}

__global__ void k_mask_bits(const int* __restrict__ mask){
    int wrp = blockIdx.x*8 + (threadIdx.x>>5);
    int lane = threadIdx.x & 31;
    size_t base = (size_t)wrp*32;
    for (int j=0;j<32;j++){
        size_t w = base + j;
        int mv = mask[w*32 + lane];
        uint32_t bits = __ballot_sync(0xffffffffu, mv != 0);
        if (lane==0) g_mbits[w] = bits;
    }
}

// ---------------- projection GEMM ------------------------------------------
// 128x128 tile, k16 stages x4, cp.async + ldmatrix + 3-mma split
// p-pair batched, term-major MMA order (breaks accumulator RAW chains)
// which==2 (V): single-bf16
#define PSTG 6144            // u32 per stage (4 buffers x 1536)
#define BUFB 6144            // bytes per buffer

__global__ void __launch_bounds__(256,2) proj_kernel(
    const float* __restrict__ bq, const float* __restrict__ bk,
    const float* __restrict__ bv)
{
    extern __shared__ uint32_t smp[];
    const uint32_t sbase = smem_u32addr(smp);

    const int which = blockIdx.z;
    const bool vonly = (which == 2);
    const uint32_t* gAh = g_Ih[which];
    const uint32_t* gAl = g_Il[which];
    const uint32_t* gBh = g_Wth[which];
    const uint32_t* gBl = g_Wtl[which];
    const float* bias = which==0 ? bq : which==1 ? bk : bv;

    const int m0 = blockIdx.y*128, n0 = blockIdx.x*128;
    const int tid = threadIdx.x, lane = tid & 31, wid = tid >> 5;
    const int wm = (wid & 3)*32, wn = (wid >> 2)*64;

    const int crow = tid >> 1, chalf = tid & 1;
    const uint32_t* gsrc0 = gAh + (size_t)(m0+crow)*512 + chalf*4;
    const uint32_t* gsrc1 = gAl + (size_t)(m0+crow)*512 + chalf*4;
    const uint32_t* gsrc2 = gBh + (size_t)(n0+crow)*512 + chalf*4;
    const uint32_t* gsrc3 = gBl + (size_t)(n0+crow)*512 + chalf*4;
    const uint32_t sdst = sbase + crow*48 + chalf*16;

    auto issue = [&](int itk){
        int stage = itk & 3;
        uint32_t so = sdst + stage*(PSTG*4);
        size_t ko = (size_t)itk*8;
        cp_async16(so + 0*BUFB, gsrc0 + ko);
        cp_async16(so + 2*BUFB, gsrc2 + ko);
        if (!vonly){
            cp_async16(so + 1*BUFB, gsrc1 + ko);
            cp_async16(so + 3*BUFB, gsrc3 + ko);
        }
        cp_commit();
    };

    float acc[2][8][4];
    #pragma unroll
    for (int a=0;a<2;a++)
        #pragma unroll
        for (int b2=0;b2<8;b2++){ acc[a][b2][0]=0.f;acc[a][b2][1]=0.f;acc[a][b2][2]=0.f;acc[a][b2][3]=0.f; }

    issue(0); issue(1); issue(2);

    const uint32_t arow = wm + (lane & 15);
    const uint32_t aoff0 = arow*48 + ((lane>>4)&1)*16;
    const uint32_t brow = wn + (lane & 7) + ((lane & 16) ? 8 : 0);
    const uint32_t boff0 = 2*BUFB + brow*48 + ((lane & 8) ? 16 : 0);

    #pragma unroll 1
    for (int it=0; it<64; it++){
        if (it <= 61) cp_wait<2>(); else if (it == 62) cp_wait<1>(); else cp_wait<0>();
        __syncthreads();
        if (it + 3 < 64) issue(it+3);

        uint32_t sb = sbase + (it & 3)*(PSTG*4);
        uint32_t a_h[2][4], a_l[2][4];
        ldsm_x4(a_h[0], sb + aoff0);
        ldsm_x4(a_h[1], sb + aoff0 + 16*48);
        if (!vonly){
            ldsm_x4(a_l[0], sb + aoff0 + BUFB);
            ldsm_x4(a_l[1], sb + aoff0 + BUFB + 16*48);
        }
        #pragma unroll
        for (int pp=0;pp<2;pp++){
            const int p0 = 2*pp, p1 = 2*pp + 1;
            uint32_t b0h[4], b1h[4], b0l[4], b1l[4];
            ldsm_x4(b0h, sb + boff0 + p0*16*48);
            ldsm_x4(b1h, sb + boff0 + p1*16*48);
            if (!vonly){
                ldsm_x4(b0l, sb + boff0 + BUFB + p0*16*48);
                ldsm_x4(b1l, sb + boff0 + BUFB + p1*16*48);
            }
            // term hh — 8 independent accumulators
            #pragma unroll
            for (int mt=0;mt<2;mt++){
                mma16816(acc[mt][2*p0],   a_h[mt][0],a_h[mt][1],a_h[mt][2],a_h[mt][3], b0h[0],b0h[1]);
                mma16816(acc[mt][2*p0+1], a_h[mt][0],a_h[mt][1],a_h[mt][2],a_h[mt][3], b0h[2],b0h[3]);
                mma16816(acc[mt][2*p1],   a_h[mt][0],a_h[mt][1],a_h[mt][2],a_h[mt][3], b1h[0],b1h[1]);
                mma16816(acc[mt][2*p1+1], a_h[mt][0],a_h[mt][1],a_h[mt][2],a_h[mt][3], b1h[2],b1h[3]);
            }
            if (!vonly){
                // term hl
                #pragma unroll
                for (int mt=0;mt<2;mt++){
                    mma16816(acc[mt][2*p0],   a_h[mt][0],a_h[mt][1],a_h[mt][2],a_h[mt][3], b0l[0],b0l[1]);
                    mma16816(acc[mt][2*p0+1], a_h[mt][0],a_h[mt][1],a_h[mt][2],a_h[mt][3], b0l[2],b0l[3]);
                    mma16816(acc[mt][2*p1],   a_h[mt][0],a_h[mt][1],a_h[mt][2],a_h[mt][3], b1l[0],b1l[1]);
                    mma16816(acc[mt][2*p1+1], a_h[mt][0],a_h[mt][1],a_h[mt][2],a_h[mt][3], b1l[2],b1l[3]);
                }
                // term lh
                #pragma unroll
                for (int mt=0;mt<2;mt++){
                    mma16816(acc[mt][2*p0],   a_l[mt][0],a_l[mt][1],a_l[mt][2],a_l[mt][3], b0h[0],b0h[1]);
                    mma16816(acc[mt][2*p0+1], a_l[mt][0],a_l[mt][1],a_l[mt][2],a_l[mt][3], b0h[2],b0h[3]);
                    mma16816(acc[mt][2*p1],   a_l[mt][0],a_l[mt][1],a_l[mt][2],a_l[mt][3], b1h[0],b1h[1]);
                    mma16816(acc[mt][2*p1+1], a_l[mt][0],a_l[mt][1],a_l[mt][2],a_l[mt][3], b1h[2],b1h[3]);
                }
            }
        }
    }

    const float sc = (which==0) ? 0.125f : 1.0f;
    __nv_bfloat16* vt = reinterpret_cast<__nv_bfloat16*>(g_Vh);
    #pragma unroll
    for (int mt=0;mt<2;mt++){
        int r0 = m0 + wm + mt*16 + (lane>>2);
        #pragma unroll
        for (int nt=0;nt<8;nt++){
            int col = n0 + wn + nt*8 + 2*(lane&3);
            float2 bv2 = *reinterpret_cast<const float2*>(bias + col);
            int hh = col>>6, dd = col&63;
            #pragma unroll
            for (int rr=0;rr<2;rr++){
                int r = r0 + rr*8;
                int bb2 = r>>11, ll = r&2047;
                float x0 = (acc[mt][nt][rr*2]   + bv2.x)*sc;
                float x1 = (acc[mt][nt][rr*2+1] + bv2.y)*sc;
                if (which==2){
                    size_t vb = ((size_t)(bb2*NH_+hh)*64 + dd)*2048 + ll;
                    vt[vb]        = __float2bfloat16(x0);
                    vt[vb + 2048] = __float2bfloat16(x1);
                } else {
                    size_t o = (((size_t)(bb2*NH_+hh))*LQ_ + ll)*32 + (dd>>1);
                    uint32_t h, l; split_u32(x0, x1, h, l);
                    if (which==0){ g_Qhi[o]=h; g_Qlo[o]=l; }
                    else         { g_Khi[o]=h; g_Klo[o]=l; }
                }
            }
        }
    }
}

// ---------------- FC GEMM + bias + residual --------------------------------
#define FSTG 3072

__global__ void __launch_bounds__(256,2) fc_kernel(
    const float* __restrict__ fc_b, const float* __restrict__ q_in,
    float* __restrict__ out)
{
    extern __shared__ uint32_t smf[];
    const uint32_t sbase = smem_u32addr(smf);

    const int m0 = blockIdx.y*128, n0 = blockIdx.x*128;
    const int tid = threadIdx.x, lane = tid & 31, wid = tid >> 5;
    const int wm = (wid & 3)*32, wn = (wid >> 2)*64;

    const int crow = tid >> 1, chalf = tid & 1;
    const uint32_t* gsrc0 = g_Hbf    + (size_t)(m0+crow)*512 + chalf*4;
    const uint32_t* gsrc1 = g_Wth[3] + (size_t)(n0+crow)*512 + chalf*4;
    const uint32_t sdst = sbase + crow*48 + chalf*16;

    auto issue = [&](int itk){
        int stage = itk & 3;
        uint32_t so = sdst + stage*(FSTG*4);
        size_t ko = (size_t)itk*8;
        cp_async16(so,        gsrc0 + ko);
        cp_async16(so + BUFB, gsrc1 + ko);
        cp_commit();
    };

    float acc[2][8][4];
    #pragma unroll
    for (int a=0;a<2;a++)
        #pragma unroll
        for (int b2=0;b2<8;b2++){ acc[a][b2][0]=0.f;acc[a][b2][1]=0.f;acc[a][b2][2]=0.f;acc[a][b2][3]=0.f; }

    issue(0); issue(1); issue(2);

    const uint32_t arow = wm + (lane & 15);
    const uint32_t aoff0 = arow*48 + ((lane>>4)&1)*16;
    const uint32_t brow = wn + (lane & 7) + ((lane & 16) ? 8 : 0);
    const uint32_t boff0 = BUFB + brow*48 + ((lane & 8) ? 16 : 0);

    #pragma unroll 1
    for (int it=0; it<64; it++){
        if (it <= 61) cp_wait<2>(); else if (it == 62) cp_wait<1>(); else cp_wait<0>();
        __syncthreads();
        if (it + 3 < 64) issue(it+3);

        uint32_t sb = sbase + (it & 3)*(FSTG*4);
        uint32_t a_h[2][4];
        ldsm_x4(a_h[0], sb + aoff0);
        ldsm_x4(a_h[1], sb + aoff0 + 16*48);
        #pragma unroll
        for (int p=0;p<4;p++){
            uint32_t bh4[4];
            ldsm_x4(bh4, sb + boff0 + p*16*48);
            #pragma unroll
            for (int mt=0;mt<2;mt++){
                mma16816(acc[mt][2*p],   a_h[mt][0],a_h[mt][1],a_h[mt][2],a_h[mt][3], bh4[0],bh4[1]);
                mma16816(acc[mt][2*p+1], a_h[mt][0],a_h[mt][1],a_h[mt][2],a_h[mt][3], bh4[2],bh4[3]);
            }
        }
    }

    #pragma unroll
    for (int mt=0;mt<2;mt++){
        int r0 = m0 + wm + mt*16 + (lane>>2);
        #pragma unroll
        for (int nt=0;nt<8;nt++){
            int col = n0 + wn + nt*8 + 2*(lane&3);
            float2 bv2 = *reinterpret_cast<const float2*>(fc_b + col);
            #pragma unroll
            for (int rr=0;rr<2;rr++){
                size_t idx = (size_t)(r0+rr*8)*DM_ + col;
                float2 res = *reinterpret_cast<const float2*>(q_in + idx);
                *reinterpret_cast<float2*>(out + idx) =
                    make_float2(acc[mt][nt][rr*2]+bv2.x+res.x, acc[mt][nt][rr*2+1]+bv2.y+res.y);
            }
        }
    }
}

// ---------------- attention: double-buffered cp.async, fp16 p_tilde --------
#define QSTR 36
#define OF_QH 0
#define OF_QL 4608
#define OF_K0 9216                   // per buf: Kh 4608 + Kl 4608
#define OF_V0 27648                  // per buf: 64*68 = 4352
#define ATTN_SMEM_U32 36352          // 145408 bytes

__global__ void __launch_bounds__(256,1) attn_kernel()
{
    extern __shared__ uint32_t smq[];
    const uint32_t sbase = smem_u32addr(smq);
    uint32_t* Qh = smq;
    uint32_t* Ql = smq + OF_QL;

    const int b  = blockIdx.z, h = blockIdx.y;
    const int q0 = blockIdx.x * 128;
    const int bh = b*NH_ + h;
    const int tid = threadIdx.x, lane = tid & 31, wid = tid >> 5;
    const int wrow = wid * 16;
    const size_t ho32 = (size_t)bh * LK_ * 32;

    // K/V chunk loader (cp.async, 48KB per chunk)
    auto load_kv = [&](int kc, int buf){
        uint32_t kb = sbase + (OF_K0 + buf*9216)*4;
        uint32_t vb = sbase + (OF_V0 + buf*4352)*4;
        #pragma unroll
        for (int p=0;p<4;p++){
            int id = tid + p*256;
            int row = id>>3, c = id&7;
            const uint32_t* ks = g_Khi + ho32 + (size_t)(kc+row)*32 + c*4;
            const uint32_t* ls = g_Klo + ho32 + (size_t)(kc+row)*32 + c*4;
            cp_async16(kb + row*144 + c*16, ks);
            cp_async16(kb + 4608*4 + row*144 + c*16, ls);
            int d = id>>4, c2 = id&15;
            const uint32_t* vs = g_Vh + ((size_t)bh*64 + d)*1024 + (kc>>1) + c2*4;
            cp_async16(vb + d*272 + c2*16, vs);
        }
        cp_commit();
    };

    load_kv(0, 0);

    // Q tile (pre-scaled, pre-split) — plain loads, overlap with cp.async
    #pragma unroll
    for (int p=0;p<4;p++){
        int item = tid + p*256;
        int row = item>>3, o = item&7;
        *reinterpret_cast<uint4*>(Qh + row*QSTR + o*4) =
            *reinterpret_cast<const uint4*>(g_Qhi + ho32 + (size_t)(q0+row)*32 + o*4);
        *reinterpret_cast<uint4*>(Ql + row*QSTR + o*4) =
            *reinterpret_cast<const uint4*>(g_Qlo + ho32 + (size_t)(q0+row)*32 + o*4);
    }

    float mrow0 = -INFINITY, mrow1 = -INFINITY;
    float lrow0 = 0.f, lrow1 = 0.f;
    float o_[8][4];
    #pragma unroll
    for (int t=0;t<8;t++){ o_[t][0]=0.f;o_[t][1]=0.f;o_[t][2]=0.f;o_[t][3]=0.f; }

    const int rbase = q0 + wrow + (lane>>2);
    const uint32_t* mbits_row0 = g_mbits + ((size_t)b*LQ_ + rbase)*64;

    const uint32_t aaddr = sbase + (wrow + (lane&15))*144 + ((lane&16)?16:0);
    const uint32_t boff  = ((lane&7) + ((lane&16)?8:0))*144 + ((lane&8)?16:0);
    const uint32_t voff  = ((lane&7) + ((lane&16)?8:0))*272 + ((lane&8)?16:0);

    int cur = 0;
    #pragma unroll 1
    for (int kc=0; kc<LK_; kc+=128){
        cp_wait<0>();
        __syncthreads();
        if (kc + 128 < LK_) load_kv(kc+128, cur^1);

        const uint32_t kb = sbase + (OF_K0 + cur*9216)*4;
        const uint32_t vb = sbase + (OF_V0 + cur*4352)*4;
        const uint32_t baddr = kb + boff;
        const uint32_t vaddr = vb + voff;

        // hoist mask word loads (latency overlapped with S mma loop)
        uint32_t mw0[4], mw1[4];
        #pragma unroll
        for (int c2=0;c2<4;c2++){
            mw0[c2] = mbits_row0[(kc>>5) + c2];
            mw1[c2] = mbits_row0[8*64 + (kc>>5) + c2];
        }

        float s[16][4];
        #pragma unroll
        for (int t=0;t<16;t++){ s[t][0]=0.f;s[t][1]=0.f;s[t][2]=0.f;s[t][3]=0.f; }
        #pragma unroll
        for (int ks=0; ks<4; ks++){
            uint32_t ah[4], al[4];
            ldsm_x4(ah, aaddr + ks*32);
            ldsm_x4(al, aaddr + (OF_QL-OF_QH)*4 + ks*32);
            #pragma unroll
            for (int p=0;p<8;p++){
                uint32_t bh4[4], bl4[4];
                ldsm_x4(bh4, baddr + p*16*144 + ks*32);
                ldsm_x4(bl4, baddr + 4608*4 + p*16*144 + ks*32);
                mma16816(s[2*p],   ah[0],ah[1],ah[2],ah[3], bh4[0],bh4[1]);
                mma16816(s[2*p+1], ah[0],ah[1],ah[2],ah[3], bh4[2],bh4[3]);
                mma16816(s[2*p],   ah[0],ah[1],ah[2],ah[3], bl4[0],bl4[1]);
                mma16816(s[2*p+1], ah[0],ah[1],ah[2],ah[3], bl4[2],bl4[3]);
                mma16816(s[2*p],   al[0],al[1],al[2],al[3], bh4[0],bh4[1]);
                mma16816(s[2*p+1], al[0],al[1],al[2],al[3], bh4[2],bh4[3]);
            }
        }

        float cm0 = -INFINITY, cm1 = -INFINITY;
        #pragma unroll
        for (int nt=0;nt<16;nt++){
            uint32_t w0 = mw0[nt>>2], w1 = mw1[nt>>2];
            int bsh = ((nt&3)<<3) + ((lane&3)<<1);
            if ((w0>>bsh)&1)     s[nt][0] = -INFINITY;
            if ((w0>>(bsh+1))&1) s[nt][1] = -INFINITY;
            if ((w1>>bsh)&1)     s[nt][2] = -INFINITY;
            if ((w1>>(bsh+1))&1) s[nt][3] = -INFINITY;
            cm0 = fmaxf(cm0, fmaxf(s[nt][0], s[nt][1]));
            cm1 = fmaxf(cm1, fmaxf(s[nt][2], s[nt][3]));
        }
        cm0 = fmaxf(cm0, __shfl_xor_sync(0xffffffffu, cm0, 1));
        cm0 = fmaxf(cm0, __shfl_xor_sync(0xffffffffu, cm0, 2));
        cm1 = fmaxf(cm1, __shfl_xor_sync(0xffffffffu, cm1, 1));
        cm1 = fmaxf(cm1, __shfl_xor_sync(0xffffffffu, cm1, 2));

        float mn0 = fmaxf(mrow0, cm0), mn1 = fmaxf(mrow1, cm1);
        float corr0 = (mrow0 == -INFINITY) ? 0.f : __expf(mrow0 - mn0);
        float corr1 = (mrow1 == -INFINITY) ? 0.f : __expf(mrow1 - mn1);

        float sum0 = 0.f, sum1 = 0.f;
        #pragma unroll
        for (int nt=0;nt<16;nt++){
            s[nt][0] = __expf(s[nt][0] - mn0);
            s[nt][1] = __expf(s[nt][1] - mn0);
            s[nt][2] = __expf(s[nt][2] - mn1);
            s[nt][3] = __expf(s[nt][3] - mn1);
            sum0 += s[nt][0] + s[nt][1];
            sum1 += s[nt][2] + s[nt][3];
        }
        sum0 += __shfl_xor_sync(0xffffffffu, sum0, 1);
        sum0 += __shfl_xor_sync(0xffffffffu, sum0, 2);
        sum1 += __shfl_xor_sync(0xffffffffu, sum1, 1);
        sum1 += __shfl_xor_sync(0xffffffffu, sum1, 2);

        lrow0 = lrow0*corr0 + sum0;
        lrow1 = lrow1*corr1 + sum1;
        mrow0 = mn0; mrow1 = mn1;

        #pragma unroll
        for (int t=0;t<8;t++){
            o_[t][0]*=corr0; o_[t][1]*=corr0; o_[t][2]*=corr1; o_[t][3]*=corr1;
        }

        // write p_tilde as fp16x2 (halves store traffic; rescale expands to fp32)
        uint32_t* pr0 = g_Pt + ((size_t)bh*LQ_ + rbase)*(LK_/2);
        uint32_t* pr1 = pr0 + 8*(size_t)(LK_/2);
        #pragma unroll
        for (int nt=0;nt<16;nt++){
            int colh = (kc + nt*8 + 2*(lane&3)) >> 1;
            __stcs(pr0 + colh, pack_h2(s[nt][0], s[nt][1]));
            __stcs(pr1 + colh, pack_h2(s[nt][2], s[nt][3]));
        }
        if ((lane & 3) == 0){
            g_mchunk[((size_t)bh*LQ_ + rbase)*16 + (kc>>7)]     = mn0;
            g_mchunk[((size_t)bh*LQ_ + rbase + 8)*16 + (kc>>7)] = mn1;
        }

        #pragma unroll
        for (int kk=0;kk<8;kk++){
            uint32_t a0 = pack_bf16(s[2*kk][0],   s[2*kk][1]);
            uint32_t a1 = pack_bf16(s[2*kk][2],   s[2*kk][3]);
            uint32_t a2 = pack_bf16(s[2*kk+1][0], s[2*kk+1][1]);
            uint32_t a3 = pack_bf16(s[2*kk+1][2], s[2*kk+1][3]);
            #pragma unroll
            for (int g=0; g<4; g++){
                uint32_t bv4[4];
                ldsm_x4(bv4, vaddr + g*16*272 + kk*32);
                mma16816(o_[2*g],   a0,a1,a2,a3, bv4[0],bv4[1]);
                mma16816(o_[2*g+1], a0,a1,a2,a3, bv4[2],bv4[3]);
            }
        }
        cur ^= 1;
    }

    float inv0 = 1.f / lrow0, inv1 = 1.f / lrow1;
    #pragma unroll
    for (int nt2=0;nt2<8;nt2++){
        int dcol = nt2*8 + 2*(lane&3);
        size_t ro = ((size_t)b*LQ_ + rbase)*512 + h*32 + (dcol>>1);
        g_Hbf[ro]         = pack_bf16(o_[nt2][0]*inv0, o_[nt2][1]*inv0);
        g_Hbf[ro + 8*512] = pack_bf16(o_[nt2][2]*inv1, o_[nt2][3]*inv1);
    }
    if ((lane & 3) == 0){
        g_rowstat[(size_t)bh*LQ_ + rbase]     = make_float2(mrow0, lrow0);
        g_rowstat[(size_t)bh*LQ_ + rbase + 8] = make_float2(mrow1, lrow1);
    }
}

// ---------------- rescale: fp16 p_tilde -> fp32 probs ----------------------
__global__ void rescale_kernel(float* __restrict__ attn)
{
    const int bh = blockIdx.y;
    const int qq = blockIdx.x;
    const size_t rowidx = (size_t)bh*LQ_ + qq;
    float2 st = g_rowstat[rowidx];
    int t = threadIdx.x;
    int chunk = t >> 4;
    float f = __expf(g_mchunk[rowidx*16 + chunk] - st.x) / st.y;
    const uint32_t* src = g_Pt + rowidx*(LK_/2) + t*4;
    uint32_t a0 = __ldcs(src), a1 = __ldcs(src+1), a2 = __ldcs(src+2), a3 = __ldcs(src+3);
    float2 f0 = __half22float2(*reinterpret_cast<__half2*>(&a0));
    float2 f1 = __half22float2(*reinterpret_cast<__half2*>(&a1));
    float2 f2 = __half22float2(*reinterpret_cast<__half2*>(&a2));
    float2 f3 = __half22float2(*reinterpret_cast<__half2*>(&a3));
    float4* p = reinterpret_cast<float4*>(attn + rowidx*LK_ + t*8);
    p[0] = make_float4(f0.x*f, f0.y*f, f1.x*f, f1.y*f);
    p[1] = make_float4(f2.x*f, f2.y*f, f3.x*f, f3.y*f);
}

// ---------------- launch ----------------------------------------------------
extern "C" void kernel_launch(void* const* d_in, const int* in_sizes, int n_in,
                              void* d_out, int out_size)
{
    const float* q    = (const float*)d_in[0];
    const float* k    = (const float*)d_in[1];
    const float* v    = (const float*)d_in[2];
    const int*   mask = (const int*)d_in[3];
    const float* w_qs = (const float*)d_in[4];
    const float* b_qs = (const float*)d_in[5];
    const float* w_ks = (const float*)d_in[6];
    const float* b_ks = (const float*)d_in[7];
    const float* w_vs = (const float*)d_in[8];
    const float* b_vs = (const float*)d_in[9];
    const float* fc_w = (const float*)d_in[10];
    const float* fc_b = (const float*)d_in[11];

    float* out = (float*)d_out;
    float* attn_out = out + (size_t)M_ * DM_;

    // one-time setup on the eager (non-captured) correctness call
    static cudaStream_t s1 = nullptr;
    static cudaEvent_t evFork = nullptr, evMask = nullptr, evAttn = nullptr, evResc = nullptr;
    if (s1 == nullptr){
        cudaStreamCreateWithFlags(&s1, cudaStreamNonBlocking);
        cudaEventCreateWithFlags(&evFork, cudaEventDisableTiming);
        cudaEventCreateWithFlags(&evMask, cudaEventDisableTiming);
        cudaEventCreateWithFlags(&evAttn, cudaEventDisableTiming);
        cudaEventCreateWithFlags(&evResc, cudaEventDisableTiming);
        cudaFuncSetAttribute(proj_kernel, cudaFuncAttributeMaxDynamicSharedMemorySize, 4*PSTG*4);
        cudaFuncSetAttribute(fc_kernel,   cudaFuncAttributeMaxDynamicSharedMemorySize, 4*FSTG*4);
        cudaFuncSetAttribute(attn_kernel, cudaFuncAttributeMaxDynamicSharedMemorySize, ATTN_SMEM_U32*4);
    }

    // stream 0: converts -> proj -> attn -> fc
    // stream 1 (forked):        mask-pack  (|| proj)   and   rescale (|| fc)
    k_split_inputs<<<24576, 256>>>(q, k, v);
    k_conv_w<<<dim3(32,32,4), 256>>>(w_qs, w_ks, w_vs, fc_w);

    cudaEventRecord(evFork, 0);
    cudaStreamWaitEvent(s1, evFork, 0);
    k_mask_bits<<<2048, 256, 0, s1>>>(mask);
    cudaEventRecord(evMask, s1);

    proj_kernel<<<dim3(8,64,3), 256, 4*PSTG*4>>>(b_qs, b_ks, b_vs);

    cudaStreamWaitEvent(0, evMask, 0);
    attn_kernel<<<dim3(16,NH_,B_), 256, ATTN_SMEM_U32*4>>>();

    cudaEventRecord(evAttn, 0);
    cudaStreamWaitEvent(s1, evAttn, 0);
    rescale_kernel<<<dim3(LQ_, B_*NH_), 256, 0, s1>>>(attn_out);
    cudaEventRecord(evResc, s1);

    fc_kernel<<<dim3(8,64), 256, 4*FSTG*4>>>(fc_b, q, out);

    cudaStreamWaitEvent(0, evResc, 0);
}

// round 14
// speedup vs baseline: 1.1093x; 1.0660x over previous
#include <cuda_runtime.h>
#include <cuda_bf16.h>
#include <cuda_fp16.h>
#include <math.h>
#include <stdint.h>

#define B_   4
#define LQ_  2048
#define LK_  2048
#define DM_  1024
#define NH_  16
#define M_   8192

// ---------------- device scratch (allocation-free rule) --------------------
__device__ uint32_t g_Ih[3][4194304];     // split-hi of q,k,v inputs (bf16x2)
__device__ uint32_t g_Il[3][4194304];     // split-lo (mat 2 unused)
__device__ uint32_t g_Wth[4][524288];     // transposed weights hi [n][k-pair]; idx3 = fc_w
__device__ uint32_t g_Wtl[3][524288];     // transposed weights lo
__device__ uint32_t g_Qhi[4194304], g_Qlo[4194304];   // [b,h,l,d-pair], pre-scaled 1/8
__device__ uint32_t g_Khi[4194304], g_Klo[4194304];
__device__ uint32_t g_Vh [4194304];       // V TRANSPOSED bf16 [bh*64+d][l]
__device__ uint32_t g_Hbf[4194304];       // attn output bf16 [m][k-pair] for FC
__device__ uint32_t g_mbits[524288];      // mask bitwords [b][lq][lk/32]
__device__ uint32_t g_Pt[134217728];      // p_tilde staging, fp16x2 [bh*lq][lk/2]
__device__ float    g_mchunk[(size_t)B_*NH_*LQ_*32];
__device__ float2   g_rowstat[(size_t)B_*NH_*LQ_];

// ---------------- helpers --------------------------------------------------
__device__ __forceinline__ uint32_t pack_bf16(float x, float y){
    __nv_bfloat162 t = __floats2bfloat162_rn(x, y);
    return *reinterpret_cast<uint32_t*>(&t);
}
__device__ __forceinline__ uint32_t pack_h2(float x, float y){
    __half2 t = __floats2half2_rn(x, y);
    return *reinterpret_cast<uint32_t*>(&t);
}
__device__ __forceinline__ void split_u32(float x0, float x1, uint32_t& h, uint32_t& l){
    float h0 = __bfloat162float(__float2bfloat16(x0));
    float h1 = __bfloat162float(__float2bfloat16(x1));
    h = pack_bf16(h0, h1);
    l = pack_bf16(x0 - h0, x1 - h1);
}
__device__ __forceinline__ void mma16816(float* c,
    uint32_t a0, uint32_t a1, uint32_t a2, uint32_t a3, uint32_t b0, uint32_t b1){
    asm volatile("mma.sync.aligned.m16n8k16.row.col.f32.bf16.bf16.f32 "
        "{%0,%1,%2,%3}, {%4,%5,%6,%7}, {%8,%9}, {%0,%1,%2,%3};"
        : "+f"(c[0]), "+f"(c[1]), "+f"(c[2]), "+f"(c[3])
        : "r"(a0), "r"(a1), "r"(a2), "r"(a3), "r"(b0), "r"(b1));
}
__device__ __forceinline__ void ldsm_x4(uint32_t* r, uint32_t addr){
    asm volatile("ldmatrix.sync.aligned.m8n8.x4.shared.b16 {%0,%1,%2,%3}, [%4];"
        : "=r"(r[0]), "=r"(r[1]), "=r"(r[2]), "=r"(r[3]) : "r"(addr));
}
__device__ __forceinline__ void cp_async16(uint32_t saddr, const void* gaddr){
    asm volatile("cp.async.cg.shared.global [%0], [%1], 16;" :: "r"(saddr), "l"(gaddr));
}
__device__ __forceinline__ void cp_commit(){ asm volatile("cp.async.commit_group;"); }
template<int N> __device__ __forceinline__ void cp_wait(){
    asm volatile("cp.async.wait_group %0;" :: "n"(N));
}
__device__ __forceinline__ uint32_t smem_u32addr(const void* p){
    uint32_t a;
    asm("{.reg .u64 t; cvta.to.shared.u64 t, %1; cvt.u32.u64 %0, t;}" : "=r"(a) : "l"(p));
    return a;
}

// ---------------- convert kernels ------------------------------------------
__global__ void k_split_inputs(const float* __restrict__ q,
                               const float* __restrict__ k,
                               const float* __restrict__ v){
    size_t F = (size_t)blockIdx.x*256 + threadIdx.x;   // float4 index
    int mat = (int)(F >> 21);
    size_t rem = F & 2097151u;
    const float* src = mat==0 ? q : mat==1 ? k : v;
    float4 a = reinterpret_cast<const float4*>(src)[rem];
    uint32_t h0,l0,h1,l1;
    split_u32(a.x, a.y, h0, l0);
    split_u32(a.z, a.w, h1, l1);
    g_Ih[mat][rem*2]   = h0; g_Ih[mat][rem*2+1] = h1;
    if (mat < 2){
        g_Il[mat][rem*2] = l0; g_Il[mat][rem*2+1] = l1;
    }
}

__global__ void k_conv_w(const float* __restrict__ wq, const float* __restrict__ wk,
                         const float* __restrict__ wv, const float* __restrict__ fcw){
    const int mat = blockIdx.z;
    const float* W = mat==0 ? wq : mat==1 ? wk : mat==2 ? wv : fcw;
    __shared__ float T[32][33];
    const int k0 = blockIdx.y*32, n0 = blockIdx.x*32;
    const int tx = threadIdx.x & 31, ty = threadIdx.x >> 5;
    #pragma unroll
    for (int i=0;i<4;i++)
        T[ty+8*i][tx] = W[(size_t)(k0+ty+8*i)*DM_ + n0 + tx];
    __syncthreads();
    const int n = threadIdx.x >> 3;
    const int kp0 = (threadIdx.x & 7)*2;
    #pragma unroll
    for (int s2=0;s2<2;s2++){
        int kp = kp0 + s2;
        float x0 = T[kp*2][n], x1 = T[kp*2+1][n];
        uint32_t h, l; split_u32(x0, x1, h, l);
        size_t o = (size_t)(n0+n)*512 + (k0>>1) + kp;
        g_Wth[mat][o] = h;
        if (mat < 3) g_Wtl[mat][o] = l;
    }
}

__global__ void k_mask_bits(const int* __restrict__ mask){
    int wrp = blockIdx.x*8 + (threadIdx.x>>5);
    int lane = threadIdx.x & 31;
    size_t base = (size_t)wrp*32;
    for (int j=0;j<32;j++){
        size_t w = base + j;
        int mv = mask[w*32 + lane];
        uint32_t bits = __ballot_sync(0xffffffffu, mv != 0);
        if (lane==0) g_mbits[w] = bits;
    }
}

// ---------------- projection GEMM ------------------------------------------
#define PSTG 6144
#define BUFB 6144

__global__ void __launch_bounds__(256,2) proj_kernel(
    const float* __restrict__ bq, const float* __restrict__ bk,
    const float* __restrict__ bv)
{
    extern __shared__ uint32_t smp[];
    const uint32_t sbase = smem_u32addr(smp);

    const int which = blockIdx.z;
    const bool vonly = (which == 2);
    const uint32_t* gAh = g_Ih[which];
    const uint32_t* gAl = g_Il[which];
    const uint32_t* gBh = g_Wth[which];
    const uint32_t* gBl = g_Wtl[which];
    const float* bias = which==0 ? bq : which==1 ? bk : bv;

    const int m0 = blockIdx.y*128, n0 = blockIdx.x*128;
    const int tid = threadIdx.x, lane = tid & 31, wid = tid >> 5;
    const int wm = (wid & 3)*32, wn = (wid >> 2)*64;

    const int crow = tid >> 1, chalf = tid & 1;
    const uint32_t* gsrc0 = gAh + (size_t)(m0+crow)*512 + chalf*4;
    const uint32_t* gsrc1 = gAl + (size_t)(m0+crow)*512 + chalf*4;
    const uint32_t* gsrc2 = gBh + (size_t)(n0+crow)*512 + chalf*4;
    const uint32_t* gsrc3 = gBl + (size_t)(n0+crow)*512 + chalf*4;
    const uint32_t sdst = sbase + crow*48 + chalf*16;

    auto issue = [&](int itk){
        int stage = itk & 3;
        uint32_t so = sdst + stage*(PSTG*4);
        size_t ko = (size_t)itk*8;
        cp_async16(so + 0*BUFB, gsrc0 + ko);
        cp_async16(so + 2*BUFB, gsrc2 + ko);
        if (!vonly){
            cp_async16(so + 1*BUFB, gsrc1 + ko);
            cp_async16(so + 3*BUFB, gsrc3 + ko);
        }
        cp_commit();
    };

    float acc[2][8][4];
    #pragma unroll
    for (int a=0;a<2;a++)
        #pragma unroll
        for (int b2=0;b2<8;b2++){ acc[a][b2][0]=0.f;acc[a][b2][1]=0.f;acc[a][b2][2]=0.f;acc[a][b2][3]=0.f; }

    issue(0); issue(1); issue(2);

    const uint32_t arow = wm + (lane & 15);
    const uint32_t aoff0 = arow*48 + ((lane>>4)&1)*16;
    const uint32_t brow = wn + (lane & 7) + ((lane & 16) ? 8 : 0);
    const uint32_t boff0 = 2*BUFB + brow*48 + ((lane & 8) ? 16 : 0);

    #pragma unroll 1
    for (int it=0; it<64; it++){
        if (it <= 61) cp_wait<2>(); else if (it == 62) cp_wait<1>(); else cp_wait<0>();
        __syncthreads();
        if (it + 3 < 64) issue(it+3);

        uint32_t sb = sbase + (it & 3)*(PSTG*4);
        uint32_t a_h[2][4], a_l[2][4];
        ldsm_x4(a_h[0], sb + aoff0);
        ldsm_x4(a_h[1], sb + aoff0 + 16*48);
        if (!vonly){
            ldsm_x4(a_l[0], sb + aoff0 + BUFB);
            ldsm_x4(a_l[1], sb + aoff0 + BUFB + 16*48);
        }
        #pragma unroll
        for (int pp=0;pp<2;pp++){
            const int p0 = 2*pp, p1 = 2*pp + 1;
            uint32_t b0h[4], b1h[4], b0l[4], b1l[4];
            ldsm_x4(b0h, sb + boff0 + p0*16*48);
            ldsm_x4(b1h, sb + boff0 + p1*16*48);
            if (!vonly){
                ldsm_x4(b0l, sb + boff0 + BUFB + p0*16*48);
                ldsm_x4(b1l, sb + boff0 + BUFB + p1*16*48);
            }
            #pragma unroll
            for (int mt=0;mt<2;mt++){
                mma16816(acc[mt][2*p0],   a_h[mt][0],a_h[mt][1],a_h[mt][2],a_h[mt][3], b0h[0],b0h[1]);
                mma16816(acc[mt][2*p0+1], a_h[mt][0],a_h[mt][1],a_h[mt][2],a_h[mt][3], b0h[2],b0h[3]);
                mma16816(acc[mt][2*p1],   a_h[mt][0],a_h[mt][1],a_h[mt][2],a_h[mt][3], b1h[0],b1h[1]);
                mma16816(acc[mt][2*p1+1], a_h[mt][0],a_h[mt][1],a_h[mt][2],a_h[mt][3], b1h[2],b1h[3]);
            }
            if (!vonly){
                #pragma unroll
                for (int mt=0;mt<2;mt++){
                    mma16816(acc[mt][2*p0],   a_h[mt][0],a_h[mt][1],a_h[mt][2],a_h[mt][3], b0l[0],b0l[1]);
                    mma16816(acc[mt][2*p0+1], a_h[mt][0],a_h[mt][1],a_h[mt][2],a_h[mt][3], b0l[2],b0l[3]);
                    mma16816(acc[mt][2*p1],   a_h[mt][0],a_h[mt][1],a_h[mt][2],a_h[mt][3], b1l[0],b1l[1]);
                    mma16816(acc[mt][2*p1+1], a_h[mt][0],a_h[mt][1],a_h[mt][2],a_h[mt][3], b1l[2],b1l[3]);
                }
                #pragma unroll
                for (int mt=0;mt<2;mt++){
                    mma16816(acc[mt][2*p0],   a_l[mt][0],a_l[mt][1],a_l[mt][2],a_l[mt][3], b0h[0],b0h[1]);
                    mma16816(acc[mt][2*p0+1], a_l[mt][0],a_l[mt][1],a_l[mt][2],a_l[mt][3], b0h[2],b0h[3]);
                    mma16816(acc[mt][2*p1],   a_l[mt][0],a_l[mt][1],a_l[mt][2],a_l[mt][3], b1h[0],b1h[1]);
                    mma16816(acc[mt][2*p1+1], a_l[mt][0],a_l[mt][1],a_l[mt][2],a_l[mt][3], b1h[2],b1h[3]);
                }
            }
        }
    }

    const float sc = (which==0) ? 0.125f : 1.0f;
    __nv_bfloat16* vt = reinterpret_cast<__nv_bfloat16*>(g_Vh);
    #pragma unroll
    for (int mt=0;mt<2;mt++){
        int r0 = m0 + wm + mt*16 + (lane>>2);
        #pragma unroll
        for (int nt=0;nt<8;nt++){
            int col = n0 + wn + nt*8 + 2*(lane&3);
            float2 bv2 = *reinterpret_cast<const float2*>(bias + col);
            int hh = col>>6, dd = col&63;
            #pragma unroll
            for (int rr=0;rr<2;rr++){
                int r = r0 + rr*8;
                int bb2 = r>>11, ll = r&2047;
                float x0 = (acc[mt][nt][rr*2]   + bv2.x)*sc;
                float x1 = (acc[mt][nt][rr*2+1] + bv2.y)*sc;
                if (which==2){
                    size_t vb = ((size_t)(bb2*NH_+hh)*64 + dd)*2048 + ll;
                    vt[vb]        = __float2bfloat16(x0);
                    vt[vb + 2048] = __float2bfloat16(x1);
                } else {
                    size_t o = (((size_t)(bb2*NH_+hh))*LQ_ + ll)*32 + (dd>>1);
                    uint32_t h, l; split_u32(x0, x1, h, l);
                    if (which==0){ g_Qhi[o]=h; g_Qlo[o]=l; }
                    else         { g_Khi[o]=h; g_Klo[o]=l; }
                }
            }
        }
    }
}

// ---------------- FC GEMM + bias + residual --------------------------------
#define FSTG 3072

__global__ void __launch_bounds__(256,2) fc_kernel(
    const float* __restrict__ fc_b, const float* __restrict__ q_in,
    float* __restrict__ out)
{
    extern __shared__ uint32_t smf[];
    const uint32_t sbase = smem_u32addr(smf);

    const int m0 = blockIdx.y*128, n0 = blockIdx.x*128;
    const int tid = threadIdx.x, lane = tid & 31, wid = tid >> 5;
    const int wm = (wid & 3)*32, wn = (wid >> 2)*64;

    const int crow = tid >> 1, chalf = tid & 1;
    const uint32_t* gsrc0 = g_Hbf    + (size_t)(m0+crow)*512 + chalf*4;
    const uint32_t* gsrc1 = g_Wth[3] + (size_t)(n0+crow)*512 + chalf*4;
    const uint32_t sdst = sbase + crow*48 + chalf*16;

    auto issue = [&](int itk){
        int stage = itk & 3;
        uint32_t so = sdst + stage*(FSTG*4);
        size_t ko = (size_t)itk*8;
        cp_async16(so,        gsrc0 + ko);
        cp_async16(so + BUFB, gsrc1 + ko);
        cp_commit();
    };

    float acc[2][8][4];
    #pragma unroll
    for (int a=0;a<2;a++)
        #pragma unroll
        for (int b2=0;b2<8;b2++){ acc[a][b2][0]=0.f;acc[a][b2][1]=0.f;acc[a][b2][2]=0.f;acc[a][b2][3]=0.f; }

    issue(0); issue(1); issue(2);

    const uint32_t arow = wm + (lane & 15);
    const uint32_t aoff0 = arow*48 + ((lane>>4)&1)*16;
    const uint32_t brow = wn + (lane & 7) + ((lane & 16) ? 8 : 0);
    const uint32_t boff0 = BUFB + brow*48 + ((lane & 8) ? 16 : 0);

    #pragma unroll 1
    for (int it=0; it<64; it++){
        if (it <= 61) cp_wait<2>(); else if (it == 62) cp_wait<1>(); else cp_wait<0>();
        __syncthreads();
        if (it + 3 < 64) issue(it+3);

        uint32_t sb = sbase + (it & 3)*(FSTG*4);
        uint32_t a_h[2][4];
        ldsm_x4(a_h[0], sb + aoff0);
        ldsm_x4(a_h[1], sb + aoff0 + 16*48);
        #pragma unroll
        for (int p=0;p<4;p++){
            uint32_t bh4[4];
            ldsm_x4(bh4, sb + boff0 + p*16*48);
            #pragma unroll
            for (int mt=0;mt<2;mt++){
                mma16816(acc[mt][2*p],   a_h[mt][0],a_h[mt][1],a_h[mt][2],a_h[mt][3], bh4[0],bh4[1]);
                mma16816(acc[mt][2*p+1], a_h[mt][0],a_h[mt][1],a_h[mt][2],a_h[mt][3], bh4[2],bh4[3]);
            }
        }
    }

    #pragma unroll
    for (int mt=0;mt<2;mt++){
        int r0 = m0 + wm + mt*16 + (lane>>2);
        #pragma unroll
        for (int nt=0;nt<8;nt++){
            int col = n0 + wn + nt*8 + 2*(lane&3);
            float2 bv2 = *reinterpret_cast<const float2*>(fc_b + col);
            #pragma unroll
            for (int rr=0;rr<2;rr++){
                size_t idx = (size_t)(r0+rr*8)*DM_ + col;
                float2 res = *reinterpret_cast<const float2*>(q_in + idx);
                *reinterpret_cast<float2*>(out + idx) =
                    make_float2(acc[mt][nt][rr*2]+bv2.x+res.x, acc[mt][nt][rr*2+1]+bv2.y+res.y);
            }
        }
    }
}

// ---------------- attention: KCH=64, 2 CTAs/SM, fp16 p_tilde ----------------
#define QSTR 36
#define OF_QH 0
#define OF_QL 4608
#define OF_K0 9216                   // per buf: Kh 2304 + Kl 2304 = 4608 u32, 2 bufs
#define OF_V0 18432                  // per buf: 64*36 = 2304 u32, 2 bufs
#define ATTN_SMEM_U32 23040          // 92160 bytes -> 2 CTAs/SM

__global__ void __launch_bounds__(256,2) attn_kernel()
{
    extern __shared__ uint32_t smq[];
    const uint32_t sbase = smem_u32addr(smq);
    uint32_t* Qh = smq;
    uint32_t* Ql = smq + OF_QL;

    const int b  = blockIdx.z, h = blockIdx.y;
    const int q0 = blockIdx.x * 128;
    const int bh = b*NH_ + h;
    const int tid = threadIdx.x, lane = tid & 31, wid = tid >> 5;
    const int wrow = wid * 16;
    const size_t ho32 = (size_t)bh * LK_ * 32;

    // K/V chunk loader (cp.async, 24KB per 64-col chunk)
    auto load_kv = [&](int kc, int buf){
        uint32_t kb = sbase + (OF_K0 + buf*4608)*4;
        uint32_t vb = sbase + (OF_V0 + buf*2304)*4;
        #pragma unroll
        for (int p=0;p<2;p++){
            int id = tid + p*256;
            int row = id>>3, c = id&7;
            const uint32_t* ks = g_Khi + ho32 + (size_t)(kc+row)*32 + c*4;
            const uint32_t* ls = g_Klo + ho32 + (size_t)(kc+row)*32 + c*4;
            cp_async16(kb + row*144 + c*16, ks);
            cp_async16(kb + 2304*4 + row*144 + c*16, ls);
            const uint32_t* vs = g_Vh + ((size_t)bh*64 + row)*1024 + (kc>>1) + c*4;
            cp_async16(vb + row*144 + c*16, vs);
        }
        cp_commit();
    };

    load_kv(0, 0);

    // Q tile (pre-scaled, pre-split)
    #pragma unroll
    for (int p=0;p<4;p++){
        int item = tid + p*256;
        int row = item>>3, o = item&7;
        *reinterpret_cast<uint4*>(Qh + row*QSTR + o*4) =
            *reinterpret_cast<const uint4*>(g_Qhi + ho32 + (size_t)(q0+row)*32 + o*4);
        *reinterpret_cast<uint4*>(Ql + row*QSTR + o*4) =
            *reinterpret_cast<const uint4*>(g_Qlo + ho32 + (size_t)(q0+row)*32 + o*4);
    }

    float mrow0 = -INFINITY, mrow1 = -INFINITY;
    float lrow0 = 0.f, lrow1 = 0.f;
    float o_[8][4];
    #pragma unroll
    for (int t=0;t<8;t++){ o_[t][0]=0.f;o_[t][1]=0.f;o_[t][2]=0.f;o_[t][3]=0.f; }

    const int rbase = q0 + wrow + (lane>>2);
    const uint32_t* mbits_row0 = g_mbits + ((size_t)b*LQ_ + rbase)*64;

    const uint32_t aaddr = sbase + (wrow + (lane&15))*144 + ((lane&16)?16:0);
    const uint32_t boff  = ((lane&7) + ((lane&16)?8:0))*144 + ((lane&8)?16:0);
    const uint32_t voff  = ((lane&7) + ((lane&16)?8:0))*144 + ((lane&8)?16:0);

    int cur = 0;
    #pragma unroll 1
    for (int kc=0; kc<LK_; kc+=64){
        cp_wait<0>();
        __syncthreads();
        if (kc + 64 < LK_) load_kv(kc+64, cur^1);

        const uint32_t kb = sbase + (OF_K0 + cur*4608)*4;
        const uint32_t vb = sbase + (OF_V0 + cur*2304)*4;
        const uint32_t baddr = kb + boff;
        const uint32_t vaddr = vb + voff;

        uint32_t mw0[2], mw1[2];
        #pragma unroll
        for (int c2=0;c2<2;c2++){
            mw0[c2] = mbits_row0[(kc>>5) + c2];
            mw1[c2] = mbits_row0[8*64 + (kc>>5) + c2];
        }

        float s[8][4];
        #pragma unroll
        for (int t=0;t<8;t++){ s[t][0]=0.f;s[t][1]=0.f;s[t][2]=0.f;s[t][3]=0.f; }
        #pragma unroll
        for (int ks=0; ks<4; ks++){
            uint32_t ah[4], al[4];
            ldsm_x4(ah, aaddr + ks*32);
            ldsm_x4(al, aaddr + (OF_QL-OF_QH)*4 + ks*32);
            #pragma unroll
            for (int p=0;p<4;p++){
                uint32_t bh4[4], bl4[4];
                ldsm_x4(bh4, baddr + p*16*144 + ks*32);
                ldsm_x4(bl4, baddr + 2304*4 + p*16*144 + ks*32);
                mma16816(s[2*p],   ah[0],ah[1],ah[2],ah[3], bh4[0],bh4[1]);
                mma16816(s[2*p+1], ah[0],ah[1],ah[2],ah[3], bh4[2],bh4[3]);
                mma16816(s[2*p],   ah[0],ah[1],ah[2],ah[3], bl4[0],bl4[1]);
                mma16816(s[2*p+1], ah[0],ah[1],ah[2],ah[3], bl4[2],bl4[3]);
                mma16816(s[2*p],   al[0],al[1],al[2],al[3], bh4[0],bh4[1]);
                mma16816(s[2*p+1], al[0],al[1],al[2],al[3], bh4[2],bh4[3]);
            }
        }

        float cm0 = -INFINITY, cm1 = -INFINITY;
        #pragma unroll
        for (int nt=0;nt<8;nt++){
            uint32_t w0 = mw0[nt>>2], w1 = mw1[nt>>2];
            int bsh = ((nt&3)<<3) + ((lane&3)<<1);
            if ((w0>>bsh)&1)     s[nt][0] = -INFINITY;
            if ((w0>>(bsh+1))&1) s[nt][1] = -INFINITY;
            if ((w1>>bsh)&1)     s[nt][2] = -INFINITY;
            if ((w1>>(bsh+1))&1) s[nt][3] = -INFINITY;
            cm0 = fmaxf(cm0, fmaxf(s[nt][0], s[nt][1]));
            cm1 = fmaxf(cm1, fmaxf(s[nt][2], s[nt][3]));
        }
        cm0 = fmaxf(cm0, __shfl_xor_sync(0xffffffffu, cm0, 1));
        cm0 = fmaxf(cm0, __shfl_xor_sync(0xffffffffu, cm0, 2));
        cm1 = fmaxf(cm1, __shfl_xor_sync(0xffffffffu, cm1, 1));
        cm1 = fmaxf(cm1, __shfl_xor_sync(0xffffffffu, cm1, 2));

        float mn0 = fmaxf(mrow0, cm0), mn1 = fmaxf(mrow1, cm1);
        float corr0 = (mrow0 == -INFINITY) ? 0.f : __expf(mrow0 - mn0);
        float corr1 = (mrow1 == -INFINITY) ? 0.f : __expf(mrow1 - mn1);

        float sum0 = 0.f, sum1 = 0.f;
        #pragma unroll
        for (int nt=0;nt<8;nt++){
            s[nt][0] = __expf(s[nt][0] - mn0);
            s[nt][1] = __expf(s[nt][1] - mn0);
            s[nt][2] = __expf(s[nt][2] - mn1);
            s[nt][3] = __expf(s[nt][3] - mn1);
            sum0 += s[nt][0] + s[nt][1];
            sum1 += s[nt][2] + s[nt][3];
        }
        sum0 += __shfl_xor_sync(0xffffffffu, sum0, 1);
        sum0 += __shfl_xor_sync(0xffffffffu, sum0, 2);
        sum1 += __shfl_xor_sync(0xffffffffu, sum1, 1);
        sum1 += __shfl_xor_sync(0xffffffffu, sum1, 2);

        lrow0 = lrow0*corr0 + sum0;
        lrow1 = lrow1*corr1 + sum1;
        mrow0 = mn0; mrow1 = mn1;

        #pragma unroll
        for (int t=0;t<8;t++){
            o_[t][0]*=corr0; o_[t][1]*=corr0; o_[t][2]*=corr1; o_[t][3]*=corr1;
        }

        // write p_tilde as fp16x2
        uint32_t* pr0 = g_Pt + ((size_t)bh*LQ_ + rbase)*(LK_/2);
        uint32_t* pr1 = pr0 + 8*(size_t)(LK_/2);
        #pragma unroll
        for (int nt=0;nt<8;nt++){
            int colh = (kc + nt*8 + 2*(lane&3)) >> 1;
            __stcs(pr0 + colh, pack_h2(s[nt][0], s[nt][1]));
            __stcs(pr1 + colh, pack_h2(s[nt][2], s[nt][3]));
        }
        if ((lane & 3) == 0){
            g_mchunk[((size_t)bh*LQ_ + rbase)*32 + (kc>>6)]     = mn0;
            g_mchunk[((size_t)bh*LQ_ + rbase + 8)*32 + (kc>>6)] = mn1;
        }

        #pragma unroll
        for (int kk=0;kk<4;kk++){
            uint32_t a0 = pack_bf16(s[2*kk][0],   s[2*kk][1]);
            uint32_t a1 = pack_bf16(s[2*kk][2],   s[2*kk][3]);
            uint32_t a2 = pack_bf16(s[2*kk+1][0], s[2*kk+1][1]);
            uint32_t a3 = pack_bf16(s[2*kk+1][2], s[2*kk+1][3]);
            #pragma unroll
            for (int g=0; g<4; g++){
                uint32_t bv4[4];
                ldsm_x4(bv4, vaddr + g*16*144 + kk*32);
                mma16816(o_[2*g],   a0,a1,a2,a3, bv4[0],bv4[1]);
                mma16816(o_[2*g+1], a0,a1,a2,a3, bv4[2],bv4[3]);
            }
        }
        cur ^= 1;
    }

    float inv0 = 1.f / lrow0, inv1 = 1.f / lrow1;
    #pragma unroll
    for (int nt2=0;nt2<8;nt2++){
        int dcol = nt2*8 + 2*(lane&3);
        size_t ro = ((size_t)b*LQ_ + rbase)*512 + h*32 + (dcol>>1);
        g_Hbf[ro]         = pack_bf16(o_[nt2][0]*inv0, o_[nt2][1]*inv0);
        g_Hbf[ro + 8*512] = pack_bf16(o_[nt2][2]*inv1, o_[nt2][3]*inv1);
    }
    if ((lane & 3) == 0){
        g_rowstat[(size_t)bh*LQ_ + rbase]     = make_float2(mrow0, lrow0);
        g_rowstat[(size_t)bh*LQ_ + rbase + 8] = make_float2(mrow1, lrow1);
    }
}

// ---------------- rescale: fp16 p_tilde -> fp32 probs ----------------------
__global__ void rescale_kernel(float* __restrict__ attn)
{
    const int bh = blockIdx.y;
    const int qq = blockIdx.x;
    const size_t rowidx = (size_t)bh*LQ_ + qq;
    float2 st = g_rowstat[rowidx];
    int t = threadIdx.x;
    int chunk = t >> 3;                       // 64-col chunks
    float f = __expf(g_mchunk[rowidx*32 + chunk] - st.x) / st.y;
    const uint32_t* src = g_Pt + rowidx*(LK_/2) + t*4;
    uint32_t a0 = __ldcs(src), a1 = __ldcs(src+1), a2 = __ldcs(src+2), a3 = __ldcs(src+3);
    float2 f0 = __half22float2(*reinterpret_cast<__half2*>(&a0));
    float2 f1 = __half22float2(*reinterpret_cast<__half2*>(&a1));
    float2 f2 = __half22float2(*reinterpret_cast<__half2*>(&a2));
    float2 f3 = __half22float2(*reinterpret_cast<__half2*>(&a3));
    float4* p = reinterpret_cast<float4*>(attn + rowidx*LK_ + t*8);
    p[0] = make_float4(f0.x*f, f0.y*f, f1.x*f, f1.y*f);
    p[1] = make_float4(f2.x*f, f2.y*f, f3.x*f, f3.y*f);
}

// ---------------- launch ----------------------------------------------------
extern "C" void kernel_launch(void* const* d_in, const int* in_sizes, int n_in,
                              void* d_out, int out_size)
{
    const float* q    = (const float*)d_in[0];
    const float* k    = (const float*)d_in[1];
    const float* v    = (const float*)d_in[2];
    const int*   mask = (const int*)d_in[3];
    const float* w_qs = (const float*)d_in[4];
    const float* b_qs = (const float*)d_in[5];
    const float* w_ks = (const float*)d_in[6];
    const float* b_ks = (const float*)d_in[7];
    const float* w_vs = (const float*)d_in[8];
    const float* b_vs = (const float*)d_in[9];
    const float* fc_w = (const float*)d_in[10];
    const float* fc_b = (const float*)d_in[11];

    float* out = (float*)d_out;
    float* attn_out = out + (size_t)M_ * DM_;

    static cudaStream_t s1 = nullptr;
    static cudaEvent_t evFork = nullptr, evMask = nullptr, evAttn = nullptr, evResc = nullptr;
    if (s1 == nullptr){
        cudaStreamCreateWithFlags(&s1, cudaStreamNonBlocking);
        cudaEventCreateWithFlags(&evFork, cudaEventDisableTiming);
        cudaEventCreateWithFlags(&evMask, cudaEventDisableTiming);
        cudaEventCreateWithFlags(&evAttn, cudaEventDisableTiming);
        cudaEventCreateWithFlags(&evResc, cudaEventDisableTiming);
        cudaFuncSetAttribute(proj_kernel, cudaFuncAttributeMaxDynamicSharedMemorySize, 4*PSTG*4);
        cudaFuncSetAttribute(fc_kernel,   cudaFuncAttributeMaxDynamicSharedMemorySize, 4*FSTG*4);
        cudaFuncSetAttribute(attn_kernel, cudaFuncAttributeMaxDynamicSharedMemorySize, ATTN_SMEM_U32*4);
    }

    k_split_inputs<<<24576, 256>>>(q, k, v);
    k_conv_w<<<dim3(32,32,4), 256>>>(w_qs, w_ks, w_vs, fc_w);

    cudaEventRecord(evFork, 0);
    cudaStreamWaitEvent(s1, evFork, 0);
    k_mask_bits<<<2048, 256, 0, s1>>>(mask);
    cudaEventRecord(evMask, s1);

    proj_kernel<<<dim3(8,64,3), 256, 4*PSTG*4>>>(b_qs, b_ks, b_vs);

    cudaStreamWaitEvent(0, evMask, 0);
    attn_kernel<<<dim3(16,NH_,B_), 256, ATTN_SMEM_U32*4>>>();

    cudaEventRecord(evAttn, 0);
    cudaStreamWaitEvent(s1, evAttn, 0);
    rescale_kernel<<<dim3(LQ_, B_*NH_), 256, 0, s1>>>(attn_out);
    cudaEventRecord(evResc, s1);

    fc_kernel<<<dim3(8,64), 256, 4*FSTG*4>>>(fc_b, q, out);

    cudaStreamWaitEvent(0, evResc, 0);
}

// round 15
// speedup vs baseline: 1.2138x; 1.0943x over previous
#include <cuda_runtime.h>
#include <cuda_bf16.h>
#include <cuda_fp16.h>
#include <math.h>
#include <stdint.h>

#define B_   4
#define LQ_  2048
#define LK_  2048
#define DM_  1024
#define NH_  16
#define M_   8192

// ---------------- device scratch (allocation-free rule) --------------------
__device__ uint32_t g_Ih[3][4194304];     // split-hi of q,k,v inputs (bf16x2)
__device__ uint32_t g_Il[3][4194304];     // split-lo (mat 2 unused)
__device__ uint32_t g_Wth[4][524288];     // transposed weights hi [n][k-pair]; idx3 = fc_w
__device__ uint32_t g_Wtl[3][524288];     // transposed weights lo
__device__ uint32_t g_Qh16[4194304];      // Q fp16x2 [b,h,l,d-pair], pre-scaled 1/8
__device__ uint32_t g_Kh16[4194304];      // K fp16x2
__device__ uint32_t g_Vh [4194304];       // V TRANSPOSED fp16 [bh*64+d][l]
__device__ uint32_t g_Hbf[4194304];       // attn output bf16 [m][k-pair] for FC
__device__ uint32_t g_mbits[524288];      // mask bitwords [b][lq][lk/32]
__device__ uint32_t g_Pt[134217728];      // p_tilde staging, fp16x2 [bh*lq][lk/2]
__device__ float    g_mchunk[(size_t)B_*NH_*LQ_*32];
__device__ float2   g_rowstat[(size_t)B_*NH_*LQ_];

// ---------------- helpers --------------------------------------------------
__device__ __forceinline__ uint32_t pack_bf16(float x, float y){
    __nv_bfloat162 t = __floats2bfloat162_rn(x, y);
    return *reinterpret_cast<uint32_t*>(&t);
}
__device__ __forceinline__ uint32_t pack_h2(float x, float y){
    __half2 t = __floats2half2_rn(x, y);
    return *reinterpret_cast<uint32_t*>(&t);
}
__device__ __forceinline__ void split_u32(float x0, float x1, uint32_t& h, uint32_t& l){
    float h0 = __bfloat162float(__float2bfloat16(x0));
    float h1 = __bfloat162float(__float2bfloat16(x1));
    h = pack_bf16(h0, h1);
    l = pack_bf16(x0 - h0, x1 - h1);
}
__device__ __forceinline__ void mma16816(float* c,
    uint32_t a0, uint32_t a1, uint32_t a2, uint32_t a3, uint32_t b0, uint32_t b1){
    asm volatile("mma.sync.aligned.m16n8k16.row.col.f32.bf16.bf16.f32 "
        "{%0,%1,%2,%3}, {%4,%5,%6,%7}, {%8,%9}, {%0,%1,%2,%3};"
        : "+f"(c[0]), "+f"(c[1]), "+f"(c[2]), "+f"(c[3])
        : "r"(a0), "r"(a1), "r"(a2), "r"(a3), "r"(b0), "r"(b1));
}
__device__ __forceinline__ void mma16816h(float* c,
    uint32_t a0, uint32_t a1, uint32_t a2, uint32_t a3, uint32_t b0, uint32_t b1){
    asm volatile("mma.sync.aligned.m16n8k16.row.col.f32.f16.f16.f32 "
        "{%0,%1,%2,%3}, {%4,%5,%6,%7}, {%8,%9}, {%0,%1,%2,%3};"
        : "+f"(c[0]), "+f"(c[1]), "+f"(c[2]), "+f"(c[3])
        : "r"(a0), "r"(a1), "r"(a2), "r"(a3), "r"(b0), "r"(b1));
}
__device__ __forceinline__ void ldsm_x4(uint32_t* r, uint32_t addr){
    asm volatile("ldmatrix.sync.aligned.m8n8.x4.shared.b16 {%0,%1,%2,%3}, [%4];"
        : "=r"(r[0]), "=r"(r[1]), "=r"(r[2]), "=r"(r[3]) : "r"(addr));
}
__device__ __forceinline__ void cp_async16(uint32_t saddr, const void* gaddr){
    asm volatile("cp.async.cg.shared.global [%0], [%1], 16;" :: "r"(saddr), "l"(gaddr));
}
__device__ __forceinline__ void cp_commit(){ asm volatile("cp.async.commit_group;"); }
template<int N> __device__ __forceinline__ void cp_wait(){
    asm volatile("cp.async.wait_group %0;" :: "n"(N));
}
__device__ __forceinline__ uint32_t smem_u32addr(const void* p){
    uint32_t a;
    asm("{.reg .u64 t; cvta.to.shared.u64 t, %1; cvt.u32.u64 %0, t;}" : "=r"(a) : "l"(p));
    return a;
}

// ---------------- convert kernels ------------------------------------------
__global__ void k_split_inputs(const float* __restrict__ q,
                               const float* __restrict__ k,
                               const float* __restrict__ v){
    size_t F = (size_t)blockIdx.x*256 + threadIdx.x;
    int mat = (int)(F >> 21);
    size_t rem = F & 2097151u;
    const float* src = mat==0 ? q : mat==1 ? k : v;
    float4 a = reinterpret_cast<const float4*>(src)[rem];
    uint32_t h0,l0,h1,l1;
    split_u32(a.x, a.y, h0, l0);
    split_u32(a.z, a.w, h1, l1);
    g_Ih[mat][rem*2]   = h0; g_Ih[mat][rem*2+1] = h1;
    if (mat < 2){
        g_Il[mat][rem*2] = l0; g_Il[mat][rem*2+1] = l1;
    }
}

__global__ void k_conv_w(const float* __restrict__ wq, const float* __restrict__ wk,
                         const float* __restrict__ wv, const float* __restrict__ fcw){
    const int mat = blockIdx.z;
    const float* W = mat==0 ? wq : mat==1 ? wk : mat==2 ? wv : fcw;
    __shared__ float T[32][33];
    const int k0 = blockIdx.y*32, n0 = blockIdx.x*32;
    const int tx = threadIdx.x & 31, ty = threadIdx.x >> 5;
    #pragma unroll
    for (int i=0;i<4;i++)
        T[ty+8*i][tx] = W[(size_t)(k0+ty+8*i)*DM_ + n0 + tx];
    __syncthreads();
    const int n = threadIdx.x >> 3;
    const int kp0 = (threadIdx.x & 7)*2;
    #pragma unroll
    for (int s2=0;s2<2;s2++){
        int kp = kp0 + s2;
        float x0 = T[kp*2][n], x1 = T[kp*2+1][n];
        uint32_t h, l; split_u32(x0, x1, h, l);
        size_t o = (size_t)(n0+n)*512 + (k0>>1) + kp;
        g_Wth[mat][o] = h;
        if (mat < 3) g_Wtl[mat][o] = l;
    }
}

__global__ void k_mask_bits(const int* __restrict__ mask){
    int wrp = blockIdx.x*8 + (threadIdx.x>>5);
    int lane = threadIdx.x & 31;
    size_t base = (size_t)wrp*32;
    for (int j=0;j<32;j++){
        size_t w = base + j;
        int mv = mask[w*32 + lane];
        uint32_t bits = __ballot_sync(0xffffffffu, mv != 0);
        if (lane==0) g_mbits[w] = bits;
    }
}

// ---------------- projection GEMM ------------------------------------------
#define PSTG 6144
#define BUFB 6144

__global__ void __launch_bounds__(256,2) proj_kernel(
    const float* __restrict__ bq, const float* __restrict__ bk,
    const float* __restrict__ bv)
{
    extern __shared__ uint32_t smp[];
    const uint32_t sbase = smem_u32addr(smp);

    const int which = blockIdx.z;
    const bool vonly = (which == 2);
    const uint32_t* gAh = g_Ih[which];
    const uint32_t* gAl = g_Il[which];
    const uint32_t* gBh = g_Wth[which];
    const uint32_t* gBl = g_Wtl[which];
    const float* bias = which==0 ? bq : which==1 ? bk : bv;

    const int m0 = blockIdx.y*128, n0 = blockIdx.x*128;
    const int tid = threadIdx.x, lane = tid & 31, wid = tid >> 5;
    const int wm = (wid & 3)*32, wn = (wid >> 2)*64;

    const int crow = tid >> 1, chalf = tid & 1;
    const uint32_t* gsrc0 = gAh + (size_t)(m0+crow)*512 + chalf*4;
    const uint32_t* gsrc1 = gAl + (size_t)(m0+crow)*512 + chalf*4;
    const uint32_t* gsrc2 = gBh + (size_t)(n0+crow)*512 + chalf*4;
    const uint32_t* gsrc3 = gBl + (size_t)(n0+crow)*512 + chalf*4;
    const uint32_t sdst = sbase + crow*48 + chalf*16;

    auto issue = [&](int itk){
        int stage = itk & 3;
        uint32_t so = sdst + stage*(PSTG*4);
        size_t ko = (size_t)itk*8;
        cp_async16(so + 0*BUFB, gsrc0 + ko);
        cp_async16(so + 2*BUFB, gsrc2 + ko);
        if (!vonly){
            cp_async16(so + 1*BUFB, gsrc1 + ko);
            cp_async16(so + 3*BUFB, gsrc3 + ko);
        }
        cp_commit();
    };

    float acc[2][8][4];
    #pragma unroll
    for (int a=0;a<2;a++)
        #pragma unroll
        for (int b2=0;b2<8;b2++){ acc[a][b2][0]=0.f;acc[a][b2][1]=0.f;acc[a][b2][2]=0.f;acc[a][b2][3]=0.f; }

    issue(0); issue(1); issue(2);

    const uint32_t arow = wm + (lane & 15);
    const uint32_t aoff0 = arow*48 + ((lane>>4)&1)*16;
    const uint32_t brow = wn + (lane & 7) + ((lane & 16) ? 8 : 0);
    const uint32_t boff0 = 2*BUFB + brow*48 + ((lane & 8) ? 16 : 0);

    #pragma unroll 1
    for (int it=0; it<64; it++){
        if (it <= 61) cp_wait<2>(); else if (it == 62) cp_wait<1>(); else cp_wait<0>();
        __syncthreads();
        if (it + 3 < 64) issue(it+3);

        uint32_t sb = sbase + (it & 3)*(PSTG*4);
        uint32_t a_h[2][4], a_l[2][4];
        ldsm_x4(a_h[0], sb + aoff0);
        ldsm_x4(a_h[1], sb + aoff0 + 16*48);
        if (!vonly){
            ldsm_x4(a_l[0], sb + aoff0 + BUFB);
            ldsm_x4(a_l[1], sb + aoff0 + BUFB + 16*48);
        }
        #pragma unroll
        for (int pp=0;pp<2;pp++){
            const int p0 = 2*pp, p1 = 2*pp + 1;
            uint32_t b0h[4], b1h[4], b0l[4], b1l[4];
            ldsm_x4(b0h, sb + boff0 + p0*16*48);
            ldsm_x4(b1h, sb + boff0 + p1*16*48);
            if (!vonly){
                ldsm_x4(b0l, sb + boff0 + BUFB + p0*16*48);
                ldsm_x4(b1l, sb + boff0 + BUFB + p1*16*48);
            }
            #pragma unroll
            for (int mt=0;mt<2;mt++){
                mma16816(acc[mt][2*p0],   a_h[mt][0],a_h[mt][1],a_h[mt][2],a_h[mt][3], b0h[0],b0h[1]);
                mma16816(acc[mt][2*p0+1], a_h[mt][0],a_h[mt][1],a_h[mt][2],a_h[mt][3], b0h[2],b0h[3]);
                mma16816(acc[mt][2*p1],   a_h[mt][0],a_h[mt][1],a_h[mt][2],a_h[mt][3], b1h[0],b1h[1]);
                mma16816(acc[mt][2*p1+1], a_h[mt][0],a_h[mt][1],a_h[mt][2],a_h[mt][3], b1h[2],b1h[3]);
            }
            if (!vonly){
                #pragma unroll
                for (int mt=0;mt<2;mt++){
                    mma16816(acc[mt][2*p0],   a_h[mt][0],a_h[mt][1],a_h[mt][2],a_h[mt][3], b0l[0],b0l[1]);
                    mma16816(acc[mt][2*p0+1], a_h[mt][0],a_h[mt][1],a_h[mt][2],a_h[mt][3], b0l[2],b0l[3]);
                    mma16816(acc[mt][2*p1],   a_h[mt][0],a_h[mt][1],a_h[mt][2],a_h[mt][3], b1l[0],b1l[1]);
                    mma16816(acc[mt][2*p1+1], a_h[mt][0],a_h[mt][1],a_h[mt][2],a_h[mt][3], b1l[2],b1l[3]);
                }
                #pragma unroll
                for (int mt=0;mt<2;mt++){
                    mma16816(acc[mt][2*p0],   a_l[mt][0],a_l[mt][1],a_l[mt][2],a_l[mt][3], b0h[0],b0h[1]);
                    mma16816(acc[mt][2*p0+1], a_l[mt][0],a_l[mt][1],a_l[mt][2],a_l[mt][3], b0h[2],b0h[3]);
                    mma16816(acc[mt][2*p1],   a_l[mt][0],a_l[mt][1],a_l[mt][2],a_l[mt][3], b1h[0],b1h[1]);
                    mma16816(acc[mt][2*p1+1], a_l[mt][0],a_l[mt][1],a_l[mt][2],a_l[mt][3], b1h[2],b1h[3]);
                }
            }
        }
    }

    const float sc = (which==0) ? 0.125f : 1.0f;
    __half* vt = reinterpret_cast<__half*>(g_Vh);
    #pragma unroll
    for (int mt=0;mt<2;mt++){
        int r0 = m0 + wm + mt*16 + (lane>>2);
        #pragma unroll
        for (int nt=0;nt<8;nt++){
            int col = n0 + wn + nt*8 + 2*(lane&3);
            float2 bv2 = *reinterpret_cast<const float2*>(bias + col);
            int hh = col>>6, dd = col&63;
            #pragma unroll
            for (int rr=0;rr<2;rr++){
                int r = r0 + rr*8;
                int bb2 = r>>11, ll = r&2047;
                float x0 = (acc[mt][nt][rr*2]   + bv2.x)*sc;
                float x1 = (acc[mt][nt][rr*2+1] + bv2.y)*sc;
                if (which==2){
                    size_t vb = ((size_t)(bb2*NH_+hh)*64 + dd)*2048 + ll;
                    vt[vb]        = __float2half(x0);
                    vt[vb + 2048] = __float2half(x1);
                } else {
                    size_t o = (((size_t)(bb2*NH_+hh))*LQ_ + ll)*32 + (dd>>1);
                    uint32_t hx = pack_h2(x0, x1);
                    if (which==0) g_Qh16[o] = hx; else g_Kh16[o] = hx;
                }
            }
        }
    }
}

// ---------------- FC GEMM + bias + residual --------------------------------
#define FSTG 3072

__global__ void __launch_bounds__(256,2) fc_kernel(
    const float* __restrict__ fc_b, const float* __restrict__ q_in,
    float* __restrict__ out)
{
    extern __shared__ uint32_t smf[];
    const uint32_t sbase = smem_u32addr(smf);

    const int m0 = blockIdx.y*128, n0 = blockIdx.x*128;
    const int tid = threadIdx.x, lane = tid & 31, wid = tid >> 5;
    const int wm = (wid & 3)*32, wn = (wid >> 2)*64;

    const int crow = tid >> 1, chalf = tid & 1;
    const uint32_t* gsrc0 = g_Hbf    + (size_t)(m0+crow)*512 + chalf*4;
    const uint32_t* gsrc1 = g_Wth[3] + (size_t)(n0+crow)*512 + chalf*4;
    const uint32_t sdst = sbase + crow*48 + chalf*16;

    auto issue = [&](int itk){
        int stage = itk & 3;
        uint32_t so = sdst + stage*(FSTG*4);
        size_t ko = (size_t)itk*8;
        cp_async16(so,        gsrc0 + ko);
        cp_async16(so + BUFB, gsrc1 + ko);
        cp_commit();
    };

    float acc[2][8][4];
    #pragma unroll
    for (int a=0;a<2;a++)
        #pragma unroll
        for (int b2=0;b2<8;b2++){ acc[a][b2][0]=0.f;acc[a][b2][1]=0.f;acc[a][b2][2]=0.f;acc[a][b2][3]=0.f; }

    issue(0); issue(1); issue(2);

    const uint32_t arow = wm + (lane & 15);
    const uint32_t aoff0 = arow*48 + ((lane>>4)&1)*16;
    const uint32_t brow = wn + (lane & 7) + ((lane & 16) ? 8 : 0);
    const uint32_t boff0 = BUFB + brow*48 + ((lane & 8) ? 16 : 0);

    #pragma unroll 1
    for (int it=0; it<64; it++){
        if (it <= 61) cp_wait<2>(); else if (it == 62) cp_wait<1>(); else cp_wait<0>();
        __syncthreads();
        if (it + 3 < 64) issue(it+3);

        uint32_t sb = sbase + (it & 3)*(FSTG*4);
        uint32_t a_h[2][4];
        ldsm_x4(a_h[0], sb + aoff0);
        ldsm_x4(a_h[1], sb + aoff0 + 16*48);
        #pragma unroll
        for (int p=0;p<4;p++){
            uint32_t bh4[4];
            ldsm_x4(bh4, sb + boff0 + p*16*48);
            #pragma unroll
            for (int mt=0;mt<2;mt++){
                mma16816(acc[mt][2*p],   a_h[mt][0],a_h[mt][1],a_h[mt][2],a_h[mt][3], bh4[0],bh4[1]);
                mma16816(acc[mt][2*p+1], a_h[mt][0],a_h[mt][1],a_h[mt][2],a_h[mt][3], bh4[2],bh4[3]);
            }
        }
    }

    #pragma unroll
    for (int mt=0;mt<2;mt++){
        int r0 = m0 + wm + mt*16 + (lane>>2);
        #pragma unroll
        for (int nt=0;nt<8;nt++){
            int col = n0 + wn + nt*8 + 2*(lane&3);
            float2 bv2 = *reinterpret_cast<const float2*>(fc_b + col);
            #pragma unroll
            for (int rr=0;rr<2;rr++){
                size_t idx = (size_t)(r0+rr*8)*DM_ + col;
                float2 res = *reinterpret_cast<const float2*>(q_in + idx);
                *reinterpret_cast<float2*>(out + idx) =
                    make_float2(acc[mt][nt][rr*2]+bv2.x+res.x, acc[mt][nt][rr*2+1]+bv2.y+res.y);
            }
        }
    }
}

// ---------------- attention: fp16 single-term, KCH=64, 2 CTAs/SM -----------
#define OF_K0 4608                   // Q tile: 128x36 u32 = 4608
#define OF_V0 9216                   // K bufs: 2 x 2304 ; V bufs: 2 x 2304
#define ATTN_SMEM_U32 13824          // 55296 bytes

__global__ void __launch_bounds__(256,2) attn_kernel()
{
    extern __shared__ uint32_t smq[];
    const uint32_t sbase = smem_u32addr(smq);
    uint32_t* Qs = smq;

    const int b  = blockIdx.z, h = blockIdx.y;
    const int q0 = blockIdx.x * 128;
    const int bh = b*NH_ + h;
    const int tid = threadIdx.x, lane = tid & 31, wid = tid >> 5;
    const int wrow = wid * 16;
    const size_t ho32 = (size_t)bh * LK_ * 32;

    // K/V chunk loader (cp.async, 18KB per 64-col chunk)
    auto load_kv = [&](int kc, int buf){
        uint32_t kb = sbase + (OF_K0 + buf*2304)*4;
        uint32_t vb = sbase + (OF_V0 + buf*2304)*4;
        {
            int id = tid;                        // 256 of 512 K uint4s x2
            #pragma unroll
            for (int p=0;p<2;p++){
                int row = id>>3, c = id&7;
                cp_async16(kb + row*144 + c*16, g_Kh16 + ho32 + (size_t)(kc+row)*32 + c*4);
                cp_async16(vb + row*144 + c*16, g_Vh + ((size_t)bh*64 + row)*1024 + (kc>>1) + c*4);
                id += 256;
            }
        }
        cp_commit();
    };

    load_kv(0, 0);

    // Q tile (pre-scaled fp16)
    #pragma unroll
    for (int p=0;p<4;p++){
        int item = tid + p*256;
        int row = item>>3, o = item&7;
        *reinterpret_cast<uint4*>(Qs + row*36 + o*4) =
            *reinterpret_cast<const uint4*>(g_Qh16 + ho32 + (size_t)(q0+row)*32 + o*4);
    }

    float mrow0 = -INFINITY, mrow1 = -INFINITY;
    float lrow0 = 0.f, lrow1 = 0.f;
    float o_[8][4];
    #pragma unroll
    for (int t=0;t<8;t++){ o_[t][0]=0.f;o_[t][1]=0.f;o_[t][2]=0.f;o_[t][3]=0.f; }

    const int rbase = q0 + wrow + (lane>>2);
    const uint32_t* mbits_row0 = g_mbits + ((size_t)b*LQ_ + rbase)*64;

    const uint32_t aaddr = sbase + (wrow + (lane&15))*144 + ((lane&16)?16:0);
    const uint32_t boff  = ((lane&7) + ((lane&16)?8:0))*144 + ((lane&8)?16:0);

    int cur = 0;
    #pragma unroll 1
    for (int kc=0; kc<LK_; kc+=64){
        cp_wait<0>();
        __syncthreads();
        if (kc + 64 < LK_) load_kv(kc+64, cur^1);

        const uint32_t baddr = sbase + (OF_K0 + cur*2304)*4 + boff;
        const uint32_t vaddr = sbase + (OF_V0 + cur*2304)*4 + boff;

        uint32_t mw0[2], mw1[2];
        #pragma unroll
        for (int c2=0;c2<2;c2++){
            mw0[c2] = mbits_row0[(kc>>5) + c2];
            mw1[c2] = mbits_row0[8*64 + (kc>>5) + c2];
        }

        float s[8][4];
        #pragma unroll
        for (int t=0;t<8;t++){ s[t][0]=0.f;s[t][1]=0.f;s[t][2]=0.f;s[t][3]=0.f; }
        #pragma unroll
        for (int ks=0; ks<4; ks++){
            uint32_t ah[4];
            ldsm_x4(ah, aaddr + ks*32);
            #pragma unroll
            for (int p=0;p<4;p++){
                uint32_t bh4[4];
                ldsm_x4(bh4, baddr + p*16*144 + ks*32);
                mma16816h(s[2*p],   ah[0],ah[1],ah[2],ah[3], bh4[0],bh4[1]);
                mma16816h(s[2*p+1], ah[0],ah[1],ah[2],ah[3], bh4[2],bh4[3]);
            }
        }

        float cm0 = -INFINITY, cm1 = -INFINITY;
        #pragma unroll
        for (int nt=0;nt<8;nt++){
            uint32_t w0 = mw0[nt>>2], w1 = mw1[nt>>2];
            int bsh = ((nt&3)<<3) + ((lane&3)<<1);
            if ((w0>>bsh)&1)     s[nt][0] = -INFINITY;
            if ((w0>>(bsh+1))&1) s[nt][1] = -INFINITY;
            if ((w1>>bsh)&1)     s[nt][2] = -INFINITY;
            if ((w1>>(bsh+1))&1) s[nt][3] = -INFINITY;
            cm0 = fmaxf(cm0, fmaxf(s[nt][0], s[nt][1]));
            cm1 = fmaxf(cm1, fmaxf(s[nt][2], s[nt][3]));
        }
        cm0 = fmaxf(cm0, __shfl_xor_sync(0xffffffffu, cm0, 1));
        cm0 = fmaxf(cm0, __shfl_xor_sync(0xffffffffu, cm0, 2));
        cm1 = fmaxf(cm1, __shfl_xor_sync(0xffffffffu, cm1, 1));
        cm1 = fmaxf(cm1, __shfl_xor_sync(0xffffffffu, cm1, 2));

        float mn0 = fmaxf(mrow0, cm0), mn1 = fmaxf(mrow1, cm1);
        float corr0 = (mrow0 == -INFINITY) ? 0.f : __expf(mrow0 - mn0);
        float corr1 = (mrow1 == -INFINITY) ? 0.f : __expf(mrow1 - mn1);

        float sum0 = 0.f, sum1 = 0.f;
        #pragma unroll
        for (int nt=0;nt<8;nt++){
            s[nt][0] = __expf(s[nt][0] - mn0);
            s[nt][1] = __expf(s[nt][1] - mn0);
            s[nt][2] = __expf(s[nt][2] - mn1);
            s[nt][3] = __expf(s[nt][3] - mn1);
            sum0 += s[nt][0] + s[nt][1];
            sum1 += s[nt][2] + s[nt][3];
        }
        sum0 += __shfl_xor_sync(0xffffffffu, sum0, 1);
        sum0 += __shfl_xor_sync(0xffffffffu, sum0, 2);
        sum1 += __shfl_xor_sync(0xffffffffu, sum1, 1);
        sum1 += __shfl_xor_sync(0xffffffffu, sum1, 2);

        lrow0 = lrow0*corr0 + sum0;
        lrow1 = lrow1*corr1 + sum1;
        mrow0 = mn0; mrow1 = mn1;

        #pragma unroll
        for (int t=0;t<8;t++){
            o_[t][0]*=corr0; o_[t][1]*=corr0; o_[t][2]*=corr1; o_[t][3]*=corr1;
        }

        // fp16 packs: used for BOTH the p_tilde store and the PV A-operand
        uint32_t ph[8][2];
        #pragma unroll
        for (int nt=0;nt<8;nt++){
            ph[nt][0] = pack_h2(s[nt][0], s[nt][1]);
            ph[nt][1] = pack_h2(s[nt][2], s[nt][3]);
        }

        uint32_t* pr0 = g_Pt + ((size_t)bh*LQ_ + rbase)*(LK_/2);
        uint32_t* pr1 = pr0 + 8*(size_t)(LK_/2);
        #pragma unroll
        for (int nt=0;nt<8;nt++){
            int colh = (kc + nt*8 + 2*(lane&3)) >> 1;
            __stcs(pr0 + colh, ph[nt][0]);
            __stcs(pr1 + colh, ph[nt][1]);
        }
        if ((lane & 3) == 0){
            g_mchunk[((size_t)bh*LQ_ + rbase)*32 + (kc>>6)]     = mn0;
            g_mchunk[((size_t)bh*LQ_ + rbase + 8)*32 + (kc>>6)] = mn1;
        }

        #pragma unroll
        for (int kk=0;kk<4;kk++){
            uint32_t a0 = ph[2*kk][0],   a1 = ph[2*kk][1];
            uint32_t a2 = ph[2*kk+1][0], a3 = ph[2*kk+1][1];
            #pragma unroll
            for (int g=0; g<4; g++){
                uint32_t bv4[4];
                ldsm_x4(bv4, vaddr + g*16*144 + kk*32);
                mma16816h(o_[2*g],   a0,a1,a2,a3, bv4[0],bv4[1]);
                mma16816h(o_[2*g+1], a0,a1,a2,a3, bv4[2],bv4[3]);
            }
        }
        cur ^= 1;
    }

    float inv0 = 1.f / lrow0, inv1 = 1.f / lrow1;
    #pragma unroll
    for (int nt2=0;nt2<8;nt2++){
        int dcol = nt2*8 + 2*(lane&3);
        size_t ro = ((size_t)b*LQ_ + rbase)*512 + h*32 + (dcol>>1);
        g_Hbf[ro]         = pack_bf16(o_[nt2][0]*inv0, o_[nt2][1]*inv0);
        g_Hbf[ro + 8*512] = pack_bf16(o_[nt2][2]*inv1, o_[nt2][3]*inv1);
    }
    if ((lane & 3) == 0){
        g_rowstat[(size_t)bh*LQ_ + rbase]     = make_float2(mrow0, lrow0);
        g_rowstat[(size_t)bh*LQ_ + rbase + 8] = make_float2(mrow1, lrow1);
    }
}

// ---------------- rescale: fp16 p_tilde -> fp32 probs ----------------------
__global__ void rescale_kernel(float* __restrict__ attn)
{
    const int bh = blockIdx.y;
    const int qq = blockIdx.x;
    const size_t rowidx = (size_t)bh*LQ_ + qq;
    float2 st = g_rowstat[rowidx];
    int t = threadIdx.x;
    int chunk = t >> 3;                       // 64-col chunks
    float f = __expf(g_mchunk[rowidx*32 + chunk] - st.x) / st.y;
    const uint32_t* src = g_Pt + rowidx*(LK_/2) + t*4;
    uint32_t a0 = __ldcs(src), a1 = __ldcs(src+1), a2 = __ldcs(src+2), a3 = __ldcs(src+3);
    float2 f0 = __half22float2(*reinterpret_cast<__half2*>(&a0));
    float2 f1 = __half22float2(*reinterpret_cast<__half2*>(&a1));
    float2 f2 = __half22float2(*reinterpret_cast<__half2*>(&a2));
    float2 f3 = __half22float2(*reinterpret_cast<__half2*>(&a3));
    float4* p = reinterpret_cast<float4*>(attn + rowidx*LK_ + t*8);
    p[0] = make_float4(f0.x*f, f0.y*f, f1.x*f, f1.y*f);
    p[1] = make_float4(f2.x*f, f2.y*f, f3.x*f, f3.y*f);
}

// ---------------- launch ----------------------------------------------------
extern "C" void kernel_launch(void* const* d_in, const int* in_sizes, int n_in,
                              void* d_out, int out_size)
{
    const float* q    = (const float*)d_in[0];
    const float* k    = (const float*)d_in[1];
    const float* v    = (const float*)d_in[2];
    const int*   mask = (const int*)d_in[3];
    const float* w_qs = (const float*)d_in[4];
    const float* b_qs = (const float*)d_in[5];
    const float* w_ks = (const float*)d_in[6];
    const float* b_ks = (const float*)d_in[7];
    const float* w_vs = (const float*)d_in[8];
    const float* b_vs = (const float*)d_in[9];
    const float* fc_w = (const float*)d_in[10];
    const float* fc_b = (const float*)d_in[11];

    float* out = (float*)d_out;
    float* attn_out = out + (size_t)M_ * DM_;

    static cudaStream_t s1 = nullptr;
    static cudaEvent_t evFork = nullptr, evMask = nullptr, evAttn = nullptr, evResc = nullptr;
    if (s1 == nullptr){
        cudaStreamCreateWithFlags(&s1, cudaStreamNonBlocking);
        cudaEventCreateWithFlags(&evFork, cudaEventDisableTiming);
        cudaEventCreateWithFlags(&evMask, cudaEventDisableTiming);
        cudaEventCreateWithFlags(&evAttn, cudaEventDisableTiming);
        cudaEventCreateWithFlags(&evResc, cudaEventDisableTiming);
        cudaFuncSetAttribute(proj_kernel, cudaFuncAttributeMaxDynamicSharedMemorySize, 4*PSTG*4);
        cudaFuncSetAttribute(fc_kernel,   cudaFuncAttributeMaxDynamicSharedMemorySize, 4*FSTG*4);
        cudaFuncSetAttribute(attn_kernel, cudaFuncAttributeMaxDynamicSharedMemorySize, ATTN_SMEM_U32*4);
    }

    k_split_inputs<<<24576, 256>>>(q, k, v);
    k_conv_w<<<dim3(32,32,4), 256>>>(w_qs, w_ks, w_vs, fc_w);

    cudaEventRecord(evFork, 0);
    cudaStreamWaitEvent(s1, evFork, 0);
    k_mask_bits<<<2048, 256, 0, s1>>>(mask);
    cudaEventRecord(evMask, s1);

    proj_kernel<<<dim3(8,64,3), 256, 4*PSTG*4>>>(b_qs, b_ks, b_vs);

    cudaStreamWaitEvent(0, evMask, 0);
    attn_kernel<<<dim3(16,NH_,B_), 256, ATTN_SMEM_U32*4>>>();

    cudaEventRecord(evAttn, 0);
    cudaStreamWaitEvent(s1, evAttn, 0);
    rescale_kernel<<<dim3(LQ_, B_*NH_), 256, 0, s1>>>(attn_out);
    cudaEventRecord(evResc, s1);

    fc_kernel<<<dim3(8,64), 256, 4*FSTG*4>>>(fc_b, q, out);

    cudaStreamWaitEvent(0, evResc, 0);
}

// round 16
// speedup vs baseline: 1.3098x; 1.0790x over previous
#include <cuda_runtime.h>
#include <cuda_bf16.h>
#include <cuda_fp16.h>
#include <math.h>
#include <stdint.h>

#define B_   4
#define LQ_  2048
#define LK_  2048
#define DM_  1024
#define NH_  16
#define M_   8192

// ---------------- device scratch (allocation-free rule) --------------------
__device__ uint32_t g_Ih[3][4194304];     // fp16-hi of q,k,v inputs (fp16x2)
__device__ uint32_t g_Il[2][4194304];     // fp16-lo (q,k only)
__device__ uint32_t g_Wt [4][524288];     // transposed weights fp16 [n][k-pair]; idx3 = fc_w
__device__ uint32_t g_Qh16[4194304];      // Q fp16x2 [b,h,l,d-pair], pre-scaled 1/8
__device__ uint32_t g_Kh16[4194304];      // K fp16x2
__device__ uint32_t g_Vh [4194304];       // V TRANSPOSED fp16 [bh*64+d][l]
__device__ uint32_t g_Hbf[4194304];       // attn output fp16 [m][k-pair] for FC
__device__ uint32_t g_mbits[524288];      // mask bitwords [b][lq][lk/32]
__device__ uint32_t g_Pt[134217728];      // p_tilde staging, fp16x2 [bh*lq][lk/2]
__device__ float    g_mchunk[(size_t)B_*NH_*LQ_*32];
__device__ float2   g_rowstat[(size_t)B_*NH_*LQ_];

// ---------------- helpers --------------------------------------------------
__device__ __forceinline__ uint32_t pack_h2(float x, float y){
    __half2 t = __floats2half2_rn(x, y);
    return *reinterpret_cast<uint32_t*>(&t);
}
__device__ __forceinline__ void split_h(float x0, float x1, uint32_t& h, uint32_t& l){
    float h0 = __half2float(__float2half_rn(x0));
    float h1 = __half2float(__float2half_rn(x1));
    h = pack_h2(h0, h1);
    l = pack_h2(x0 - h0, x1 - h1);
}
__device__ __forceinline__ void mma16816h(float* c,
    uint32_t a0, uint32_t a1, uint32_t a2, uint32_t a3, uint32_t b0, uint32_t b1){
    asm volatile("mma.sync.aligned.m16n8k16.row.col.f32.f16.f16.f32 "
        "{%0,%1,%2,%3}, {%4,%5,%6,%7}, {%8,%9}, {%0,%1,%2,%3};"
        : "+f"(c[0]), "+f"(c[1]), "+f"(c[2]), "+f"(c[3])
        : "r"(a0), "r"(a1), "r"(a2), "r"(a3), "r"(b0), "r"(b1));
}
__device__ __forceinline__ void ldsm_x4(uint32_t* r, uint32_t addr){
    asm volatile("ldmatrix.sync.aligned.m8n8.x4.shared.b16 {%0,%1,%2,%3}, [%4];"
        : "=r"(r[0]), "=r"(r[1]), "=r"(r[2]), "=r"(r[3]) : "r"(addr));
}
__device__ __forceinline__ void cp_async16(uint32_t saddr, const void* gaddr){
    asm volatile("cp.async.cg.shared.global [%0], [%1], 16;" :: "r"(saddr), "l"(gaddr));
}
__device__ __forceinline__ void cp_commit(){ asm volatile("cp.async.commit_group;"); }
template<int N> __device__ __forceinline__ void cp_wait(){
    asm volatile("cp.async.wait_group %0;" :: "n"(N));
}
__device__ __forceinline__ uint32_t smem_u32addr(const void* p){
    uint32_t a;
    asm("{.reg .u64 t; cvta.to.shared.u64 t, %1; cvt.u32.u64 %0, t;}" : "=r"(a) : "l"(p));
    return a;
}

// ---------------- convert kernels ------------------------------------------
__global__ void k_split_inputs(const float* __restrict__ q,
                               const float* __restrict__ k,
                               const float* __restrict__ v){
    size_t F = (size_t)blockIdx.x*256 + threadIdx.x;
    int mat = (int)(F >> 21);
    size_t rem = F & 2097151u;
    const float* src = mat==0 ? q : mat==1 ? k : v;
    float4 a = reinterpret_cast<const float4*>(src)[rem];
    uint32_t h0,l0,h1,l1;
    split_h(a.x, a.y, h0, l0);
    split_h(a.z, a.w, h1, l1);
    g_Ih[mat][rem*2]   = h0; g_Ih[mat][rem*2+1] = h1;
    if (mat < 2){
        g_Il[mat][rem*2] = l0; g_Il[mat][rem*2+1] = l1;
    }
}

__global__ void k_conv_w(const float* __restrict__ wq, const float* __restrict__ wk,
                         const float* __restrict__ wv, const float* __restrict__ fcw){
    const int mat = blockIdx.z;
    const float* W = mat==0 ? wq : mat==1 ? wk : mat==2 ? wv : fcw;
    __shared__ float T[32][33];
    const int k0 = blockIdx.y*32, n0 = blockIdx.x*32;
    const int tx = threadIdx.x & 31, ty = threadIdx.x >> 5;
    #pragma unroll
    for (int i=0;i<4;i++)
        T[ty+8*i][tx] = W[(size_t)(k0+ty+8*i)*DM_ + n0 + tx];
    __syncthreads();
    const int n = threadIdx.x >> 3;
    const int kp0 = (threadIdx.x & 7)*2;
    #pragma unroll
    for (int s2=0;s2<2;s2++){
        int kp = kp0 + s2;
        size_t o = (size_t)(n0+n)*512 + (k0>>1) + kp;
        g_Wt[mat][o] = pack_h2(T[kp*2][n], T[kp*2+1][n]);
    }
}

__global__ void k_mask_bits(const int* __restrict__ mask){
    int wrp = blockIdx.x*8 + (threadIdx.x>>5);
    int lane = threadIdx.x & 31;
    size_t base = (size_t)wrp*32;
    for (int j=0;j<32;j++){
        size_t w = base + j;
        int mv = mask[w*32 + lane];
        uint32_t bits = __ballot_sync(0xffffffffu, mv != 0);
        if (lane==0) g_mbits[w] = bits;
    }
}

// ---------------- projection GEMM (fp16: Q/K 2-term, V 1-term) -------------
#define PSTG 6144            // u32 per stage (up to 4 buffers x 1536; 3 used)
#define BUFB 6144            // bytes per buffer

__global__ void __launch_bounds__(256,2) proj_kernel(
    const float* __restrict__ bq, const float* __restrict__ bk,
    const float* __restrict__ bv)
{
    extern __shared__ uint32_t smp[];
    const uint32_t sbase = smem_u32addr(smp);

    const int which = blockIdx.z;
    const bool vonly = (which == 2);
    const uint32_t* gAh = g_Ih[which];
    const uint32_t* gAl = vonly ? g_Ih[which] : g_Il[which];
    const uint32_t* gB  = g_Wt[which];
    const float* bias = which==0 ? bq : which==1 ? bk : bv;

    const int m0 = blockIdx.y*128, n0 = blockIdx.x*128;
    const int tid = threadIdx.x, lane = tid & 31, wid = tid >> 5;
    const int wm = (wid & 3)*32, wn = (wid >> 2)*64;

    const int crow = tid >> 1, chalf = tid & 1;
    const uint32_t* gsrc0 = gAh + (size_t)(m0+crow)*512 + chalf*4;
    const uint32_t* gsrc1 = gAl + (size_t)(m0+crow)*512 + chalf*4;
    const uint32_t* gsrc2 = gB  + (size_t)(n0+crow)*512 + chalf*4;
    const uint32_t sdst = sbase + crow*48 + chalf*16;

    auto issue = [&](int itk){
        int stage = itk & 3;
        uint32_t so = sdst + stage*(PSTG*4);
        size_t ko = (size_t)itk*8;
        cp_async16(so + 0*BUFB, gsrc0 + ko);
        cp_async16(so + 2*BUFB, gsrc2 + ko);
        if (!vonly) cp_async16(so + 1*BUFB, gsrc1 + ko);
        cp_commit();
    };

    float acc[2][8][4];
    #pragma unroll
    for (int a=0;a<2;a++)
        #pragma unroll
        for (int b2=0;b2<8;b2++){ acc[a][b2][0]=0.f;acc[a][b2][1]=0.f;acc[a][b2][2]=0.f;acc[a][b2][3]=0.f; }

    issue(0); issue(1); issue(2);

    const uint32_t arow = wm + (lane & 15);
    const uint32_t aoff0 = arow*48 + ((lane>>4)&1)*16;
    const uint32_t brow = wn + (lane & 7) + ((lane & 16) ? 8 : 0);
    const uint32_t boff0 = 2*BUFB + brow*48 + ((lane & 8) ? 16 : 0);

    #pragma unroll 1
    for (int it=0; it<64; it++){
        if (it <= 61) cp_wait<2>(); else if (it == 62) cp_wait<1>(); else cp_wait<0>();
        __syncthreads();
        if (it + 3 < 64) issue(it+3);

        uint32_t sb = sbase + (it & 3)*(PSTG*4);
        uint32_t a_h[2][4], a_l[2][4];
        ldsm_x4(a_h[0], sb + aoff0);
        ldsm_x4(a_h[1], sb + aoff0 + 16*48);
        if (!vonly){
            ldsm_x4(a_l[0], sb + aoff0 + BUFB);
            ldsm_x4(a_l[1], sb + aoff0 + BUFB + 16*48);
        }
        #pragma unroll
        for (int pp=0;pp<2;pp++){
            const int p0 = 2*pp, p1 = 2*pp + 1;
            uint32_t b0h[4], b1h[4];
            ldsm_x4(b0h, sb + boff0 + p0*16*48);
            ldsm_x4(b1h, sb + boff0 + p1*16*48);
            // term A_hi — 8 independent accumulators
            #pragma unroll
            for (int mt=0;mt<2;mt++){
                mma16816h(acc[mt][2*p0],   a_h[mt][0],a_h[mt][1],a_h[mt][2],a_h[mt][3], b0h[0],b0h[1]);
                mma16816h(acc[mt][2*p0+1], a_h[mt][0],a_h[mt][1],a_h[mt][2],a_h[mt][3], b0h[2],b0h[3]);
                mma16816h(acc[mt][2*p1],   a_h[mt][0],a_h[mt][1],a_h[mt][2],a_h[mt][3], b1h[0],b1h[1]);
                mma16816h(acc[mt][2*p1+1], a_h[mt][0],a_h[mt][1],a_h[mt][2],a_h[mt][3], b1h[2],b1h[3]);
            }
            if (!vonly){
                // term A_lo
                #pragma unroll
                for (int mt=0;mt<2;mt++){
                    mma16816h(acc[mt][2*p0],   a_l[mt][0],a_l[mt][1],a_l[mt][2],a_l[mt][3], b0h[0],b0h[1]);
                    mma16816h(acc[mt][2*p0+1], a_l[mt][0],a_l[mt][1],a_l[mt][2],a_l[mt][3], b0h[2],b0h[3]);
                    mma16816h(acc[mt][2*p1],   a_l[mt][0],a_l[mt][1],a_l[mt][2],a_l[mt][3], b1h[0],b1h[1]);
                    mma16816h(acc[mt][2*p1+1], a_l[mt][0],a_l[mt][1],a_l[mt][2],a_l[mt][3], b1h[2],b1h[3]);
                }
            }
        }
    }

    const float sc = (which==0) ? 0.125f : 1.0f;
    __half* vt = reinterpret_cast<__half*>(g_Vh);
    #pragma unroll
    for (int mt=0;mt<2;mt++){
        int r0 = m0 + wm + mt*16 + (lane>>2);
        #pragma unroll
        for (int nt=0;nt<8;nt++){
            int col = n0 + wn + nt*8 + 2*(lane&3);
            float2 bv2 = *reinterpret_cast<const float2*>(bias + col);
            int hh = col>>6, dd = col&63;
            #pragma unroll
            for (int rr=0;rr<2;rr++){
                int r = r0 + rr*8;
                int bb2 = r>>11, ll = r&2047;
                float x0 = (acc[mt][nt][rr*2]   + bv2.x)*sc;
                float x1 = (acc[mt][nt][rr*2+1] + bv2.y)*sc;
                if (which==2){
                    size_t vb = ((size_t)(bb2*NH_+hh)*64 + dd)*2048 + ll;
                    vt[vb]        = __float2half(x0);
                    vt[vb + 2048] = __float2half(x1);
                } else {
                    size_t o = (((size_t)(bb2*NH_+hh))*LQ_ + ll)*32 + (dd>>1);
                    uint32_t hx = pack_h2(x0, x1);
                    if (which==0) g_Qh16[o] = hx; else g_Kh16[o] = hx;
                }
            }
        }
    }
}

// ---------------- FC GEMM (fp16 x fp16) + bias + residual ------------------
#define FSTG 3072

__global__ void __launch_bounds__(256,2) fc_kernel(
    const float* __restrict__ fc_b, const float* __restrict__ q_in,
    float* __restrict__ out)
{
    extern __shared__ uint32_t smf[];
    const uint32_t sbase = smem_u32addr(smf);

    const int m0 = blockIdx.y*128, n0 = blockIdx.x*128;
    const int tid = threadIdx.x, lane = tid & 31, wid = tid >> 5;
    const int wm = (wid & 3)*32, wn = (wid >> 2)*64;

    const int crow = tid >> 1, chalf = tid & 1;
    const uint32_t* gsrc0 = g_Hbf   + (size_t)(m0+crow)*512 + chalf*4;
    const uint32_t* gsrc1 = g_Wt[3] + (size_t)(n0+crow)*512 + chalf*4;
    const uint32_t sdst = sbase + crow*48 + chalf*16;

    auto issue = [&](int itk){
        int stage = itk & 3;
        uint32_t so = sdst + stage*(FSTG*4);
        size_t ko = (size_t)itk*8;
        cp_async16(so,        gsrc0 + ko);
        cp_async16(so + BUFB, gsrc1 + ko);
        cp_commit();
    };

    float acc[2][8][4];
    #pragma unroll
    for (int a=0;a<2;a++)
        #pragma unroll
        for (int b2=0;b2<8;b2++){ acc[a][b2][0]=0.f;acc[a][b2][1]=0.f;acc[a][b2][2]=0.f;acc[a][b2][3]=0.f; }

    issue(0); issue(1); issue(2);

    const uint32_t arow = wm + (lane & 15);
    const uint32_t aoff0 = arow*48 + ((lane>>4)&1)*16;
    const uint32_t brow = wn + (lane & 7) + ((lane & 16) ? 8 : 0);
    const uint32_t boff0 = BUFB + brow*48 + ((lane & 8) ? 16 : 0);

    #pragma unroll 1
    for (int it=0; it<64; it++){
        if (it <= 61) cp_wait<2>(); else if (it == 62) cp_wait<1>(); else cp_wait<0>();
        __syncthreads();
        if (it + 3 < 64) issue(it+3);

        uint32_t sb = sbase + (it & 3)*(FSTG*4);
        uint32_t a_h[2][4];
        ldsm_x4(a_h[0], sb + aoff0);
        ldsm_x4(a_h[1], sb + aoff0 + 16*48);
        #pragma unroll
        for (int p=0;p<4;p++){
            uint32_t bh4[4];
            ldsm_x4(bh4, sb + boff0 + p*16*48);
            #pragma unroll
            for (int mt=0;mt<2;mt++){
                mma16816h(acc[mt][2*p],   a_h[mt][0],a_h[mt][1],a_h[mt][2],a_h[mt][3], bh4[0],bh4[1]);
                mma16816h(acc[mt][2*p+1], a_h[mt][0],a_h[mt][1],a_h[mt][2],a_h[mt][3], bh4[2],bh4[3]);
            }
        }
    }

    #pragma unroll
    for (int mt=0;mt<2;mt++){
        int r0 = m0 + wm + mt*16 + (lane>>2);
        #pragma unroll
        for (int nt=0;nt<8;nt++){
            int col = n0 + wn + nt*8 + 2*(lane&3);
            float2 bv2 = *reinterpret_cast<const float2*>(fc_b + col);
            #pragma unroll
            for (int rr=0;rr<2;rr++){
                size_t idx = (size_t)(r0+rr*8)*DM_ + col;
                float2 res = *reinterpret_cast<const float2*>(q_in + idx);
                *reinterpret_cast<float2*>(out + idx) =
                    make_float2(acc[mt][nt][rr*2]+bv2.x+res.x, acc[mt][nt][rr*2+1]+bv2.y+res.y);
            }
        }
    }
}

// ---------------- attention: fp16 single-term, KCH=64, 2 CTAs/SM -----------
#define OF_K0 4608                   // Q tile: 128x36 u32 = 4608
#define OF_V0 9216                   // K bufs: 2 x 2304 ; V bufs: 2 x 2304
#define ATTN_SMEM_U32 13824          // 55296 bytes

__global__ void __launch_bounds__(256,2) attn_kernel()
{
    extern __shared__ uint32_t smq[];
    const uint32_t sbase = smem_u32addr(smq);
    uint32_t* Qs = smq;

    const int b  = blockIdx.z, h = blockIdx.y;
    const int q0 = blockIdx.x * 128;
    const int bh = b*NH_ + h;
    const int tid = threadIdx.x, lane = tid & 31, wid = tid >> 5;
    const int wrow = wid * 16;
    const size_t ho32 = (size_t)bh * LK_ * 32;

    auto load_kv = [&](int kc, int buf){
        uint32_t kb = sbase + (OF_K0 + buf*2304)*4;
        uint32_t vb = sbase + (OF_V0 + buf*2304)*4;
        {
            int id = tid;
            #pragma unroll
            for (int p=0;p<2;p++){
                int row = id>>3, c = id&7;
                cp_async16(kb + row*144 + c*16, g_Kh16 + ho32 + (size_t)(kc+row)*32 + c*4);
                cp_async16(vb + row*144 + c*16, g_Vh + ((size_t)bh*64 + row)*1024 + (kc>>1) + c*4);
                id += 256;
            }
        }
        cp_commit();
    };

    load_kv(0, 0);

    #pragma unroll
    for (int p=0;p<4;p++){
        int item = tid + p*256;
        int row = item>>3, o = item&7;
        *reinterpret_cast<uint4*>(Qs + row*36 + o*4) =
            *reinterpret_cast<const uint4*>(g_Qh16 + ho32 + (size_t)(q0+row)*32 + o*4);
    }

    float mrow0 = -INFINITY, mrow1 = -INFINITY;
    float lrow0 = 0.f, lrow1 = 0.f;
    float o_[8][4];
    #pragma unroll
    for (int t=0;t<8;t++){ o_[t][0]=0.f;o_[t][1]=0.f;o_[t][2]=0.f;o_[t][3]=0.f; }

    const int rbase = q0 + wrow + (lane>>2);
    const uint32_t* mbits_row0 = g_mbits + ((size_t)b*LQ_ + rbase)*64;

    const uint32_t aaddr = sbase + (wrow + (lane&15))*144 + ((lane&16)?16:0);
    const uint32_t boff  = ((lane&7) + ((lane&16)?8:0))*144 + ((lane&8)?16:0);

    int cur = 0;
    #pragma unroll 1
    for (int kc=0; kc<LK_; kc+=64){
        cp_wait<0>();
        __syncthreads();
        if (kc + 64 < LK_) load_kv(kc+64, cur^1);

        const uint32_t baddr = sbase + (OF_K0 + cur*2304)*4 + boff;
        const uint32_t vaddr = sbase + (OF_V0 + cur*2304)*4 + boff;

        uint32_t mw0[2], mw1[2];
        #pragma unroll
        for (int c2=0;c2<2;c2++){
            mw0[c2] = mbits_row0[(kc>>5) + c2];
            mw1[c2] = mbits_row0[8*64 + (kc>>5) + c2];
        }

        float s[8][4];
        #pragma unroll
        for (int t=0;t<8;t++){ s[t][0]=0.f;s[t][1]=0.f;s[t][2]=0.f;s[t][3]=0.f; }
        #pragma unroll
        for (int ks=0; ks<4; ks++){
            uint32_t ah[4];
            ldsm_x4(ah, aaddr + ks*32);
            #pragma unroll
            for (int p=0;p<4;p++){
                uint32_t bh4[4];
                ldsm_x4(bh4, baddr + p*16*144 + ks*32);
                mma16816h(s[2*p],   ah[0],ah[1],ah[2],ah[3], bh4[0],bh4[1]);
                mma16816h(s[2*p+1], ah[0],ah[1],ah[2],ah[3], bh4[2],bh4[3]);
            }
        }

        float cm0 = -INFINITY, cm1 = -INFINITY;
        #pragma unroll
        for (int nt=0;nt<8;nt++){
            uint32_t w0 = mw0[nt>>2], w1 = mw1[nt>>2];
            int bsh = ((nt&3)<<3) + ((lane&3)<<1);
            if ((w0>>bsh)&1)     s[nt][0] = -INFINITY;
            if ((w0>>(bsh+1))&1) s[nt][1] = -INFINITY;
            if ((w1>>bsh)&1)     s[nt][2] = -INFINITY;
            if ((w1>>(bsh+1))&1) s[nt][3] = -INFINITY;
            cm0 = fmaxf(cm0, fmaxf(s[nt][0], s[nt][1]));
            cm1 = fmaxf(cm1, fmaxf(s[nt][2], s[nt][3]));
        }
        cm0 = fmaxf(cm0, __shfl_xor_sync(0xffffffffu, cm0, 1));
        cm0 = fmaxf(cm0, __shfl_xor_sync(0xffffffffu, cm0, 2));
        cm1 = fmaxf(cm1, __shfl_xor_sync(0xffffffffu, cm1, 1));
        cm1 = fmaxf(cm1, __shfl_xor_sync(0xffffffffu, cm1, 2));

        float mn0 = fmaxf(mrow0, cm0), mn1 = fmaxf(mrow1, cm1);
        float corr0 = (mrow0 == -INFINITY) ? 0.f : __expf(mrow0 - mn0);
        float corr1 = (mrow1 == -INFINITY) ? 0.f : __expf(mrow1 - mn1);

        float sum0 = 0.f, sum1 = 0.f;
        #pragma unroll
        for (int nt=0;nt<8;nt++){
            s[nt][0] = __expf(s[nt][0] - mn0);
            s[nt][1] = __expf(s[nt][1] - mn0);
            s[nt][2] = __expf(s[nt][2] - mn1);
            s[nt][3] = __expf(s[nt][3] - mn1);
            sum0 += s[nt][0] + s[nt][1];
            sum1 += s[nt][2] + s[nt][3];
        }
        sum0 += __shfl_xor_sync(0xffffffffu, sum0, 1);
        sum0 += __shfl_xor_sync(0xffffffffu, sum0, 2);
        sum1 += __shfl_xor_sync(0xffffffffu, sum1, 1);
        sum1 += __shfl_xor_sync(0xffffffffu, sum1, 2);

        lrow0 = lrow0*corr0 + sum0;
        lrow1 = lrow1*corr1 + sum1;
        mrow0 = mn0; mrow1 = mn1;

        #pragma unroll
        for (int t=0;t<8;t++){
            o_[t][0]*=corr0; o_[t][1]*=corr0; o_[t][2]*=corr1; o_[t][3]*=corr1;
        }

        uint32_t ph[8][2];
        #pragma unroll
        for (int nt=0;nt<8;nt++){
            ph[nt][0] = pack_h2(s[nt][0], s[nt][1]);
            ph[nt][1] = pack_h2(s[nt][2], s[nt][3]);
        }

        uint32_t* pr0 = g_Pt + ((size_t)bh*LQ_ + rbase)*(LK_/2);
        uint32_t* pr1 = pr0 + 8*(size_t)(LK_/2);
        #pragma unroll
        for (int nt=0;nt<8;nt++){
            int colh = (kc + nt*8 + 2*(lane&3)) >> 1;
            __stcs(pr0 + colh, ph[nt][0]);
            __stcs(pr1 + colh, ph[nt][1]);
        }
        if ((lane & 3) == 0){
            g_mchunk[((size_t)bh*LQ_ + rbase)*32 + (kc>>6)]     = mn0;
            g_mchunk[((size_t)bh*LQ_ + rbase + 8)*32 + (kc>>6)] = mn1;
        }

        #pragma unroll
        for (int kk=0;kk<4;kk++){
            uint32_t a0 = ph[2*kk][0],   a1 = ph[2*kk][1];
            uint32_t a2 = ph[2*kk+1][0], a3 = ph[2*kk+1][1];
            #pragma unroll
            for (int g=0; g<4; g++){
                uint32_t bv4[4];
                ldsm_x4(bv4, vaddr + g*16*144 + kk*32);
                mma16816h(o_[2*g],   a0,a1,a2,a3, bv4[0],bv4[1]);
                mma16816h(o_[2*g+1], a0,a1,a2,a3, bv4[2],bv4[3]);
            }
        }
        cur ^= 1;
    }

    float inv0 = 1.f / lrow0, inv1 = 1.f / lrow1;
    #pragma unroll
    for (int nt2=0;nt2<8;nt2++){
        int dcol = nt2*8 + 2*(lane&3);
        size_t ro = ((size_t)b*LQ_ + rbase)*512 + h*32 + (dcol>>1);
        g_Hbf[ro]         = pack_h2(o_[nt2][0]*inv0, o_[nt2][1]*inv0);
        g_Hbf[ro + 8*512] = pack_h2(o_[nt2][2]*inv1, o_[nt2][3]*inv1);
    }
    if ((lane & 3) == 0){
        g_rowstat[(size_t)bh*LQ_ + rbase]     = make_float2(mrow0, lrow0);
        g_rowstat[(size_t)bh*LQ_ + rbase + 8] = make_float2(mrow1, lrow1);
    }
}

// ---------------- rescale: fp16 p_tilde -> fp32 probs ----------------------
__global__ void rescale_kernel(float* __restrict__ attn)
{
    const int bh = blockIdx.y;
    const int qq = blockIdx.x;
    const size_t rowidx = (size_t)bh*LQ_ + qq;
    float2 st = g_rowstat[rowidx];
    int t = threadIdx.x;
    int chunk = t >> 3;
    float f = __expf(g_mchunk[rowidx*32 + chunk] - st.x) / st.y;
    const uint32_t* src = g_Pt + rowidx*(LK_/2) + t*4;
    uint32_t a0 = __ldcs(src), a1 = __ldcs(src+1), a2 = __ldcs(src+2), a3 = __ldcs(src+3);
    float2 f0 = __half22float2(*reinterpret_cast<__half2*>(&a0));
    float2 f1 = __half22float2(*reinterpret_cast<__half2*>(&a1));
    float2 f2 = __half22float2(*reinterpret_cast<__half2*>(&a2));
    float2 f3 = __half22float2(*reinterpret_cast<__half2*>(&a3));
    float4* p = reinterpret_cast<float4*>(attn + rowidx*LK_ + t*8);
    p[0] = make_float4(f0.x*f, f0.y*f, f1.x*f, f1.y*f);
    p[1] = make_float4(f2.x*f, f2.y*f, f3.x*f, f3.y*f);
}

// ---------------- launch ----------------------------------------------------
extern "C" void kernel_launch(void* const* d_in, const int* in_sizes, int n_in,
                              void* d_out, int out_size)
{
    const float* q    = (const float*)d_in[0];
    const float* k    = (const float*)d_in[1];
    const float* v    = (const float*)d_in[2];
    const int*   mask = (const int*)d_in[3];
    const float* w_qs = (const float*)d_in[4];
    const float* b_qs = (const float*)d_in[5];
    const float* w_ks = (const float*)d_in[6];
    const float* b_ks = (const float*)d_in[7];
    const float* w_vs = (const float*)d_in[8];
    const float* b_vs = (const float*)d_in[9];
    const float* fc_w = (const float*)d_in[10];
    const float* fc_b = (const float*)d_in[11];

    float* out = (float*)d_out;
    float* attn_out = out + (size_t)M_ * DM_;

    static cudaStream_t s1 = nullptr;
    static cudaEvent_t evFork = nullptr, evMask = nullptr, evAttn = nullptr, evResc = nullptr;
    if (s1 == nullptr){
        cudaStreamCreateWithFlags(&s1, cudaStreamNonBlocking);
        cudaEventCreateWithFlags(&evFork, cudaEventDisableTiming);
        cudaEventCreateWithFlags(&evMask, cudaEventDisableTiming);
        cudaEventCreateWithFlags(&evAttn, cudaEventDisableTiming);
        cudaEventCreateWithFlags(&evResc, cudaEventDisableTiming);
        cudaFuncSetAttribute(proj_kernel, cudaFuncAttributeMaxDynamicSharedMemorySize, 4*PSTG*4);
        cudaFuncSetAttribute(fc_kernel,   cudaFuncAttributeMaxDynamicSharedMemorySize, 4*FSTG*4);
        cudaFuncSetAttribute(attn_kernel, cudaFuncAttributeMaxDynamicSharedMemorySize, ATTN_SMEM_U32*4);
    }

    k_split_inputs<<<24576, 256>>>(q, k, v);
    k_conv_w<<<dim3(32,32,4), 256>>>(w_qs, w_ks, w_vs, fc_w);

    cudaEventRecord(evFork, 0);
    cudaStreamWaitEvent(s1, evFork, 0);
    k_mask_bits<<<2048, 256, 0, s1>>>(mask);
    cudaEventRecord(evMask, s1);

    proj_kernel<<<dim3(8,64,3), 256, 4*PSTG*4>>>(b_qs, b_ks, b_vs);

    cudaStreamWaitEvent(0, evMask, 0);
    attn_kernel<<<dim3(16,NH_,B_), 256, ATTN_SMEM_U32*4>>>();

    cudaEventRecord(evAttn, 0);
    cudaStreamWaitEvent(s1, evAttn, 0);
    rescale_kernel<<<dim3(LQ_, B_*NH_), 256, 0, s1>>>(attn_out);
    cudaEventRecord(evResc, s1);

    fc_kernel<<<dim3(8,64), 256, 4*FSTG*4>>>(fc_b, q, out);

    cudaStreamWaitEvent(0, evResc, 0);
}

// round 17
// speedup vs baseline: 1.4661x; 1.1194x over previous
#include <cuda_runtime.h>
#include <cuda_bf16.h>
#include <cuda_fp16.h>
#include <math.h>
#include <stdint.h>

#define B_   4
#define LQ_  2048
#define LK_  2048
#define DM_  1024
#define NH_  16
#define M_   8192

// ---------------- device scratch (allocation-free rule) --------------------
__device__ uint32_t g_Ih[3][4194304];     // fp16 of q,k,v inputs (fp16x2)
__device__ uint32_t g_Wt [4][524288];     // transposed weights fp16 [n][k-pair]; idx3 = fc_w
__device__ uint32_t g_Qh16[4194304];      // Q fp16x2 [b,h,l,d-pair], pre-scaled log2e/8
__device__ uint32_t g_Kh16[4194304];      // K fp16x2
__device__ uint32_t g_Vh [4194304];       // V TRANSPOSED fp16 [bh*64+d][l]
__device__ uint32_t g_Hbf[4194304];       // attn output fp16 [m][k-pair] for FC
__device__ uint32_t g_mbits[524288];      // mask bitwords [b][lq][lk/32]
__device__ uint32_t g_Pt[134217728];      // p_tilde staging, fp16x2 [bh*lq][lk/2]
__device__ float    g_mchunk[(size_t)B_*NH_*LQ_*32];
__device__ float2   g_rowstat[(size_t)B_*NH_*LQ_];

// ---------------- helpers --------------------------------------------------
__device__ __forceinline__ uint32_t pack_h2(float x, float y){
    __half2 t = __floats2half2_rn(x, y);
    return *reinterpret_cast<uint32_t*>(&t);
}
__device__ __forceinline__ void mma16816h(float* c,
    uint32_t a0, uint32_t a1, uint32_t a2, uint32_t a3, uint32_t b0, uint32_t b1){
    asm volatile("mma.sync.aligned.m16n8k16.row.col.f32.f16.f16.f32 "
        "{%0,%1,%2,%3}, {%4,%5,%6,%7}, {%8,%9}, {%0,%1,%2,%3};"
        : "+f"(c[0]), "+f"(c[1]), "+f"(c[2]), "+f"(c[3])
        : "r"(a0), "r"(a1), "r"(a2), "r"(a3), "r"(b0), "r"(b1));
}
__device__ __forceinline__ void ldsm_x4(uint32_t* r, uint32_t addr){
    asm volatile("ldmatrix.sync.aligned.m8n8.x4.shared.b16 {%0,%1,%2,%3}, [%4];"
        : "=r"(r[0]), "=r"(r[1]), "=r"(r[2]), "=r"(r[3]) : "r"(addr));
}
__device__ __forceinline__ void cp_async16(uint32_t saddr, const void* gaddr){
    asm volatile("cp.async.cg.shared.global [%0], [%1], 16;" :: "r"(saddr), "l"(gaddr));
}
__device__ __forceinline__ void cp_commit(){ asm volatile("cp.async.commit_group;"); }
template<int N> __device__ __forceinline__ void cp_wait(){
    asm volatile("cp.async.wait_group %0;" :: "n"(N));
}
__device__ __forceinline__ uint32_t smem_u32addr(const void* p){
    uint32_t a;
    asm("{.reg .u64 t; cvta.to.shared.u64 t, %1; cvt.u32.u64 %0, t;}" : "=r"(a) : "l"(p));
    return a;
}

// ---------------- convert kernels ------------------------------------------
__global__ void k_split_inputs(const float* __restrict__ q,
                               const float* __restrict__ k,
                               const float* __restrict__ v){
    size_t F = (size_t)blockIdx.x*256 + threadIdx.x;
    int mat = (int)(F >> 21);
    size_t rem = F & 2097151u;
    const float* src = mat==0 ? q : mat==1 ? k : v;
    float4 a = reinterpret_cast<const float4*>(src)[rem];
    g_Ih[mat][rem*2]   = pack_h2(a.x, a.y);
    g_Ih[mat][rem*2+1] = pack_h2(a.z, a.w);
}

__global__ void k_conv_w(const float* __restrict__ wq, const float* __restrict__ wk,
                         const float* __restrict__ wv, const float* __restrict__ fcw){
    const int mat = blockIdx.z;
    const float* W = mat==0 ? wq : mat==1 ? wk : mat==2 ? wv : fcw;
    __shared__ float T[32][33];
    const int k0 = blockIdx.y*32, n0 = blockIdx.x*32;
    const int tx = threadIdx.x & 31, ty = threadIdx.x >> 5;
    #pragma unroll
    for (int i=0;i<4;i++)
        T[ty+8*i][tx] = W[(size_t)(k0+ty+8*i)*DM_ + n0 + tx];
    __syncthreads();
    const int n = threadIdx.x >> 3;
    const int kp0 = (threadIdx.x & 7)*2;
    #pragma unroll
    for (int s2=0;s2<2;s2++){
        int kp = kp0 + s2;
        size_t o = (size_t)(n0+n)*512 + (k0>>1) + kp;
        g_Wt[mat][o] = pack_h2(T[kp*2][n], T[kp*2+1][n]);
    }
}

__global__ void k_mask_bits(const int* __restrict__ mask){
    int wrp = blockIdx.x*8 + (threadIdx.x>>5);
    int lane = threadIdx.x & 31;
    size_t base = (size_t)wrp*32;
    for (int j=0;j<32;j++){
        size_t w = base + j;
        int mv = mask[w*32 + lane];
        uint32_t bits = __ballot_sync(0xffffffffu, mv != 0);
        if (lane==0) g_mbits[w] = bits;
    }
}

// ---------------- projection GEMM (single fp16 term) ------------------------
#define PSTG 3072            // u32 per stage (2 buffers x 1536)
#define BUFB 6144            // bytes per buffer

__global__ void __launch_bounds__(256,2) proj_kernel(
    const float* __restrict__ bq, const float* __restrict__ bk,
    const float* __restrict__ bv)
{
    extern __shared__ uint32_t smp[];
    const uint32_t sbase = smem_u32addr(smp);

    const int which = blockIdx.z;
    const uint32_t* gA = g_Ih[which];
    const uint32_t* gB = g_Wt[which];
    const float* bias = which==0 ? bq : which==1 ? bk : bv;

    const int m0 = blockIdx.y*128, n0 = blockIdx.x*128;
    const int tid = threadIdx.x, lane = tid & 31, wid = tid >> 5;
    const int wm = (wid & 3)*32, wn = (wid >> 2)*64;

    const int crow = tid >> 1, chalf = tid & 1;
    const uint32_t* gsrc0 = gA + (size_t)(m0+crow)*512 + chalf*4;
    const uint32_t* gsrc1 = gB + (size_t)(n0+crow)*512 + chalf*4;
    const uint32_t sdst = sbase + crow*48 + chalf*16;

    auto issue = [&](int itk){
        int stage = itk & 3;
        uint32_t so = sdst + stage*(PSTG*4);
        size_t ko = (size_t)itk*8;
        cp_async16(so,        gsrc0 + ko);
        cp_async16(so + BUFB, gsrc1 + ko);
        cp_commit();
    };

    float acc[2][8][4];
    #pragma unroll
    for (int a=0;a<2;a++)
        #pragma unroll
        for (int b2=0;b2<8;b2++){ acc[a][b2][0]=0.f;acc[a][b2][1]=0.f;acc[a][b2][2]=0.f;acc[a][b2][3]=0.f; }

    issue(0); issue(1); issue(2);

    const uint32_t arow = wm + (lane & 15);
    const uint32_t aoff0 = arow*48 + ((lane>>4)&1)*16;
    const uint32_t brow = wn + (lane & 7) + ((lane & 16) ? 8 : 0);
    const uint32_t boff0 = BUFB + brow*48 + ((lane & 8) ? 16 : 0);

    #pragma unroll 1
    for (int it=0; it<64; it++){
        if (it <= 61) cp_wait<2>(); else if (it == 62) cp_wait<1>(); else cp_wait<0>();
        __syncthreads();
        if (it + 3 < 64) issue(it+3);

        uint32_t sb = sbase + (it & 3)*(PSTG*4);
        uint32_t a_h[2][4];
        ldsm_x4(a_h[0], sb + aoff0);
        ldsm_x4(a_h[1], sb + aoff0 + 16*48);
        #pragma unroll
        for (int p=0;p<4;p++){
            uint32_t bh4[4];
            ldsm_x4(bh4, sb + boff0 + p*16*48);
            #pragma unroll
            for (int mt=0;mt<2;mt++){
                mma16816h(acc[mt][2*p],   a_h[mt][0],a_h[mt][1],a_h[mt][2],a_h[mt][3], bh4[0],bh4[1]);
                mma16816h(acc[mt][2*p+1], a_h[mt][0],a_h[mt][1],a_h[mt][2],a_h[mt][3], bh4[2],bh4[3]);
            }
        }
    }

    // Q prescaled by log2e/8 so softmax uses bare exp2
    const float sc = (which==0) ? 0.180336880111120f : 1.0f;
    __half* vt = reinterpret_cast<__half*>(g_Vh);
    #pragma unroll
    for (int mt=0;mt<2;mt++){
        int r0 = m0 + wm + mt*16 + (lane>>2);
        #pragma unroll
        for (int nt=0;nt<8;nt++){
            int col = n0 + wn + nt*8 + 2*(lane&3);
            float2 bv2 = *reinterpret_cast<const float2*>(bias + col);
            int hh = col>>6, dd = col&63;
            #pragma unroll
            for (int rr=0;rr<2;rr++){
                int r = r0 + rr*8;
                int bb2 = r>>11, ll = r&2047;
                float x0 = (acc[mt][nt][rr*2]   + bv2.x)*sc;
                float x1 = (acc[mt][nt][rr*2+1] + bv2.y)*sc;
                if (which==2){
                    size_t vb = ((size_t)(bb2*NH_+hh)*64 + dd)*2048 + ll;
                    vt[vb]        = __float2half(x0);
                    vt[vb + 2048] = __float2half(x1);
                } else {
                    size_t o = (((size_t)(bb2*NH_+hh))*LQ_ + ll)*32 + (dd>>1);
                    uint32_t hx = pack_h2(x0, x1);
                    if (which==0) g_Qh16[o] = hx; else g_Kh16[o] = hx;
                }
            }
        }
    }
}

// ---------------- FC GEMM (fp16 x fp16) + bias + residual ------------------
#define FSTG 3072

__global__ void __launch_bounds__(256,2) fc_kernel(
    const float* __restrict__ fc_b, const float* __restrict__ q_in,
    float* __restrict__ out)
{
    extern __shared__ uint32_t smf[];
    const uint32_t sbase = smem_u32addr(smf);

    const int m0 = blockIdx.y*128, n0 = blockIdx.x*128;
    const int tid = threadIdx.x, lane = tid & 31, wid = tid >> 5;
    const int wm = (wid & 3)*32, wn = (wid >> 2)*64;

    const int crow = tid >> 1, chalf = tid & 1;
    const uint32_t* gsrc0 = g_Hbf   + (size_t)(m0+crow)*512 + chalf*4;
    const uint32_t* gsrc1 = g_Wt[3] + (size_t)(n0+crow)*512 + chalf*4;
    const uint32_t sdst = sbase + crow*48 + chalf*16;

    auto issue = [&](int itk){
        int stage = itk & 3;
        uint32_t so = sdst + stage*(FSTG*4);
        size_t ko = (size_t)itk*8;
        cp_async16(so,        gsrc0 + ko);
        cp_async16(so + BUFB, gsrc1 + ko);
        cp_commit();
    };

    float acc[2][8][4];
    #pragma unroll
    for (int a=0;a<2;a++)
        #pragma unroll
        for (int b2=0;b2<8;b2++){ acc[a][b2][0]=0.f;acc[a][b2][1]=0.f;acc[a][b2][2]=0.f;acc[a][b2][3]=0.f; }

    issue(0); issue(1); issue(2);

    const uint32_t arow = wm + (lane & 15);
    const uint32_t aoff0 = arow*48 + ((lane>>4)&1)*16;
    const uint32_t brow = wn + (lane & 7) + ((lane & 16) ? 8 : 0);
    const uint32_t boff0 = BUFB + brow*48 + ((lane & 8) ? 16 : 0);

    #pragma unroll 1
    for (int it=0; it<64; it++){
        if (it <= 61) cp_wait<2>(); else if (it == 62) cp_wait<1>(); else cp_wait<0>();
        __syncthreads();
        if (it + 3 < 64) issue(it+3);

        uint32_t sb = sbase + (it & 3)*(FSTG*4);
        uint32_t a_h[2][4];
        ldsm_x4(a_h[0], sb + aoff0);
        ldsm_x4(a_h[1], sb + aoff0 + 16*48);
        #pragma unroll
        for (int p=0;p<4;p++){
            uint32_t bh4[4];
            ldsm_x4(bh4, sb + boff0 + p*16*48);
            #pragma unroll
            for (int mt=0;mt<2;mt++){
                mma16816h(acc[mt][2*p],   a_h[mt][0],a_h[mt][1],a_h[mt][2],a_h[mt][3], bh4[0],bh4[1]);
                mma16816h(acc[mt][2*p+1], a_h[mt][0],a_h[mt][1],a_h[mt][2],a_h[mt][3], bh4[2],bh4[3]);
            }
        }
    }

    #pragma unroll
    for (int mt=0;mt<2;mt++){
        int r0 = m0 + wm + mt*16 + (lane>>2);
        #pragma unroll
        for (int nt=0;nt<8;nt++){
            int col = n0 + wn + nt*8 + 2*(lane&3);
            float2 bv2 = *reinterpret_cast<const float2*>(fc_b + col);
            #pragma unroll
            for (int rr=0;rr<2;rr++){
                size_t idx = (size_t)(r0+rr*8)*DM_ + col;
                float2 res = *reinterpret_cast<const float2*>(q_in + idx);
                *reinterpret_cast<float2*>(out + idx) =
                    make_float2(acc[mt][nt][rr*2]+bv2.x+res.x, acc[mt][nt][rr*2+1]+bv2.y+res.y);
            }
        }
    }
}

// ---------------- attention: fp16 single-term, KCH=64, 2 CTAs/SM -----------
#define OF_K0 4608                   // Q tile: 128x36 u32 = 4608
#define OF_V0 9216                   // K bufs: 2 x 2304 ; V bufs: 2 x 2304
#define ATTN_SMEM_U32 13824          // 55296 bytes

__global__ void __launch_bounds__(256,2) attn_kernel()
{
    extern __shared__ uint32_t smq[];
    const uint32_t sbase = smem_u32addr(smq);
    uint32_t* Qs = smq;

    const int b  = blockIdx.z, h = blockIdx.y;
    const int q0 = blockIdx.x * 128;
    const int bh = b*NH_ + h;
    const int tid = threadIdx.x, lane = tid & 31, wid = tid >> 5;
    const int wrow = wid * 16;
    const size_t ho32 = (size_t)bh * LK_ * 32;

    auto load_kv = [&](int kc, int buf){
        uint32_t kb = sbase + (OF_K0 + buf*2304)*4;
        uint32_t vb = sbase + (OF_V0 + buf*2304)*4;
        {
            int id = tid;
            #pragma unroll
            for (int p=0;p<2;p++){
                int row = id>>3, c = id&7;
                cp_async16(kb + row*144 + c*16, g_Kh16 + ho32 + (size_t)(kc+row)*32 + c*4);
                cp_async16(vb + row*144 + c*16, g_Vh + ((size_t)bh*64 + row)*1024 + (kc>>1) + c*4);
                id += 256;
            }
        }
        cp_commit();
    };

    load_kv(0, 0);

    #pragma unroll
    for (int p=0;p<4;p++){
        int item = tid + p*256;
        int row = item>>3, o = item&7;
        *reinterpret_cast<uint4*>(Qs + row*36 + o*4) =
            *reinterpret_cast<const uint4*>(g_Qh16 + ho32 + (size_t)(q0+row)*32 + o*4);
    }

    float mrow0 = -INFINITY, mrow1 = -INFINITY;
    float lrow0 = 0.f, lrow1 = 0.f;
    float o_[8][4];
    #pragma unroll
    for (int t=0;t<8;t++){ o_[t][0]=0.f;o_[t][1]=0.f;o_[t][2]=0.f;o_[t][3]=0.f; }

    const int rbase = q0 + wrow + (lane>>2);
    const uint32_t* mbits_row0 = g_mbits + ((size_t)b*LQ_ + rbase)*64;

    const uint32_t aaddr = sbase + (wrow + (lane&15))*144 + ((lane&16)?16:0);
    const uint32_t boff  = ((lane&7) + ((lane&16)?8:0))*144 + ((lane&8)?16:0);

    int cur = 0;
    #pragma unroll 1
    for (int kc=0; kc<LK_; kc+=64){
        cp_wait<0>();
        __syncthreads();
        if (kc + 64 < LK_) load_kv(kc+64, cur^1);

        const uint32_t baddr = sbase + (OF_K0 + cur*2304)*4 + boff;
        const uint32_t vaddr = sbase + (OF_V0 + cur*2304)*4 + boff;

        uint32_t mw0[2], mw1[2];
        #pragma unroll
        for (int c2=0;c2<2;c2++){
            mw0[c2] = mbits_row0[(kc>>5) + c2];
            mw1[c2] = mbits_row0[8*64 + (kc>>5) + c2];
        }

        float s[8][4];
        #pragma unroll
        for (int t=0;t<8;t++){ s[t][0]=0.f;s[t][1]=0.f;s[t][2]=0.f;s[t][3]=0.f; }
        #pragma unroll
        for (int ks=0; ks<4; ks++){
            uint32_t ah[4];
            ldsm_x4(ah, aaddr + ks*32);
            #pragma unroll
            for (int p=0;p<4;p++){
                uint32_t bh4[4];
                ldsm_x4(bh4, baddr + p*16*144 + ks*32);
                mma16816h(s[2*p],   ah[0],ah[1],ah[2],ah[3], bh4[0],bh4[1]);
                mma16816h(s[2*p+1], ah[0],ah[1],ah[2],ah[3], bh4[2],bh4[3]);
            }
        }

        float cm0 = -INFINITY, cm1 = -INFINITY;
        #pragma unroll
        for (int nt=0;nt<8;nt++){
            uint32_t w0 = mw0[nt>>2], w1 = mw1[nt>>2];
            int bsh = ((nt&3)<<3) + ((lane&3)<<1);
            if ((w0>>bsh)&1)     s[nt][0] = -INFINITY;
            if ((w0>>(bsh+1))&1) s[nt][1] = -INFINITY;
            if ((w1>>bsh)&1)     s[nt][2] = -INFINITY;
            if ((w1>>(bsh+1))&1) s[nt][3] = -INFINITY;
            cm0 = fmaxf(cm0, fmaxf(s[nt][0], s[nt][1]));
            cm1 = fmaxf(cm1, fmaxf(s[nt][2], s[nt][3]));
        }
        cm0 = fmaxf(cm0, __shfl_xor_sync(0xffffffffu, cm0, 1));
        cm0 = fmaxf(cm0, __shfl_xor_sync(0xffffffffu, cm0, 2));
        cm1 = fmaxf(cm1, __shfl_xor_sync(0xffffffffu, cm1, 1));
        cm1 = fmaxf(cm1, __shfl_xor_sync(0xffffffffu, cm1, 2));

        float mn0 = fmaxf(mrow0, cm0), mn1 = fmaxf(mrow1, cm1);
        float corr0 = (mrow0 == -INFINITY) ? 0.f : exp2f(mrow0 - mn0);
        float corr1 = (mrow1 == -INFINITY) ? 0.f : exp2f(mrow1 - mn1);

        float sum0 = 0.f, sum1 = 0.f;
        #pragma unroll
        for (int nt=0;nt<8;nt++){
            s[nt][0] = exp2f(s[nt][0] - mn0);
            s[nt][1] = exp2f(s[nt][1] - mn0);
            s[nt][2] = exp2f(s[nt][2] - mn1);
            s[nt][3] = exp2f(s[nt][3] - mn1);
            sum0 += s[nt][0] + s[nt][1];
            sum1 += s[nt][2] + s[nt][3];
        }
        sum0 += __shfl_xor_sync(0xffffffffu, sum0, 1);
        sum0 += __shfl_xor_sync(0xffffffffu, sum0, 2);
        sum1 += __shfl_xor_sync(0xffffffffu, sum1, 1);
        sum1 += __shfl_xor_sync(0xffffffffu, sum1, 2);

        lrow0 = lrow0*corr0 + sum0;
        lrow1 = lrow1*corr1 + sum1;
        mrow0 = mn0; mrow1 = mn1;

        #pragma unroll
        for (int t=0;t<8;t++){
            o_[t][0]*=corr0; o_[t][1]*=corr0; o_[t][2]*=corr1; o_[t][3]*=corr1;
        }

        uint32_t ph[8][2];
        #pragma unroll
        for (int nt=0;nt<8;nt++){
            ph[nt][0] = pack_h2(s[nt][0], s[nt][1]);
            ph[nt][1] = pack_h2(s[nt][2], s[nt][3]);
        }

        uint32_t* pr0 = g_Pt + ((size_t)bh*LQ_ + rbase)*(LK_/2);
        uint32_t* pr1 = pr0 + 8*(size_t)(LK_/2);
        #pragma unroll
        for (int nt=0;nt<8;nt++){
            int colh = (kc + nt*8 + 2*(lane&3)) >> 1;
            __stcs(pr0 + colh, ph[nt][0]);
            __stcs(pr1 + colh, ph[nt][1]);
        }
        if ((lane & 3) == 0){
            g_mchunk[((size_t)bh*LQ_ + rbase)*32 + (kc>>6)]     = mn0;
            g_mchunk[((size_t)bh*LQ_ + rbase + 8)*32 + (kc>>6)] = mn1;
        }

        #pragma unroll
        for (int kk=0;kk<4;kk++){
            uint32_t a0 = ph[2*kk][0],   a1 = ph[2*kk][1];
            uint32_t a2 = ph[2*kk+1][0], a3 = ph[2*kk+1][1];
            #pragma unroll
            for (int g=0; g<4; g++){
                uint32_t bv4[4];
                ldsm_x4(bv4, vaddr + g*16*144 + kk*32);
                mma16816h(o_[2*g],   a0,a1,a2,a3, bv4[0],bv4[1]);
                mma16816h(o_[2*g+1], a0,a1,a2,a3, bv4[2],bv4[3]);
            }
        }
        cur ^= 1;
    }

    float inv0 = 1.f / lrow0, inv1 = 1.f / lrow1;
    #pragma unroll
    for (int nt2=0;nt2<8;nt2++){
        int dcol = nt2*8 + 2*(lane&3);
        size_t ro = ((size_t)b*LQ_ + rbase)*512 + h*32 + (dcol>>1);
        g_Hbf[ro]         = pack_h2(o_[nt2][0]*inv0, o_[nt2][1]*inv0);
        g_Hbf[ro + 8*512] = pack_h2(o_[nt2][2]*inv1, o_[nt2][3]*inv1);
    }
    if ((lane & 3) == 0){
        g_rowstat[(size_t)bh*LQ_ + rbase]     = make_float2(mrow0, lrow0);
        g_rowstat[(size_t)bh*LQ_ + rbase + 8] = make_float2(mrow1, lrow1);
    }
}

// ---------------- rescale: fp16 p_tilde -> fp32 probs ----------------------
__global__ void rescale_kernel(float* __restrict__ attn)
{
    const int bh = blockIdx.y;
    const int qq = blockIdx.x;
    const size_t rowidx = (size_t)bh*LQ_ + qq;
    float2 st = g_rowstat[rowidx];
    int t = threadIdx.x;
    int chunk = t >> 3;
    float f = exp2f(g_mchunk[rowidx*32 + chunk] - st.x) / st.y;
    const uint32_t* src = g_Pt + rowidx*(LK_/2) + t*4;
    uint32_t a0 = __ldcs(src), a1 = __ldcs(src+1), a2 = __ldcs(src+2), a3 = __ldcs(src+3);
    float2 f0 = __half22float2(*reinterpret_cast<__half2*>(&a0));
    float2 f1 = __half22float2(*reinterpret_cast<__half2*>(&a1));
    float2 f2 = __half22float2(*reinterpret_cast<__half2*>(&a2));
    float2 f3 = __half22float2(*reinterpret_cast<__half2*>(&a3));
    float4* p = reinterpret_cast<float4*>(attn + rowidx*LK_ + t*8);
    p[0] = make_float4(f0.x*f, f0.y*f, f1.x*f, f1.y*f);
    p[1] = make_float4(f2.x*f, f2.y*f, f3.x*f, f3.y*f);
}

// ---------------- launch ----------------------------------------------------
extern "C" void kernel_launch(void* const* d_in, const int* in_sizes, int n_in,
                              void* d_out, int out_size)
{
    const float* q    = (const float*)d_in[0];
    const float* k    = (const float*)d_in[1];
    const float* v    = (const float*)d_in[2];
    const int*   mask = (const int*)d_in[3];
    const float* w_qs = (const float*)d_in[4];
    const float* b_qs = (const float*)d_in[5];
    const float* w_ks = (const float*)d_in[6];
    const float* b_ks = (const float*)d_in[7];
    const float* w_vs = (const float*)d_in[8];
    const float* b_vs = (const float*)d_in[9];
    const float* fc_w = (const float*)d_in[10];
    const float* fc_b = (const float*)d_in[11];

    float* out = (float*)d_out;
    float* attn_out = out + (size_t)M_ * DM_;

    static cudaStream_t s1 = nullptr;
    static cudaEvent_t evFork = nullptr, evMask = nullptr, evAttn = nullptr, evResc = nullptr;
    if (s1 == nullptr){
        cudaStreamCreateWithFlags(&s1, cudaStreamNonBlocking);
        cudaEventCreateWithFlags(&evFork, cudaEventDisableTiming);
        cudaEventCreateWithFlags(&evMask, cudaEventDisableTiming);
        cudaEventCreateWithFlags(&evAttn, cudaEventDisableTiming);
        cudaEventCreateWithFlags(&evResc, cudaEventDisableTiming);
        cudaFuncSetAttribute(proj_kernel, cudaFuncAttributeMaxDynamicSharedMemorySize, 4*PSTG*4);
        cudaFuncSetAttribute(fc_kernel,   cudaFuncAttributeMaxDynamicSharedMemorySize, 4*FSTG*4);
        cudaFuncSetAttribute(attn_kernel, cudaFuncAttributeMaxDynamicSharedMemorySize, ATTN_SMEM_U32*4);
    }

    k_split_inputs<<<24576, 256>>>(q, k, v);
    k_conv_w<<<dim3(32,32,4), 256>>>(w_qs, w_ks, w_vs, fc_w);

    cudaEventRecord(evFork, 0);
    cudaStreamWaitEvent(s1, evFork, 0);
    k_mask_bits<<<2048, 256, 0, s1>>>(mask);
    cudaEventRecord(evMask, s1);

    proj_kernel<<<dim3(8,64,3), 256, 4*PSTG*4>>>(b_qs, b_ks, b_vs);

    cudaStreamWaitEvent(0, evMask, 0);
    attn_kernel<<<dim3(16,NH_,B_), 256, ATTN_SMEM_U32*4>>>();

    cudaEventRecord(evAttn, 0);
    cudaStreamWaitEvent(s1, evAttn, 0);
    rescale_kernel<<<dim3(LQ_, B_*NH_), 256, 0, s1>>>(attn_out);
    cudaEventRecord(evResc, s1);

    fc_kernel<<<dim3(8,64), 256, 4*FSTG*4>>>(fc_b, q, out);

    cudaStreamWaitEvent(0, evResc, 0);
}